// round 8
// baseline (speedup 1.0000x reference)
#include <cuda_runtime.h>
#include <cuda_bf16.h>
#include <stdint.h>
#include <math.h>

// Problem constants: B=2, S=1024, E=2560, H=32, D=80, 3E=7680, BS=2048, K=2560

// ---------------- device scratch ----------------
__device__ float g_qkv[2048ull * 7680];
__device__ __nv_bfloat16 g_hid_hi[2048ull * 2560];
__device__ __nv_bfloat16 g_hid_lo[2048ull * 2560];
__device__ __nv_bfloat16 g_wqkvT_hi[7680ull * 2560];   // (N,K)
__device__ __nv_bfloat16 g_wqkvT_lo[7680ull * 2560];
__device__ __nv_bfloat16 g_wprojT_hi[2560ull * 2560];
__device__ __nv_bfloat16 g_wprojT_lo[2560ull * 2560];
__device__ __nv_bfloat16 g_attn_hi[2048ull * 2560];
__device__ __nv_bfloat16 g_attn_lo[2048ull * 2560];
__device__ __nv_bfloat16 g_Khi[64ull * 1024 * 88];     // [bh][key][88]
__device__ __nv_bfloat16 g_Klo[64ull * 1024 * 88];
__device__ __nv_bfloat16 g_Vthi[64ull * 80 * 1024];    // [bh][dim][1024]
__device__ __nv_bfloat16 g_Vtlo[64ull * 80 * 1024];

__device__ __forceinline__ uint32_t smem_u32(const void* p) {
    uint32_t a;
    asm("{ .reg .u64 t; cvta.to.shared.u64 t, %1; cvt.u32.u64 %0, t; }"
        : "=r"(a) : "l"(p));
    return a;
}

#define SWZ(o) ((uint32_t)(o) ^ ((((uint32_t)(o)) >> 3) & 0x70u))

#define CP16(s, g) \
    asm volatile("cp.async.cg.shared.global [%0], [%1], 16;" :: "r"(s), "l"(g))

#define LDSM4(r, addr) \
    asm volatile("ldmatrix.sync.aligned.m8n8.x4.shared.b16 {%0,%1,%2,%3}, [%4];" \
                 : "=r"((r)[0]), "=r"((r)[1]), "=r"((r)[2]), "=r"((r)[3]) \
                 : "r"(addr))

#define MMA_BF16(acc, A, b0, b1) \
    asm volatile("mma.sync.aligned.m16n8k16.row.col.f32.bf16.bf16.f32 " \
                 "{%0,%1,%2,%3}, {%4,%5,%6,%7}, {%8,%9}, {%0,%1,%2,%3};" \
                 : "+f"((acc)[0]), "+f"((acc)[1]), "+f"((acc)[2]), "+f"((acc)[3]) \
                 : "r"((A)[0]), "r"((A)[1]), "r"((A)[2]), "r"((A)[3]), \
                   "r"(b0), "r"(b1))

// ---------------------------------------------------------------------------
// Conversion: fp32 -> bf16 hi/lo
// ---------------------------------------------------------------------------
__global__ void conv_hilo(const float* __restrict__ X,
                          __nv_bfloat16* __restrict__ Hh,
                          __nv_bfloat16* __restrict__ Ll, int n4) {
    int i = blockIdx.x * blockDim.x + threadIdx.x;
    if (i >= n4) return;
    float4 v = ((const float4*)X)[i];
    __nv_bfloat16 h0 = __float2bfloat16(v.x), h1 = __float2bfloat16(v.y);
    __nv_bfloat16 h2 = __float2bfloat16(v.z), h3 = __float2bfloat16(v.w);
    __nv_bfloat162 a, b;
    a.x = h0; a.y = h1; b.x = h2; b.y = h3;
    ((__nv_bfloat162*)Hh)[i * 2] = a;
    ((__nv_bfloat162*)Hh)[i * 2 + 1] = b;
    __nv_bfloat162 c, d;
    c.x = __float2bfloat16(v.x - __bfloat162float(h0));
    c.y = __float2bfloat16(v.y - __bfloat162float(h1));
    d.x = __float2bfloat16(v.z - __bfloat162float(h2));
    d.y = __float2bfloat16(v.w - __bfloat162float(h3));
    ((__nv_bfloat162*)Ll)[i * 2] = c;
    ((__nv_bfloat162*)Ll)[i * 2 + 1] = d;
}

// ---------------------------------------------------------------------------
// Transpose + convert: W (K,N) fp32 -> Th/Tl (N,K) bf16
// ---------------------------------------------------------------------------
__global__ void transpose_conv(const float* __restrict__ W,
                               __nv_bfloat16* __restrict__ Th,
                               __nv_bfloat16* __restrict__ Tl, int K, int N) {
    __shared__ float t[32][33];
    int n0 = blockIdx.x * 32, k0 = blockIdx.y * 32;
    int tx = threadIdx.x, ty = threadIdx.y;
#pragma unroll
    for (int j = 0; j < 4; j++)
        t[ty + j * 8][tx] = W[(size_t)(k0 + ty + j * 8) * N + n0 + tx];
    __syncthreads();
#pragma unroll
    for (int j = 0; j < 4; j++) {
        float v = t[tx][ty + j * 8];
        __nv_bfloat16 h = __float2bfloat16(v);
        size_t o = (size_t)(n0 + ty + j * 8) * K + k0 + tx;
        Th[o] = h;
        Tl[o] = __float2bfloat16(v - __bfloat162float(h));
    }
}

// ---------------------------------------------------------------------------
// prep_k: k part of qkv -> bf16 hi/lo [bh][key][88]
// ---------------------------------------------------------------------------
__global__ void prep_k(const float* __restrict__ qkv,
                       __nv_bfloat16* __restrict__ Kh,
                       __nv_bfloat16* __restrict__ Kl) {
    int idx = blockIdx.x * 256 + threadIdx.x;
    if (idx >= 64 * 1024 * 80) return;
    int d = idx % 80;
    int key = (idx / 80) & 1023;
    int bh = idx / 81920;
    int b = bh >> 5, h = bh & 31;
    float v = qkv[(size_t)(b * 1024 + key) * 7680 + 2560 + h * 80 + d];
    __nv_bfloat16 hh = __float2bfloat16(v);
    size_t o = (size_t)bh * 90112 + key * 88 + d;
    Kh[o] = hh;
    Kl[o] = __float2bfloat16(v - __bfloat162float(hh));
}

// ---------------------------------------------------------------------------
// prep_vt: v part -> transposed bf16 hi/lo [bh][dim][1024]
// ---------------------------------------------------------------------------
__global__ void prep_vt(const float* __restrict__ qkv,
                        __nv_bfloat16* __restrict__ Vh,
                        __nv_bfloat16* __restrict__ Vl) {
    __shared__ float t[64][17];
    int kt = blockIdx.x, dt = blockIdx.y, bh = blockIdx.z;
    int b = bh >> 5, h = bh & 31;
    int tx = threadIdx.x, ty = threadIdx.y;
#pragma unroll
    for (int j = 0; j < 4; j++) {
        int key = kt * 64 + ty + j * 16;
        t[ty + j * 16][tx] = qkv[(size_t)(b * 1024 + key) * 7680 + 5120 +
                                 h * 80 + dt * 16 + tx];
    }
    __syncthreads();
    size_t ob = ((size_t)bh * 80 + dt * 16 + ty) * 1024 + kt * 64;
#pragma unroll
    for (int j = 0; j < 4; j++) {
        float v = t[tx + j * 16][ty];
        __nv_bfloat16 hh = __float2bfloat16(v);
        Vh[ob + tx + j * 16] = hh;
        Vl[ob + tx + j * 16] = __float2bfloat16(v - __bfloat162float(hh));
    }
}

// ---------------------------------------------------------------------------
// mma.sync bf16x3 GEMM: C(2048,N) = A @ B^T + bias
// CTA 128x64, 256 threads, warp tile 32x32 (4 M-warps x 2 N-warps).
// K chunks of 64, 2-stage cp.async (stage 48KB, total 96KB -> 2 CTAs/SM).
// ---------------------------------------------------------------------------
__global__ __launch_bounds__(256, 2) void gemm_bf16x3(
    const __nv_bfloat16* __restrict__ Ah, const __nv_bfloat16* __restrict__ Al,
    const __nv_bfloat16* __restrict__ Bh, const __nv_bfloat16* __restrict__ Bl,
    const float* __restrict__ bias, float* __restrict__ C, int N) {
    extern __shared__ __align__(1024) char dsm[];
    const uint32_t base = smem_u32(dsm);

    const int tid = threadIdx.x;
    const int wid = tid >> 5, lane = tid & 31;
    const int mw = wid >> 1;      // 4 x 32 rows
    const int nw = wid & 1;       // 2 x 32 cols
    const int mt = blockIdx.y, nt = blockIdx.x;
    const int K = 2560;

    const int trow = tid >> 3;    // 0..31
    const int tkg = tid & 7;

    float acc[2][4][4];
#pragma unroll
    for (int a = 0; a < 2; a++)
#pragma unroll
        for (int b = 0; b < 4; b++)
#pragma unroll
            for (int c = 0; c < 4; c++) acc[a][b][c] = 0.0f;

    auto load_chunk = [&](int c, int st) {
        const int k0 = c * 64;
        const uint32_t s0 = base + st * 49152;
        // A: 128 rows hi+lo
#pragma unroll
        for (int j = 0; j < 4; j++) {
            const int row = j * 32 + trow;
            const uint32_t so = SWZ(row * 128 + tkg * 16);
            CP16(s0 + so, Ah + (size_t)(mt * 128 + row) * K + k0 + tkg * 8);
            CP16(s0 + 16384 + so, Al + (size_t)(mt * 128 + row) * K + k0 + tkg * 8);
        }
        // B: 64 rows hi+lo
#pragma unroll
        for (int j = 0; j < 2; j++) {
            const int row = j * 32 + trow;
            const uint32_t so = SWZ(row * 128 + tkg * 16);
            CP16(s0 + 32768 + so, Bh + (size_t)(nt * 64 + row) * K + k0 + tkg * 8);
            CP16(s0 + 40960 + so, Bl + (size_t)(nt * 64 + row) * K + k0 + tkg * 8);
        }
        asm volatile("cp.async.commit_group;");
    };

    const int lr = lane & 15;
    const int lc = (lane >> 4) * 16;

    load_chunk(0, 0);

    for (int c = 0; c < 40; c++) {
        const int st = c & 1;
        asm volatile("cp.async.wait_group 0;");
        __syncthreads();
        if (c < 39) load_chunk(c + 1, st ^ 1);

        const uint32_t sA = base + st * 49152;
#pragma unroll
        for (int ks = 0; ks < 4; ks++) {
            uint32_t ah[2][4], al[2][4];
#pragma unroll
            for (int mb = 0; mb < 2; mb++) {
                const uint32_t ro = (mw * 32 + mb * 16 + lr) * 128 + ks * 32 + lc;
                LDSM4(ah[mb], sA + SWZ(ro));
                LDSM4(al[mb], sA + 16384 + SWZ(ro));
            }
            uint32_t bh2[2][4], bl2[2][4];
#pragma unroll
            for (int nb = 0; nb < 2; nb++) {
                const uint32_t ro = (nw * 32 + nb * 16 + lr) * 128 + ks * 32 + lc;
                LDSM4(bh2[nb], sA + 32768 + SWZ(ro));
                LDSM4(bl2[nb], sA + 40960 + SWZ(ro));
            }
            // term-major: acc reuse distance = 8 MMAs
#pragma unroll
            for (int mb = 0; mb < 2; mb++)
#pragma unroll
                for (int nb = 0; nb < 2; nb++) {
                    MMA_BF16(acc[mb][nb * 2],     ah[mb], bh2[nb][0], bh2[nb][2]);
                    MMA_BF16(acc[mb][nb * 2 + 1], ah[mb], bh2[nb][1], bh2[nb][3]);
                }
#pragma unroll
            for (int mb = 0; mb < 2; mb++)
#pragma unroll
                for (int nb = 0; nb < 2; nb++) {
                    MMA_BF16(acc[mb][nb * 2],     ah[mb], bl2[nb][0], bl2[nb][2]);
                    MMA_BF16(acc[mb][nb * 2 + 1], ah[mb], bl2[nb][1], bl2[nb][3]);
                }
#pragma unroll
            for (int mb = 0; mb < 2; mb++)
#pragma unroll
                for (int nb = 0; nb < 2; nb++) {
                    MMA_BF16(acc[mb][nb * 2],     al[mb], bh2[nb][0], bh2[nb][2]);
                    MMA_BF16(acc[mb][nb * 2 + 1], al[mb], bh2[nb][1], bh2[nb][3]);
                }
        }
        __syncthreads();
    }

    const int row0 = mt * 128 + mw * 32 + (lane >> 2);
    const int col0 = nt * 64 + nw * 32 + 2 * (lane & 3);
#pragma unroll
    for (int mb = 0; mb < 2; mb++) {
#pragma unroll
        for (int n8 = 0; n8 < 4; n8++) {
            const int gc = col0 + n8 * 8;
            const float b0 = bias[gc], b1 = bias[gc + 1];
            const int r = row0 + mb * 16;
            float2 o0 = make_float2(acc[mb][n8][0] + b0, acc[mb][n8][1] + b1);
            float2 o1 = make_float2(acc[mb][n8][2] + b0, acc[mb][n8][3] + b1);
            *(float2*)&C[(size_t)r * N + gc] = o0;
            *(float2*)&C[(size_t)(r + 8) * N + gc] = o1;
        }
    }
}

// ---------------------------------------------------------------------------
// attn_mma v3: Q fragments hoisted into registers across all K-tiles.
// ---------------------------------------------------------------------------
#define A_OFF_QH 0u
#define A_OFF_QL 11264u
#define A_OFF_K  22528u
#define A_K_STG  45056u
#define A_OFF_SC 112640u
#define A_OFF_PH 0u
#define A_OFF_PL 33024u
#define A_OFF_V 67584u
#define A_OFF_RED 154624u
#define A_SMEM 197632

__global__ __launch_bounds__(256, 1) void attn_mma(
    const float* __restrict__ qkv,
    const __nv_bfloat16* __restrict__ Kh, const __nv_bfloat16* __restrict__ Kl,
    const __nv_bfloat16* __restrict__ Vh, const __nv_bfloat16* __restrict__ Vl,
    const float* __restrict__ gm, const float* __restrict__ gp,
    const float* __restrict__ ga, const float* __restrict__ qp,
    const float* __restrict__ isr,
    __nv_bfloat16* __restrict__ out_hi, __nv_bfloat16* __restrict__ out_lo) {
    extern __shared__ __align__(128) char smc[];
    __shared__ float coeff[240];
    __shared__ float row_l[16];
    char* sm = smc;
    const uint32_t base = smem_u32(smc);

    const int tid = threadIdx.x;
    const int wid = tid >> 5, lane = tid & 31;
    const int lr = lane & 15, lc = (lane >> 4) << 4;
    const int rr = lane >> 2, cc = (lane & 3) * 2;
    const int bh = blockIdx.y, b = bh >> 5, h = bh & 31;
    const int q0 = blockIdx.x * 16;

    const __nv_bfloat16* KhB = Kh + (size_t)bh * 90112;
    const __nv_bfloat16* KlB = Kl + (size_t)bh * 90112;
    auto load_k = [&](int kt, int stg) {
        const uint32_t sb = base + A_OFF_K + (uint32_t)stg * A_K_STG;
#pragma unroll
        for (int j = 0; j < 11; j++) {
            int idx = tid + j * 256;
            int m = idx >= 1408;
            int rem = m ? idx - 1408 : idx;
            int row = rem / 11, ch = rem - row * 11;
            const __nv_bfloat16* g =
                (m ? KlB : KhB) + (size_t)(kt * 128 + row) * 88 + ch * 8;
            CP16(sb + m * 22528u + row * 176 + ch * 16, g);
        }
        asm volatile("cp.async.commit_group;");
    };

    load_k(0, 0);

    if (tid < 240) {
        int g = tid / 80, d = tid - g * 80;
        float r0 = gm[g * 4 + 0] + gm[g * 4 + 1];
        float r1 = gm[g * 4 + 2] + gm[g * 4 + 3];
        float ph = gp[g * 80 + d];
        coeff[tid] = (cosf(ph) * r0 + sinf(ph) * r1) * ga[g * 80 + d];
    }
    __syncthreads();

    // build Qext (4 variants x 16 rows x 80 dims, scale folded in)
    const float scale = rsqrtf(80.0f);
    for (int idx = tid; idx < 1280; idx += 256) {
        int r = idx / 80, d = idx - r * 80;
        float v = qkv[(size_t)(b * 1024 + q0 + r) * 7680 + h * 80 + d] * scale;
        float vv[4] = {v, v * coeff[d], v * coeff[80 + d], v * coeff[160 + d]};
#pragma unroll
        for (int g = 0; g < 4; g++) {
            uint32_t o = (g * 16 + r) * 176 + d * 2;
            __nv_bfloat16 hh = __float2bfloat16(vv[g]);
            *(__nv_bfloat16*)(sm + A_OFF_QH + o) = hh;
            *(__nv_bfloat16*)(sm + A_OFF_QL + o) =
                __float2bfloat16(vv[g] - __bfloat162float(hh));
        }
    }
    __syncthreads();

    // hoist Q fragments into registers (kt-invariant)
    uint32_t qH[5][4][4], qL[5][4][4];
#pragma unroll
    for (int ks = 0; ks < 5; ks++) {
#pragma unroll
        for (int g = 0; g < 4; g++) {
            uint32_t ro = (g * 16 + lr) * 176 + ks * 32 + lc;
            LDSM4(qH[ks][g], base + A_OFF_QH + ro);
            LDSM4(qL[ks][g], base + A_OFF_QL + ro);
        }
    }

    const float intf = isr[0] * (1.0f / 3.0f);
    float* sc = (float*)(sm + A_OFF_SC);     // 16 x 1032

    // ---- Phase 1: scores; warp wid owns keys [kt*128 + wid*16, +16) ----
    for (int kt = 0; kt < 8; kt++) {
        const int stg = kt & 1;
        asm volatile("cp.async.wait_group 0;");
        __syncthreads();
        if (kt < 7) load_k(kt + 1, stg ^ 1);

        const uint32_t kbase = base + A_OFF_K + (uint32_t)stg * A_K_STG;
        float acc[4][2][4];
#pragma unroll
        for (int g = 0; g < 4; g++)
#pragma unroll
            for (int i = 0; i < 2; i++)
#pragma unroll
                for (int j = 0; j < 4; j++) acc[g][i][j] = 0.0f;

#pragma unroll
        for (int ks = 0; ks < 5; ks++) {
            uint32_t bH[4], bL[4];
            uint32_t rb = (wid * 16 + lr) * 176 + ks * 32 + lc;
            LDSM4(bH, kbase + rb);
            LDSM4(bL, kbase + 22528u + rb);
#pragma unroll
            for (int g = 0; g < 4; g++) {
                MMA_BF16(acc[g][0], qH[ks][g], bH[0], bH[2]);
                MMA_BF16(acc[g][1], qH[ks][g], bH[1], bH[3]);
            }
#pragma unroll
            for (int g = 0; g < 4; g++) {
                MMA_BF16(acc[g][0], qH[ks][g], bL[0], bL[2]);
                MMA_BF16(acc[g][1], qH[ks][g], bL[1], bL[3]);
            }
#pragma unroll
            for (int g = 0; g < 4; g++) {
                MMA_BF16(acc[g][0], qL[ks][g], bH[0], bH[2]);
                MMA_BF16(acc[g][1], qL[ks][g], bH[1], bH[3]);
            }
        }

        // combine interference in registers, write final fp32 scores
#pragma unroll
        for (int n8 = 0; n8 < 2; n8++) {
#pragma unroll
            for (int j = 0; j < 4; j++) {
                int r = rr + (j >> 1) * 8;
                int c = kt * 128 + wid * 16 + n8 * 8 + cc + (j & 1);
                float s  = acc[0][n8][j];
                float a0 = acc[1][n8][j];
                float a1 = acc[2][n8][j];
                float a2 = acc[3][n8][j];
                sc[r * 1032 + c] = s + (a0 * a1 + a0 * a2 + a1 * a2) * intf;
            }
        }
    }
    __syncthreads();

    // ---- Phase 2: softmax -> P (bf16 hi/lo) ----
#pragma unroll
    for (int t2 = 0; t2 < 2; t2++) {
        int r = wid * 2 + t2;
        const float* row = sc + r * 1032;
        float mx = -1e30f;
#pragma unroll 8
        for (int j = 0; j < 32; j++) mx = fmaxf(mx, row[lane + j * 32]);
#pragma unroll
        for (int off = 16; off > 0; off >>= 1)
            mx = fmaxf(mx, __shfl_xor_sync(0xffffffffu, mx, off));
        float sum = 0.0f;
#pragma unroll 8
        for (int j = 0; j < 32; j++) {
            int c = lane + j * 32;
            float p = __expf(row[c] - mx);
            sum += p;
            __nv_bfloat16 hh = __float2bfloat16(p);
            *(__nv_bfloat16*)(sm + A_OFF_PH + r * 2064 + c * 2) = hh;
            *(__nv_bfloat16*)(sm + A_OFF_PL + r * 2064 + c * 2) =
                __float2bfloat16(p - __bfloat162float(hh));
        }
#pragma unroll
        for (int off = 16; off > 0; off >>= 1)
            sum += __shfl_xor_sync(0xffffffffu, sum, off);
        if (lane == 0) row_l[r] = sum;
    }
    __syncthreads();

    // ---- Phase 3: P @ V ----
    const __nv_bfloat16* VhB = Vh + (size_t)bh * 81920;
    const __nv_bfloat16* VlB = Vl + (size_t)bh * 81920;
    auto load_v = [&](int kt, int stg) {
#pragma unroll
        for (int j = 0; j < 10; j++) {
            int idx = tid + j * 256;
            int m = idx >= 1280;
            int rem = m ? idx - 1280 : idx;
            int dim = rem >> 4, ch = rem & 15;
            const __nv_bfloat16* g =
                (m ? VlB : VhB) + (size_t)dim * 1024 + kt * 128 + ch * 8;
            CP16(base + A_OFF_V + stg * 43520 + m * 21760 + dim * 272 + ch * 16, g);
        }
        asm volatile("cp.async.commit_group;");
    };

    load_v(0, 0);
    float acc[10][4];
#pragma unroll
    for (int i = 0; i < 10; i++)
#pragma unroll
        for (int j = 0; j < 4; j++) acc[i][j] = 0.0f;

    for (int kt = 0; kt < 8; kt++) {
        const int stg = kt & 1;
        if (kt < 7) {
            load_v(kt + 1, stg ^ 1);
            asm volatile("cp.async.wait_group 1;");
        } else {
            asm volatile("cp.async.wait_group 0;");
        }
        __syncthreads();

        uint32_t aH[4], aL[4];
        uint32_t ro = lr * 2064 + kt * 256 + wid * 32 + lc;
        LDSM4(aH, base + A_OFF_PH + ro);
        LDSM4(aL, base + A_OFF_PL + ro);
        uint32_t bH[5][4], bL[5][4];
#pragma unroll
        for (int nd = 0; nd < 5; nd++) {
            uint32_t rb = stg * 43520 + (nd * 16 + lr) * 272 + wid * 32 + lc;
            LDSM4(bH[nd], base + A_OFF_V + rb);
            LDSM4(bL[nd], base + A_OFF_V + 21760 + rb);
        }
#pragma unroll
        for (int nd = 0; nd < 5; nd++) {
            MMA_BF16(acc[nd * 2],     aH, bH[nd][0], bH[nd][2]);
            MMA_BF16(acc[nd * 2 + 1], aH, bH[nd][1], bH[nd][3]);
        }
#pragma unroll
        for (int nd = 0; nd < 5; nd++) {
            MMA_BF16(acc[nd * 2],     aH, bL[nd][0], bL[nd][2]);
            MMA_BF16(acc[nd * 2 + 1], aH, bL[nd][1], bL[nd][3]);
        }
#pragma unroll
        for (int nd = 0; nd < 5; nd++) {
            MMA_BF16(acc[nd * 2],     aL, bH[nd][0], bH[nd][2]);
            MMA_BF16(acc[nd * 2 + 1], aL, bH[nd][1], bH[nd][3]);
        }
        __syncthreads();
    }

    float* red = (float*)(sm + A_OFF_RED);
    float* redw = red + wid * 1344;
#pragma unroll
    for (int j = 0; j < 10; j++) {
        int d = (j >> 1) * 16 + (j & 1) * 8 + cc;
        redw[rr * 84 + d]           = acc[j][0];
        redw[rr * 84 + d + 1]       = acc[j][1];
        redw[(rr + 8) * 84 + d]     = acc[j][2];
        redw[(rr + 8) * 84 + d + 1] = acc[j][3];
    }
    __syncthreads();

    const float cph = cosf(qp[h]);
    for (int idx = tid; idx < 1280; idx += 256) {
        int r = idx / 80, d = idx - r * 80;
        float s = 0.0f;
#pragma unroll
        for (int w = 0; w < 8; w++) s += red[w * 1344 + r * 84 + d];
        float o = s * cph / row_l[r];
        size_t go = (size_t)(b * 1024 + q0 + r) * 2560 + h * 80 + d;
        __nv_bfloat16 hh = __float2bfloat16(o);
        out_hi[go] = hh;
        out_lo[go] = __float2bfloat16(o - __bfloat162float(hh));
    }
}

// ---------------------------------------------------------------------------
extern "C" void kernel_launch(void* const* d_in, const int* in_sizes, int n_in,
                              void* d_out, int out_size) {
    const float* hidden = (const float*)d_in[0];
    const float* Wqkv   = (const float*)d_in[1];
    const float* bqkv   = (const float*)d_in[2];
    const float* Wproj  = (const float*)d_in[3];
    const float* bproj  = (const float*)d_in[4];
    const float* gm     = (const float*)d_in[5];
    const float* gp     = (const float*)d_in[6];
    const float* ga     = (const float*)d_in[7];
    const float* qp     = (const float*)d_in[8];
    const float* isr    = (const float*)d_in[9];
    float* out = (float*)d_out;

    void *p_qkv, *p_hh, *p_hl, *p_wqh, *p_wql, *p_wph, *p_wpl, *p_ah, *p_al;
    void *p_kh, *p_kl, *p_vh, *p_vl;
    cudaGetSymbolAddress(&p_qkv, g_qkv);
    cudaGetSymbolAddress(&p_hh, g_hid_hi);
    cudaGetSymbolAddress(&p_hl, g_hid_lo);
    cudaGetSymbolAddress(&p_wqh, g_wqkvT_hi);
    cudaGetSymbolAddress(&p_wql, g_wqkvT_lo);
    cudaGetSymbolAddress(&p_wph, g_wprojT_hi);
    cudaGetSymbolAddress(&p_wpl, g_wprojT_lo);
    cudaGetSymbolAddress(&p_ah, g_attn_hi);
    cudaGetSymbolAddress(&p_al, g_attn_lo);
    cudaGetSymbolAddress(&p_kh, g_Khi);
    cudaGetSymbolAddress(&p_kl, g_Klo);
    cudaGetSymbolAddress(&p_vh, g_Vthi);
    cudaGetSymbolAddress(&p_vl, g_Vtlo);

    const int GEMM_SMEM = 2 * 49152;
    cudaFuncSetAttribute(gemm_bf16x3,
                         cudaFuncAttributeMaxDynamicSharedMemorySize, GEMM_SMEM);
    cudaFuncSetAttribute(attn_mma,
                         cudaFuncAttributeMaxDynamicSharedMemorySize, A_SMEM);

    // 1) input conversions
    conv_hilo<<<5120, 256>>>(hidden, (__nv_bfloat16*)p_hh, (__nv_bfloat16*)p_hl,
                             2048 * 2560 / 4);
    transpose_conv<<<dim3(7680 / 32, 2560 / 32), dim3(32, 8)>>>(
        Wqkv, (__nv_bfloat16*)p_wqh, (__nv_bfloat16*)p_wql, 2560, 7680);
    transpose_conv<<<dim3(2560 / 32, 2560 / 32), dim3(32, 8)>>>(
        Wproj, (__nv_bfloat16*)p_wph, (__nv_bfloat16*)p_wpl, 2560, 2560);

    // 2) qkv = hidden @ Wqkv + bqkv
    gemm_bf16x3<<<dim3(120, 16), 256, GEMM_SMEM>>>(
        (const __nv_bfloat16*)p_hh, (const __nv_bfloat16*)p_hl,
        (const __nv_bfloat16*)p_wqh, (const __nv_bfloat16*)p_wql,
        bqkv, (float*)p_qkv, 7680);

    // 3) K/V conversion for tensor-core attention
    prep_k<<<20480, 256>>>((const float*)p_qkv, (__nv_bfloat16*)p_kh,
                           (__nv_bfloat16*)p_kl);
    prep_vt<<<dim3(16, 5, 64), dim3(16, 16)>>>(
        (const float*)p_qkv, (__nv_bfloat16*)p_vh, (__nv_bfloat16*)p_vl);

    // 4) tensor-core quantum attention -> bf16 hi/lo
    attn_mma<<<dim3(64, 64), 256, A_SMEM>>>(
        (const float*)p_qkv,
        (const __nv_bfloat16*)p_kh, (const __nv_bfloat16*)p_kl,
        (const __nv_bfloat16*)p_vh, (const __nv_bfloat16*)p_vl,
        gm, gp, ga, qp, isr,
        (__nv_bfloat16*)p_ah, (__nv_bfloat16*)p_al);

    // 5) out = attn @ Wproj + bproj
    gemm_bf16x3<<<dim3(40, 16), 256, GEMM_SMEM>>>(
        (const __nv_bfloat16*)p_ah, (const __nv_bfloat16*)p_al,
        (const __nv_bfloat16*)p_wph, (const __nv_bfloat16*)p_wpl,
        bproj, out, 2560);
}

// round 9
// speedup vs baseline: 1.4194x; 1.4194x over previous
#include <cuda_runtime.h>
#include <cuda_bf16.h>
#include <stdint.h>
#include <math.h>

// Problem constants: B=2, S=1024, E=2560, H=32, D=80, 3E=7680, BS=2048, K=2560

// ---------------- device scratch ----------------
__device__ float g_q[2048ull * 2560];                  // q part, fp32 compact
__device__ __nv_bfloat16 g_hid_hi[2048ull * 2560];
__device__ __nv_bfloat16 g_hid_lo[2048ull * 2560];
__device__ __nv_bfloat16 g_wqkvT_hi[7680ull * 2560];   // (N,K)
__device__ __nv_bfloat16 g_wqkvT_lo[7680ull * 2560];
__device__ __nv_bfloat16 g_wprojT_hi[2560ull * 2560];
__device__ __nv_bfloat16 g_wprojT_lo[2560ull * 2560];
__device__ __nv_bfloat16 g_attn_hi[2048ull * 2560];
__device__ __nv_bfloat16 g_attn_lo[2048ull * 2560];
__device__ __nv_bfloat16 g_Khi[64ull * 1024 * 88];     // [bh][key][88]
__device__ __nv_bfloat16 g_Klo[64ull * 1024 * 88];
__device__ __nv_bfloat16 g_Vthi[64ull * 80 * 1024];    // [bh][dim][1024]
__device__ __nv_bfloat16 g_Vtlo[64ull * 80 * 1024];

__device__ __forceinline__ uint32_t smem_u32(const void* p) {
    uint32_t a;
    asm("{ .reg .u64 t; cvta.to.shared.u64 t, %1; cvt.u32.u64 %0, t; }"
        : "=r"(a) : "l"(p));
    return a;
}

#define SWZ(o) ((uint32_t)(o) ^ ((((uint32_t)(o)) >> 3) & 0x70u))

#define CP16(s, g) \
    asm volatile("cp.async.cg.shared.global [%0], [%1], 16;" :: "r"(s), "l"(g))

#define LDSM4(r, addr) \
    asm volatile("ldmatrix.sync.aligned.m8n8.x4.shared.b16 {%0,%1,%2,%3}, [%4];" \
                 : "=r"((r)[0]), "=r"((r)[1]), "=r"((r)[2]), "=r"((r)[3]) \
                 : "r"(addr))

#define MMA_BF16(acc, A, b0, b1) \
    asm volatile("mma.sync.aligned.m16n8k16.row.col.f32.bf16.bf16.f32 " \
                 "{%0,%1,%2,%3}, {%4,%5,%6,%7}, {%8,%9}, {%0,%1,%2,%3};" \
                 : "+f"((acc)[0]), "+f"((acc)[1]), "+f"((acc)[2]), "+f"((acc)[3]) \
                 : "r"((A)[0]), "r"((A)[1]), "r"((A)[2]), "r"((A)[3]), \
                   "r"(b0), "r"(b1))

// ---------------------------------------------------------------------------
// Conversion: fp32 -> bf16 hi/lo
// ---------------------------------------------------------------------------
__global__ void conv_hilo(const float* __restrict__ X,
                          __nv_bfloat16* __restrict__ Hh,
                          __nv_bfloat16* __restrict__ Ll, int n4) {
    int i = blockIdx.x * blockDim.x + threadIdx.x;
    if (i >= n4) return;
    float4 v = ((const float4*)X)[i];
    __nv_bfloat16 h0 = __float2bfloat16(v.x), h1 = __float2bfloat16(v.y);
    __nv_bfloat16 h2 = __float2bfloat16(v.z), h3 = __float2bfloat16(v.w);
    __nv_bfloat162 a, b;
    a.x = h0; a.y = h1; b.x = h2; b.y = h3;
    ((__nv_bfloat162*)Hh)[i * 2] = a;
    ((__nv_bfloat162*)Hh)[i * 2 + 1] = b;
    __nv_bfloat162 c, d;
    c.x = __float2bfloat16(v.x - __bfloat162float(h0));
    c.y = __float2bfloat16(v.y - __bfloat162float(h1));
    d.x = __float2bfloat16(v.z - __bfloat162float(h2));
    d.y = __float2bfloat16(v.w - __bfloat162float(h3));
    ((__nv_bfloat162*)Ll)[i * 2] = c;
    ((__nv_bfloat162*)Ll)[i * 2 + 1] = d;
}

// ---------------------------------------------------------------------------
// Transpose + convert both weights in one launch (z=0: Wqkv, z=1: Wproj)
// ---------------------------------------------------------------------------
__global__ void transpose_conv2(const float* __restrict__ Wq,
                                const float* __restrict__ Wp,
                                __nv_bfloat16* __restrict__ Tqh,
                                __nv_bfloat16* __restrict__ Tql,
                                __nv_bfloat16* __restrict__ Tph,
                                __nv_bfloat16* __restrict__ Tpl) {
    __shared__ float t[32][33];
    const int z = blockIdx.z;
    if (z == 1 && blockIdx.x >= 80) return;
    const float* W = z ? Wp : Wq;
    __nv_bfloat16* Th = z ? Tph : Tqh;
    __nv_bfloat16* Tl = z ? Tpl : Tql;
    const int N = z ? 2560 : 7680;
    const int K = 2560;
    int n0 = blockIdx.x * 32, k0 = blockIdx.y * 32;
    int tx = threadIdx.x, ty = threadIdx.y;
#pragma unroll
    for (int j = 0; j < 4; j++)
        t[ty + j * 8][tx] = W[(size_t)(k0 + ty + j * 8) * N + n0 + tx];
    __syncthreads();
#pragma unroll
    for (int j = 0; j < 4; j++) {
        float v = t[tx][ty + j * 8];
        __nv_bfloat16 h = __float2bfloat16(v);
        size_t o = (size_t)(n0 + ty + j * 8) * K + k0 + tx;
        Th[o] = h;
        Tl[o] = __float2bfloat16(v - __bfloat162float(h));
    }
}

// ---------------------------------------------------------------------------
// GEMM1 (fused): qkv = hidden @ WqkvT^T + bias, epilogue routes by column:
//   cols [0,2560)    -> g_q fp32 compact
//   cols [2560,5120) -> K bf16 hi/lo [bh][key][88]
//   cols [5120,7680) -> V bf16 hi/lo transposed [bh][dim][1024]
// CTA 128x128, 512 threads (16 warps, 32x32 warp tiles), 3-stage cp.async.
// ---------------------------------------------------------------------------
__global__ __launch_bounds__(512, 1) void gemm_qkv(
    const __nv_bfloat16* __restrict__ Ah, const __nv_bfloat16* __restrict__ Al,
    const __nv_bfloat16* __restrict__ Bh, const __nv_bfloat16* __restrict__ Bl,
    const float* __restrict__ bias, float* __restrict__ Qout,
    __nv_bfloat16* __restrict__ Kh, __nv_bfloat16* __restrict__ Kl,
    __nv_bfloat16* __restrict__ Vh, __nv_bfloat16* __restrict__ Vl) {
    extern __shared__ __align__(1024) char dsm[];
    const uint32_t base = smem_u32(dsm);

    const int tid = threadIdx.x;
    const int wid = tid >> 5, lane = tid & 31;
    const int mw = wid & 3;
    const int nw = wid >> 2;
    const int mt = blockIdx.y, nt = blockIdx.x;
    const int K = 2560;

    const int trow = tid >> 3;    // 0..63
    const int tkg = tid & 7;

    float acc[2][4][4];
#pragma unroll
    for (int a = 0; a < 2; a++)
#pragma unroll
        for (int b = 0; b < 4; b++)
#pragma unroll
            for (int c = 0; c < 4; c++) acc[a][b][c] = 0.0f;

    auto load_chunk = [&](int c, int st) {
        const int k0 = c * 64;
        const uint32_t s0 = base + st * 65536;
#pragma unroll
        for (int j = 0; j < 2; j++) {
            const int row = j * 64 + trow;
            const uint32_t so = SWZ(row * 128 + tkg * 16);
            CP16(s0 + so, Ah + (size_t)(mt * 128 + row) * K + k0 + tkg * 8);
            CP16(s0 + 16384 + so, Al + (size_t)(mt * 128 + row) * K + k0 + tkg * 8);
            CP16(s0 + 32768 + so, Bh + (size_t)(nt * 128 + row) * K + k0 + tkg * 8);
            CP16(s0 + 49152 + so, Bl + (size_t)(nt * 128 + row) * K + k0 + tkg * 8);
        }
        asm volatile("cp.async.commit_group;");
    };

    const int lr = lane & 15;
    const int lc = (lane >> 4) * 16;

    load_chunk(0, 0);
    load_chunk(1, 1);

    int st = 0;
    for (int c = 0; c < 40; c++) {
        if (c < 39) {
            asm volatile("cp.async.wait_group 1;");
        } else {
            asm volatile("cp.async.wait_group 0;");
        }
        __syncthreads();
        if (c + 2 < 40) {
            int st2 = st + 2;
            if (st2 >= 3) st2 -= 3;
            load_chunk(c + 2, st2);
        }

        const uint32_t sA = base + st * 65536;
#pragma unroll
        for (int ks = 0; ks < 4; ks++) {
            uint32_t ah[2][4], al[2][4];
#pragma unroll
            for (int mb = 0; mb < 2; mb++) {
                const uint32_t ro = (mw * 32 + mb * 16 + lr) * 128 + ks * 32 + lc;
                LDSM4(ah[mb], sA + SWZ(ro));
                LDSM4(al[mb], sA + 16384 + SWZ(ro));
            }
            uint32_t bh2[2][4], bl2[2][4];
#pragma unroll
            for (int nb = 0; nb < 2; nb++) {
                const uint32_t ro = (nw * 32 + nb * 16 + lr) * 128 + ks * 32 + lc;
                LDSM4(bh2[nb], sA + 32768 + SWZ(ro));
                LDSM4(bl2[nb], sA + 49152 + SWZ(ro));
            }
#pragma unroll
            for (int mb = 0; mb < 2; mb++)
#pragma unroll
                for (int nb = 0; nb < 2; nb++) {
                    MMA_BF16(acc[mb][nb * 2],     ah[mb], bh2[nb][0], bh2[nb][2]);
                    MMA_BF16(acc[mb][nb * 2 + 1], ah[mb], bh2[nb][1], bh2[nb][3]);
                }
#pragma unroll
            for (int mb = 0; mb < 2; mb++)
#pragma unroll
                for (int nb = 0; nb < 2; nb++) {
                    MMA_BF16(acc[mb][nb * 2],     ah[mb], bl2[nb][0], bl2[nb][2]);
                    MMA_BF16(acc[mb][nb * 2 + 1], ah[mb], bl2[nb][1], bl2[nb][3]);
                }
#pragma unroll
            for (int mb = 0; mb < 2; mb++)
#pragma unroll
                for (int nb = 0; nb < 2; nb++) {
                    MMA_BF16(acc[mb][nb * 2],     al[mb], bh2[nb][0], bh2[nb][2]);
                    MMA_BF16(acc[mb][nb * 2 + 1], al[mb], bh2[nb][1], bh2[nb][3]);
                }
        }
        st++;
        if (st >= 3) st -= 3;
    }

    const int row0 = mt * 128 + mw * 32 + (lane >> 2);
    const int col0 = nt * 128 + nw * 32 + 2 * (lane & 3);

    if (nt < 20) {
        // q region -> compact fp32
#pragma unroll
        for (int mb = 0; mb < 2; mb++) {
#pragma unroll
            for (int n8 = 0; n8 < 4; n8++) {
                const int gc = col0 + n8 * 8;
                const float b0 = bias[gc], b1 = bias[gc + 1];
                const int r = row0 + mb * 16;
                float2 o0 = make_float2(acc[mb][n8][0] + b0, acc[mb][n8][1] + b1);
                float2 o1 = make_float2(acc[mb][n8][2] + b0, acc[mb][n8][3] + b1);
                *(float2*)&Qout[(size_t)r * 2560 + gc] = o0;
                *(float2*)&Qout[(size_t)(r + 8) * 2560 + gc] = o1;
            }
        }
    } else {
        const bool isK = (nt < 40);
        const int cbase = isK ? 2560 : 5120;
        __nv_bfloat16* Oh = isK ? Kh : Vh;
        __nv_bfloat16* Ol = isK ? Kl : Vl;
#pragma unroll
        for (int mb = 0; mb < 2; mb++) {
#pragma unroll
            for (int n8 = 0; n8 < 4; n8++) {
#pragma unroll
                for (int e = 0; e < 4; e++) {
                    const int gc = col0 + n8 * 8 + (e & 1);
                    const int r = row0 + mb * 16 + (e >> 1) * 8;
                    float val = acc[mb][n8][e] + bias[gc];
                    const int c2 = gc - cbase;
                    const int h = c2 / 80;
                    const int d = c2 - h * 80;
                    const int bb = r >> 10, key = r & 1023;
                    const int bh = bb * 32 + h;
                    const size_t o = isK
                        ? ((size_t)bh * 90112 + (size_t)key * 88 + d)
                        : ((size_t)bh * 81920 + (size_t)d * 1024 + key);
                    __nv_bfloat16 hh = __float2bfloat16(val);
                    Oh[o] = hh;
                    Ol[o] = __float2bfloat16(val - __bfloat162float(hh));
                }
            }
        }
    }
}

// ---------------------------------------------------------------------------
// Generic mma.sync bf16x3 GEMM (R6 proven): C(2048,N) = A @ B^T + bias
// CTA 128x128, 512 threads, warp tile 32x32, 3-stage cp.async.
// ---------------------------------------------------------------------------
__global__ __launch_bounds__(512, 1) void gemm_bf16x3(
    const __nv_bfloat16* __restrict__ Ah, const __nv_bfloat16* __restrict__ Al,
    const __nv_bfloat16* __restrict__ Bh, const __nv_bfloat16* __restrict__ Bl,
    const float* __restrict__ bias, float* __restrict__ C, int N) {
    extern __shared__ __align__(1024) char dsm[];
    const uint32_t base = smem_u32(dsm);

    const int tid = threadIdx.x;
    const int wid = tid >> 5, lane = tid & 31;
    const int mw = wid & 3;
    const int nw = wid >> 2;
    const int mt = blockIdx.y, nt = blockIdx.x;
    const int K = 2560;

    const int trow = tid >> 3;
    const int tkg = tid & 7;

    float acc[2][4][4];
#pragma unroll
    for (int a = 0; a < 2; a++)
#pragma unroll
        for (int b = 0; b < 4; b++)
#pragma unroll
            for (int c = 0; c < 4; c++) acc[a][b][c] = 0.0f;

    auto load_chunk = [&](int c, int st) {
        const int k0 = c * 64;
        const uint32_t s0 = base + st * 65536;
#pragma unroll
        for (int j = 0; j < 2; j++) {
            const int row = j * 64 + trow;
            const uint32_t so = SWZ(row * 128 + tkg * 16);
            CP16(s0 + so, Ah + (size_t)(mt * 128 + row) * K + k0 + tkg * 8);
            CP16(s0 + 16384 + so, Al + (size_t)(mt * 128 + row) * K + k0 + tkg * 8);
            CP16(s0 + 32768 + so, Bh + (size_t)(nt * 128 + row) * K + k0 + tkg * 8);
            CP16(s0 + 49152 + so, Bl + (size_t)(nt * 128 + row) * K + k0 + tkg * 8);
        }
        asm volatile("cp.async.commit_group;");
    };

    const int lr = lane & 15;
    const int lc = (lane >> 4) * 16;

    load_chunk(0, 0);
    load_chunk(1, 1);

    int st = 0;
    for (int c = 0; c < 40; c++) {
        if (c < 39) {
            asm volatile("cp.async.wait_group 1;");
        } else {
            asm volatile("cp.async.wait_group 0;");
        }
        __syncthreads();
        if (c + 2 < 40) {
            int st2 = st + 2;
            if (st2 >= 3) st2 -= 3;
            load_chunk(c + 2, st2);
        }

        const uint32_t sA = base + st * 65536;
#pragma unroll
        for (int ks = 0; ks < 4; ks++) {
            uint32_t ah[2][4], al[2][4];
#pragma unroll
            for (int mb = 0; mb < 2; mb++) {
                const uint32_t ro = (mw * 32 + mb * 16 + lr) * 128 + ks * 32 + lc;
                LDSM4(ah[mb], sA + SWZ(ro));
                LDSM4(al[mb], sA + 16384 + SWZ(ro));
            }
            uint32_t bh2[2][4], bl2[2][4];
#pragma unroll
            for (int nb = 0; nb < 2; nb++) {
                const uint32_t ro = (nw * 32 + nb * 16 + lr) * 128 + ks * 32 + lc;
                LDSM4(bh2[nb], sA + 32768 + SWZ(ro));
                LDSM4(bl2[nb], sA + 49152 + SWZ(ro));
            }
#pragma unroll
            for (int mb = 0; mb < 2; mb++)
#pragma unroll
                for (int nb = 0; nb < 2; nb++) {
                    MMA_BF16(acc[mb][nb * 2],     ah[mb], bh2[nb][0], bh2[nb][2]);
                    MMA_BF16(acc[mb][nb * 2 + 1], ah[mb], bh2[nb][1], bh2[nb][3]);
                }
#pragma unroll
            for (int mb = 0; mb < 2; mb++)
#pragma unroll
                for (int nb = 0; nb < 2; nb++) {
                    MMA_BF16(acc[mb][nb * 2],     ah[mb], bl2[nb][0], bl2[nb][2]);
                    MMA_BF16(acc[mb][nb * 2 + 1], ah[mb], bl2[nb][1], bl2[nb][3]);
                }
#pragma unroll
            for (int mb = 0; mb < 2; mb++)
#pragma unroll
                for (int nb = 0; nb < 2; nb++) {
                    MMA_BF16(acc[mb][nb * 2],     al[mb], bh2[nb][0], bh2[nb][2]);
                    MMA_BF16(acc[mb][nb * 2 + 1], al[mb], bh2[nb][1], bh2[nb][3]);
                }
        }
        st++;
        if (st >= 3) st -= 3;
    }

    const int row0 = mt * 128 + mw * 32 + (lane >> 2);
    const int col0 = nt * 128 + nw * 32 + 2 * (lane & 3);
#pragma unroll
    for (int mb = 0; mb < 2; mb++) {
#pragma unroll
        for (int n8 = 0; n8 < 4; n8++) {
            const int gc = col0 + n8 * 8;
            const float b0 = bias[gc], b1 = bias[gc + 1];
            const int r = row0 + mb * 16;
            float2 o0 = make_float2(acc[mb][n8][0] + b0, acc[mb][n8][1] + b1);
            float2 o1 = make_float2(acc[mb][n8][2] + b0, acc[mb][n8][3] + b1);
            *(float2*)&C[(size_t)r * N + gc] = o0;
            *(float2*)&C[(size_t)(r + 8) * N + gc] = o1;
        }
    }
}

// ---------------------------------------------------------------------------
// attn_mma (R6 v2, proven): warp = 16-key slice, 4 variants in registers.
// ---------------------------------------------------------------------------
#define A_OFF_QH 0u
#define A_OFF_QL 11264u
#define A_OFF_K  22528u
#define A_K_STG  45056u
#define A_OFF_SC 112640u
#define A_OFF_PH 0u
#define A_OFF_PL 33024u
#define A_OFF_V 67584u
#define A_OFF_RED 154624u
#define A_SMEM 197632

__global__ __launch_bounds__(256, 1) void attn_mma(
    const float* __restrict__ qsrc,
    const __nv_bfloat16* __restrict__ Kh, const __nv_bfloat16* __restrict__ Kl,
    const __nv_bfloat16* __restrict__ Vh, const __nv_bfloat16* __restrict__ Vl,
    const float* __restrict__ gm, const float* __restrict__ gp,
    const float* __restrict__ ga, const float* __restrict__ qp,
    const float* __restrict__ isr,
    __nv_bfloat16* __restrict__ out_hi, __nv_bfloat16* __restrict__ out_lo) {
    extern __shared__ __align__(128) char smc[];
    __shared__ float coeff[240];
    __shared__ float row_l[16];
    char* sm = smc;
    const uint32_t base = smem_u32(smc);

    const int tid = threadIdx.x;
    const int wid = tid >> 5, lane = tid & 31;
    const int lr = lane & 15, lc = (lane >> 4) << 4;
    const int rr = lane >> 2, cc = (lane & 3) * 2;
    const int bh = blockIdx.y, b = bh >> 5, h = bh & 31;
    const int q0 = blockIdx.x * 16;

    const __nv_bfloat16* KhB = Kh + (size_t)bh * 90112;
    const __nv_bfloat16* KlB = Kl + (size_t)bh * 90112;
    auto load_k = [&](int kt, int stg) {
        const uint32_t sb = base + A_OFF_K + (uint32_t)stg * A_K_STG;
#pragma unroll
        for (int j = 0; j < 11; j++) {
            int idx = tid + j * 256;
            int m = idx >= 1408;
            int rem = m ? idx - 1408 : idx;
            int row = rem / 11, ch = rem - row * 11;
            const __nv_bfloat16* g =
                (m ? KlB : KhB) + (size_t)(kt * 128 + row) * 88 + ch * 8;
            CP16(sb + m * 22528u + row * 176 + ch * 16, g);
        }
        asm volatile("cp.async.commit_group;");
    };

    load_k(0, 0);

    if (tid < 240) {
        int g = tid / 80, d = tid - g * 80;
        float r0 = gm[g * 4 + 0] + gm[g * 4 + 1];
        float r1 = gm[g * 4 + 2] + gm[g * 4 + 3];
        float ph = gp[g * 80 + d];
        coeff[tid] = (cosf(ph) * r0 + sinf(ph) * r1) * ga[g * 80 + d];
    }
    __syncthreads();

    // build Qext (4 variants x 16 rows x 80 dims, scale folded in)
    const float scale = rsqrtf(80.0f);
    for (int idx = tid; idx < 1280; idx += 256) {
        int r = idx / 80, d = idx - r * 80;
        float v = qsrc[(size_t)(b * 1024 + q0 + r) * 2560 + h * 80 + d] * scale;
        float vv[4] = {v, v * coeff[d], v * coeff[80 + d], v * coeff[160 + d]};
#pragma unroll
        for (int g = 0; g < 4; g++) {
            uint32_t o = (g * 16 + r) * 176 + d * 2;
            __nv_bfloat16 hh = __float2bfloat16(vv[g]);
            *(__nv_bfloat16*)(sm + A_OFF_QH + o) = hh;
            *(__nv_bfloat16*)(sm + A_OFF_QL + o) =
                __float2bfloat16(vv[g] - __bfloat162float(hh));
        }
    }

    const float intf = isr[0] * (1.0f / 3.0f);
    float* sc = (float*)(sm + A_OFF_SC);     // 16 x 1032

    // ---- Phase 1: scores; warp wid owns keys [kt*128 + wid*16, +16) ----
    for (int kt = 0; kt < 8; kt++) {
        const int stg = kt & 1;
        asm volatile("cp.async.wait_group 0;");
        __syncthreads();
        if (kt < 7) load_k(kt + 1, stg ^ 1);

        const uint32_t kbase = base + A_OFF_K + (uint32_t)stg * A_K_STG;
        float acc[4][2][4];
#pragma unroll
        for (int g = 0; g < 4; g++)
#pragma unroll
            for (int i = 0; i < 2; i++)
#pragma unroll
                for (int j = 0; j < 4; j++) acc[g][i][j] = 0.0f;

#pragma unroll
        for (int ks = 0; ks < 5; ks++) {
            uint32_t aH[4][4], aL[4][4];
#pragma unroll
            for (int g = 0; g < 4; g++) {
                uint32_t ro = (g * 16 + lr) * 176 + ks * 32 + lc;
                LDSM4(aH[g], base + A_OFF_QH + ro);
                LDSM4(aL[g], base + A_OFF_QL + ro);
            }
            uint32_t bH[4], bL[4];
            uint32_t rb = (wid * 16 + lr) * 176 + ks * 32 + lc;
            LDSM4(bH, kbase + rb);
            LDSM4(bL, kbase + 22528u + rb);
#pragma unroll
            for (int g = 0; g < 4; g++) {
                MMA_BF16(acc[g][0], aH[g], bH[0], bH[2]);
                MMA_BF16(acc[g][1], aH[g], bH[1], bH[3]);
            }
#pragma unroll
            for (int g = 0; g < 4; g++) {
                MMA_BF16(acc[g][0], aH[g], bL[0], bL[2]);
                MMA_BF16(acc[g][1], aH[g], bL[1], bL[3]);
            }
#pragma unroll
            for (int g = 0; g < 4; g++) {
                MMA_BF16(acc[g][0], aL[g], bH[0], bH[2]);
                MMA_BF16(acc[g][1], aL[g], bH[1], bH[3]);
            }
        }

        // combine interference in registers, write final fp32 scores
#pragma unroll
        for (int n8 = 0; n8 < 2; n8++) {
#pragma unroll
            for (int j = 0; j < 4; j++) {
                int r = rr + (j >> 1) * 8;
                int c = kt * 128 + wid * 16 + n8 * 8 + cc + (j & 1);
                float s  = acc[0][n8][j];
                float a0 = acc[1][n8][j];
                float a1 = acc[2][n8][j];
                float a2 = acc[3][n8][j];
                sc[r * 1032 + c] = s + (a0 * a1 + a0 * a2 + a1 * a2) * intf;
            }
        }
    }
    __syncthreads();

    // ---- Phase 2: softmax -> P (bf16 hi/lo) ----
#pragma unroll
    for (int t2 = 0; t2 < 2; t2++) {
        int r = wid * 2 + t2;
        const float* row = sc + r * 1032;
        float mx = -1e30f;
#pragma unroll 8
        for (int j = 0; j < 32; j++) mx = fmaxf(mx, row[lane + j * 32]);
#pragma unroll
        for (int off = 16; off > 0; off >>= 1)
            mx = fmaxf(mx, __shfl_xor_sync(0xffffffffu, mx, off));
        float sum = 0.0f;
#pragma unroll 8
        for (int j = 0; j < 32; j++) {
            int c = lane + j * 32;
            float p = __expf(row[c] - mx);
            sum += p;
            __nv_bfloat16 hh = __float2bfloat16(p);
            *(__nv_bfloat16*)(sm + A_OFF_PH + r * 2064 + c * 2) = hh;
            *(__nv_bfloat16*)(sm + A_OFF_PL + r * 2064 + c * 2) =
                __float2bfloat16(p - __bfloat162float(hh));
        }
#pragma unroll
        for (int off = 16; off > 0; off >>= 1)
            sum += __shfl_xor_sync(0xffffffffu, sum, off);
        if (lane == 0) row_l[r] = sum;
    }
    __syncthreads();

    // ---- Phase 3: P @ V ----
    const __nv_bfloat16* VhB = Vh + (size_t)bh * 81920;
    const __nv_bfloat16* VlB = Vl + (size_t)bh * 81920;
    auto load_v = [&](int kt, int stg) {
#pragma unroll
        for (int j = 0; j < 10; j++) {
            int idx = tid + j * 256;
            int m = idx >= 1280;
            int rem = m ? idx - 1280 : idx;
            int dim = rem >> 4, ch = rem & 15;
            const __nv_bfloat16* g =
                (m ? VlB : VhB) + (size_t)dim * 1024 + kt * 128 + ch * 8;
            CP16(base + A_OFF_V + stg * 43520 + m * 21760 + dim * 272 + ch * 16, g);
        }
        asm volatile("cp.async.commit_group;");
    };

    load_v(0, 0);
    float acc[10][4];
#pragma unroll
    for (int i = 0; i < 10; i++)
#pragma unroll
        for (int j = 0; j < 4; j++) acc[i][j] = 0.0f;

    for (int kt = 0; kt < 8; kt++) {
        const int stg = kt & 1;
        if (kt < 7) {
            load_v(kt + 1, stg ^ 1);
            asm volatile("cp.async.wait_group 1;");
        } else {
            asm volatile("cp.async.wait_group 0;");
        }
        __syncthreads();

        uint32_t aH[4], aL[4];
        uint32_t ro = lr * 2064 + kt * 256 + wid * 32 + lc;
        LDSM4(aH, base + A_OFF_PH + ro);
        LDSM4(aL, base + A_OFF_PL + ro);
        uint32_t bH[5][4], bL[5][4];
#pragma unroll
        for (int nd = 0; nd < 5; nd++) {
            uint32_t rb = stg * 43520 + (nd * 16 + lr) * 272 + wid * 32 + lc;
            LDSM4(bH[nd], base + A_OFF_V + rb);
            LDSM4(bL[nd], base + A_OFF_V + 21760 + rb);
        }
#pragma unroll
        for (int nd = 0; nd < 5; nd++) {
            MMA_BF16(acc[nd * 2],     aH, bH[nd][0], bH[nd][2]);
            MMA_BF16(acc[nd * 2 + 1], aH, bH[nd][1], bH[nd][3]);
        }
#pragma unroll
        for (int nd = 0; nd < 5; nd++) {
            MMA_BF16(acc[nd * 2],     aH, bL[nd][0], bL[nd][2]);
            MMA_BF16(acc[nd * 2 + 1], aH, bL[nd][1], bL[nd][3]);
        }
#pragma unroll
        for (int nd = 0; nd < 5; nd++) {
            MMA_BF16(acc[nd * 2],     aL, bH[nd][0], bH[nd][2]);
            MMA_BF16(acc[nd * 2 + 1], aL, bH[nd][1], bH[nd][3]);
        }
        __syncthreads();
    }

    float* red = (float*)(sm + A_OFF_RED);
    float* redw = red + wid * 1344;
#pragma unroll
    for (int j = 0; j < 10; j++) {
        int d = (j >> 1) * 16 + (j & 1) * 8 + cc;
        redw[rr * 84 + d]           = acc[j][0];
        redw[rr * 84 + d + 1]       = acc[j][1];
        redw[(rr + 8) * 84 + d]     = acc[j][2];
        redw[(rr + 8) * 84 + d + 1] = acc[j][3];
    }
    __syncthreads();

    const float cph = cosf(qp[h]);
    for (int idx = tid; idx < 1280; idx += 256) {
        int r = idx / 80, d = idx - r * 80;
        float s = 0.0f;
#pragma unroll
        for (int w = 0; w < 8; w++) s += red[w * 1344 + r * 84 + d];
        float o = s * cph / row_l[r];
        size_t go = (size_t)(b * 1024 + q0 + r) * 2560 + h * 80 + d;
        __nv_bfloat16 hh = __float2bfloat16(o);
        out_hi[go] = hh;
        out_lo[go] = __float2bfloat16(o - __bfloat162float(hh));
    }
}

// ---------------------------------------------------------------------------
extern "C" void kernel_launch(void* const* d_in, const int* in_sizes, int n_in,
                              void* d_out, int out_size) {
    const float* hidden = (const float*)d_in[0];
    const float* Wqkv   = (const float*)d_in[1];
    const float* bqkv   = (const float*)d_in[2];
    const float* Wproj  = (const float*)d_in[3];
    const float* bproj  = (const float*)d_in[4];
    const float* gm     = (const float*)d_in[5];
    const float* gp     = (const float*)d_in[6];
    const float* ga     = (const float*)d_in[7];
    const float* qp     = (const float*)d_in[8];
    const float* isr    = (const float*)d_in[9];
    float* out = (float*)d_out;

    void *p_q, *p_hh, *p_hl, *p_wqh, *p_wql, *p_wph, *p_wpl, *p_ah, *p_al;
    void *p_kh, *p_kl, *p_vh, *p_vl;
    cudaGetSymbolAddress(&p_q, g_q);
    cudaGetSymbolAddress(&p_hh, g_hid_hi);
    cudaGetSymbolAddress(&p_hl, g_hid_lo);
    cudaGetSymbolAddress(&p_wqh, g_wqkvT_hi);
    cudaGetSymbolAddress(&p_wql, g_wqkvT_lo);
    cudaGetSymbolAddress(&p_wph, g_wprojT_hi);
    cudaGetSymbolAddress(&p_wpl, g_wprojT_lo);
    cudaGetSymbolAddress(&p_ah, g_attn_hi);
    cudaGetSymbolAddress(&p_al, g_attn_lo);
    cudaGetSymbolAddress(&p_kh, g_Khi);
    cudaGetSymbolAddress(&p_kl, g_Klo);
    cudaGetSymbolAddress(&p_vh, g_Vthi);
    cudaGetSymbolAddress(&p_vl, g_Vtlo);

    const int GEMM_SMEM = 3 * 65536;
    cudaFuncSetAttribute(gemm_qkv,
                         cudaFuncAttributeMaxDynamicSharedMemorySize, GEMM_SMEM);
    cudaFuncSetAttribute(gemm_bf16x3,
                         cudaFuncAttributeMaxDynamicSharedMemorySize, GEMM_SMEM);
    cudaFuncSetAttribute(attn_mma,
                         cudaFuncAttributeMaxDynamicSharedMemorySize, A_SMEM);

    // 1) input conversions
    conv_hilo<<<5120, 256>>>(hidden, (__nv_bfloat16*)p_hh, (__nv_bfloat16*)p_hl,
                             2048 * 2560 / 4);
    transpose_conv2<<<dim3(240, 80, 2), dim3(32, 8)>>>(
        Wqkv, Wproj,
        (__nv_bfloat16*)p_wqh, (__nv_bfloat16*)p_wql,
        (__nv_bfloat16*)p_wph, (__nv_bfloat16*)p_wpl);

    // 2) fused qkv GEMM: q fp32 compact, k/v directly as bf16 hi/lo layouts
    gemm_qkv<<<dim3(60, 16), 512, GEMM_SMEM>>>(
        (const __nv_bfloat16*)p_hh, (const __nv_bfloat16*)p_hl,
        (const __nv_bfloat16*)p_wqh, (const __nv_bfloat16*)p_wql,
        bqkv, (float*)p_q,
        (__nv_bfloat16*)p_kh, (__nv_bfloat16*)p_kl,
        (__nv_bfloat16*)p_vh, (__nv_bfloat16*)p_vl);

    // 3) tensor-core quantum attention -> bf16 hi/lo
    attn_mma<<<dim3(64, 64), 256, A_SMEM>>>(
        (const float*)p_q,
        (const __nv_bfloat16*)p_kh, (const __nv_bfloat16*)p_kl,
        (const __nv_bfloat16*)p_vh, (const __nv_bfloat16*)p_vl,
        gm, gp, ga, qp, isr,
        (__nv_bfloat16*)p_ah, (__nv_bfloat16*)p_al);

    // 4) out = attn @ Wproj + bproj
    gemm_bf16x3<<<dim3(20, 16), 512, GEMM_SMEM>>>(
        (const __nv_bfloat16*)p_ah, (const __nv_bfloat16*)p_al,
        (const __nv_bfloat16*)p_wph, (const __nv_bfloat16*)p_wpl,
        bproj, out, 2560);
}

// round 11
// speedup vs baseline: 1.6924x; 1.1923x over previous
#include <cuda_runtime.h>
#include <cuda_bf16.h>
#include <cuda_fp16.h>
#include <stdint.h>
#include <math.h>

// Problem constants: B=2, S=1024, E=2560, H=32, D=80, 3E=7680, BS=2048, K=2560

// ---------------- device scratch ----------------
__device__ float g_q[2048ull * 2560];                  // q part, fp32 compact
__device__ __nv_bfloat16 g_hid_hi[2048ull * 2560];
__device__ __nv_bfloat16 g_hid_lo[2048ull * 2560];
__device__ __nv_bfloat16 g_wqkvT_hi[7680ull * 2560];   // (N,K)
__device__ __nv_bfloat16 g_wqkvT_lo[7680ull * 2560];
__device__ __nv_bfloat16 g_wprojT_hi[2560ull * 2560];
__device__ __nv_bfloat16 g_wprojT_lo[2560ull * 2560];
__device__ __nv_bfloat16 g_attn_hi[2048ull * 2560];
__device__ __nv_bfloat16 g_attn_lo[2048ull * 2560];
__device__ __nv_bfloat16 g_Khi[64ull * 1024 * 88];     // [bh][key][88]
__device__ __nv_bfloat16 g_Klo[64ull * 1024 * 88];
__device__ __half g_Vthi[64ull * 80 * 1024];           // [bh][dim][1024] fp16
__device__ __half g_Vtlo[64ull * 80 * 1024];

__device__ __forceinline__ uint32_t smem_u32(const void* p) {
    uint32_t a;
    asm("{ .reg .u64 t; cvta.to.shared.u64 t, %1; cvt.u32.u64 %0, t; }"
        : "=r"(a) : "l"(p));
    return a;
}

#define SWZ(o) ((uint32_t)(o) ^ ((((uint32_t)(o)) >> 3) & 0x70u))

#define CP16(s, g) \
    asm volatile("cp.async.cg.shared.global [%0], [%1], 16;" :: "r"(s), "l"(g))

#define LDSM4(r, addr) \
    asm volatile("ldmatrix.sync.aligned.m8n8.x4.shared.b16 {%0,%1,%2,%3}, [%4];" \
                 : "=r"((r)[0]), "=r"((r)[1]), "=r"((r)[2]), "=r"((r)[3]) \
                 : "r"(addr))

#define MMA_BF16(acc, A, b0, b1) \
    asm volatile("mma.sync.aligned.m16n8k16.row.col.f32.bf16.bf16.f32 " \
                 "{%0,%1,%2,%3}, {%4,%5,%6,%7}, {%8,%9}, {%0,%1,%2,%3};" \
                 : "+f"((acc)[0]), "+f"((acc)[1]), "+f"((acc)[2]), "+f"((acc)[3]) \
                 : "r"((A)[0]), "r"((A)[1]), "r"((A)[2]), "r"((A)[3]), \
                   "r"(b0), "r"(b1))

#define MMA_F16(acc, A, b0, b1) \
    asm volatile("mma.sync.aligned.m16n8k16.row.col.f32.f16.f16.f32 " \
                 "{%0,%1,%2,%3}, {%4,%5,%6,%7}, {%8,%9}, {%0,%1,%2,%3};" \
                 : "+f"((acc)[0]), "+f"((acc)[1]), "+f"((acc)[2]), "+f"((acc)[3]) \
                 : "r"((A)[0]), "r"((A)[1]), "r"((A)[2]), "r"((A)[3]), \
                   "r"(b0), "r"(b1))

__device__ __forceinline__ uint32_t pack_h2(float a, float b) {
    __half2 h = __floats2half2_rn(a, b);
    return *(uint32_t*)&h;
}

// ---------------------------------------------------------------------------
// Conversion: fp32 -> bf16 hi/lo
// ---------------------------------------------------------------------------
__global__ void conv_hilo(const float* __restrict__ X,
                          __nv_bfloat16* __restrict__ Hh,
                          __nv_bfloat16* __restrict__ Ll, int n4) {
    int i = blockIdx.x * blockDim.x + threadIdx.x;
    if (i >= n4) return;
    float4 v = ((const float4*)X)[i];
    __nv_bfloat16 h0 = __float2bfloat16(v.x), h1 = __float2bfloat16(v.y);
    __nv_bfloat16 h2 = __float2bfloat16(v.z), h3 = __float2bfloat16(v.w);
    __nv_bfloat162 a, b;
    a.x = h0; a.y = h1; b.x = h2; b.y = h3;
    ((__nv_bfloat162*)Hh)[i * 2] = a;
    ((__nv_bfloat162*)Hh)[i * 2 + 1] = b;
    __nv_bfloat162 c, d;
    c.x = __float2bfloat16(v.x - __bfloat162float(h0));
    c.y = __float2bfloat16(v.y - __bfloat162float(h1));
    d.x = __float2bfloat16(v.z - __bfloat162float(h2));
    d.y = __float2bfloat16(v.w - __bfloat162float(h3));
    ((__nv_bfloat162*)Ll)[i * 2] = c;
    ((__nv_bfloat162*)Ll)[i * 2 + 1] = d;
}

// ---------------------------------------------------------------------------
// Transpose + convert both weights in one launch (z=0: Wqkv, z=1: Wproj)
// ---------------------------------------------------------------------------
__global__ void transpose_conv2(const float* __restrict__ Wq,
                                const float* __restrict__ Wp,
                                __nv_bfloat16* __restrict__ Tqh,
                                __nv_bfloat16* __restrict__ Tql,
                                __nv_bfloat16* __restrict__ Tph,
                                __nv_bfloat16* __restrict__ Tpl) {
    __shared__ float t[32][33];
    const int z = blockIdx.z;
    if (z == 1 && blockIdx.x >= 80) return;
    const float* W = z ? Wp : Wq;
    __nv_bfloat16* Th = z ? Tph : Tqh;
    __nv_bfloat16* Tl = z ? Tpl : Tql;
    const int N = z ? 2560 : 7680;
    const int K = 2560;
    int n0 = blockIdx.x * 32, k0 = blockIdx.y * 32;
    int tx = threadIdx.x, ty = threadIdx.y;
#pragma unroll
    for (int j = 0; j < 4; j++)
        t[ty + j * 8][tx] = W[(size_t)(k0 + ty + j * 8) * N + n0 + tx];
    __syncthreads();
#pragma unroll
    for (int j = 0; j < 4; j++) {
        float v = t[tx][ty + j * 8];
        __nv_bfloat16 h = __float2bfloat16(v);
        size_t o = (size_t)(n0 + ty + j * 8) * K + k0 + tx;
        Th[o] = h;
        Tl[o] = __float2bfloat16(v - __bfloat162float(h));
    }
}

// ---------------------------------------------------------------------------
// GEMM1 (fused): epilogue routes q->fp32, k->bf16 hi/lo, v->fp16 hi/lo (transposed)
// CTA 128x128, 512 threads, warp tile 32x32, 3-stage cp.async.
// ---------------------------------------------------------------------------
__global__ __launch_bounds__(512, 1) void gemm_qkv(
    const __nv_bfloat16* __restrict__ Ah, const __nv_bfloat16* __restrict__ Al,
    const __nv_bfloat16* __restrict__ Bh, const __nv_bfloat16* __restrict__ Bl,
    const float* __restrict__ bias, float* __restrict__ Qout,
    __nv_bfloat16* __restrict__ Kh, __nv_bfloat16* __restrict__ Kl,
    __half* __restrict__ Vh, __half* __restrict__ Vl) {
    extern __shared__ __align__(1024) char dsm[];
    const uint32_t base = smem_u32(dsm);

    const int tid = threadIdx.x;
    const int wid = tid >> 5, lane = tid & 31;
    const int mw = wid & 3;
    const int nw = wid >> 2;
    const int mt = blockIdx.y, nt = blockIdx.x;
    const int K = 2560;

    const int trow = tid >> 3;
    const int tkg = tid & 7;

    float acc[2][4][4];
#pragma unroll
    for (int a = 0; a < 2; a++)
#pragma unroll
        for (int b = 0; b < 4; b++)
#pragma unroll
            for (int c = 0; c < 4; c++) acc[a][b][c] = 0.0f;

    auto load_chunk = [&](int c, int st) {
        const int k0 = c * 64;
        const uint32_t s0 = base + st * 65536;
#pragma unroll
        for (int j = 0; j < 2; j++) {
            const int row = j * 64 + trow;
            const uint32_t so = SWZ(row * 128 + tkg * 16);
            CP16(s0 + so, Ah + (size_t)(mt * 128 + row) * K + k0 + tkg * 8);
            CP16(s0 + 16384 + so, Al + (size_t)(mt * 128 + row) * K + k0 + tkg * 8);
            CP16(s0 + 32768 + so, Bh + (size_t)(nt * 128 + row) * K + k0 + tkg * 8);
            CP16(s0 + 49152 + so, Bl + (size_t)(nt * 128 + row) * K + k0 + tkg * 8);
        }
        asm volatile("cp.async.commit_group;");
    };

    const int lr = lane & 15;
    const int lc = (lane >> 4) * 16;

    load_chunk(0, 0);
    load_chunk(1, 1);

    int st = 0;
    for (int c = 0; c < 40; c++) {
        if (c < 39) {
            asm volatile("cp.async.wait_group 1;");
        } else {
            asm volatile("cp.async.wait_group 0;");
        }
        __syncthreads();
        if (c + 2 < 40) {
            int st2 = st + 2;
            if (st2 >= 3) st2 -= 3;
            load_chunk(c + 2, st2);
        }

        const uint32_t sA = base + st * 65536;
#pragma unroll
        for (int ks = 0; ks < 4; ks++) {
            uint32_t ah[2][4], al[2][4];
#pragma unroll
            for (int mb = 0; mb < 2; mb++) {
                const uint32_t ro = (mw * 32 + mb * 16 + lr) * 128 + ks * 32 + lc;
                LDSM4(ah[mb], sA + SWZ(ro));
                LDSM4(al[mb], sA + 16384 + SWZ(ro));
            }
            uint32_t bh2[2][4], bl2[2][4];
#pragma unroll
            for (int nb = 0; nb < 2; nb++) {
                const uint32_t ro = (nw * 32 + nb * 16 + lr) * 128 + ks * 32 + lc;
                LDSM4(bh2[nb], sA + 32768 + SWZ(ro));
                LDSM4(bl2[nb], sA + 49152 + SWZ(ro));
            }
#pragma unroll
            for (int mb = 0; mb < 2; mb++)
#pragma unroll
                for (int nb = 0; nb < 2; nb++) {
                    MMA_BF16(acc[mb][nb * 2],     ah[mb], bh2[nb][0], bh2[nb][2]);
                    MMA_BF16(acc[mb][nb * 2 + 1], ah[mb], bh2[nb][1], bh2[nb][3]);
                }
#pragma unroll
            for (int mb = 0; mb < 2; mb++)
#pragma unroll
                for (int nb = 0; nb < 2; nb++) {
                    MMA_BF16(acc[mb][nb * 2],     ah[mb], bl2[nb][0], bl2[nb][2]);
                    MMA_BF16(acc[mb][nb * 2 + 1], ah[mb], bl2[nb][1], bl2[nb][3]);
                }
#pragma unroll
            for (int mb = 0; mb < 2; mb++)
#pragma unroll
                for (int nb = 0; nb < 2; nb++) {
                    MMA_BF16(acc[mb][nb * 2],     al[mb], bh2[nb][0], bh2[nb][2]);
                    MMA_BF16(acc[mb][nb * 2 + 1], al[mb], bh2[nb][1], bh2[nb][3]);
                }
        }
        st++;
        if (st >= 3) st -= 3;
    }

    const int row0 = mt * 128 + mw * 32 + (lane >> 2);
    const int col0 = nt * 128 + nw * 32 + 2 * (lane & 3);

    if (nt < 20) {
#pragma unroll
        for (int mb = 0; mb < 2; mb++) {
#pragma unroll
            for (int n8 = 0; n8 < 4; n8++) {
                const int gc = col0 + n8 * 8;
                const float b0 = bias[gc], b1 = bias[gc + 1];
                const int r = row0 + mb * 16;
                float2 o0 = make_float2(acc[mb][n8][0] + b0, acc[mb][n8][1] + b1);
                float2 o1 = make_float2(acc[mb][n8][2] + b0, acc[mb][n8][3] + b1);
                *(float2*)&Qout[(size_t)r * 2560 + gc] = o0;
                *(float2*)&Qout[(size_t)(r + 8) * 2560 + gc] = o1;
            }
        }
    } else if (nt < 40) {
        // K -> bf16 hi/lo [bh][key][88]
#pragma unroll
        for (int mb = 0; mb < 2; mb++) {
#pragma unroll
            for (int n8 = 0; n8 < 4; n8++) {
#pragma unroll
                for (int e = 0; e < 4; e++) {
                    const int gc = col0 + n8 * 8 + (e & 1);
                    const int r = row0 + mb * 16 + (e >> 1) * 8;
                    float val = acc[mb][n8][e] + bias[gc];
                    const int c2 = gc - 2560;
                    const int h = c2 / 80;
                    const int d = c2 - h * 80;
                    const int bb = r >> 10, key = r & 1023;
                    const size_t o = (size_t)(bb * 32 + h) * 90112 +
                                     (size_t)key * 88 + d;
                    __nv_bfloat16 hh = __float2bfloat16(val);
                    Kh[o] = hh;
                    Kl[o] = __float2bfloat16(val - __bfloat162float(hh));
                }
            }
        }
    } else {
        // V -> fp16 hi/lo transposed [bh][dim][1024]
#pragma unroll
        for (int mb = 0; mb < 2; mb++) {
#pragma unroll
            for (int n8 = 0; n8 < 4; n8++) {
#pragma unroll
                for (int e = 0; e < 4; e++) {
                    const int gc = col0 + n8 * 8 + (e & 1);
                    const int r = row0 + mb * 16 + (e >> 1) * 8;
                    float val = acc[mb][n8][e] + bias[gc];
                    const int c2 = gc - 5120;
                    const int h = c2 / 80;
                    const int d = c2 - h * 80;
                    const int bb = r >> 10, key = r & 1023;
                    const size_t o = (size_t)(bb * 32 + h) * 81920 +
                                     (size_t)d * 1024 + key;
                    __half hh = __float2half(val);
                    Vh[o] = hh;
                    Vl[o] = __float2half(val - __half2float(hh));
                }
            }
        }
    }
}

// ---------------------------------------------------------------------------
// Generic mma.sync bf16x3 GEMM (proven): C(2048,N) = A @ B^T + bias
// ---------------------------------------------------------------------------
__global__ __launch_bounds__(512, 1) void gemm_bf16x3(
    const __nv_bfloat16* __restrict__ Ah, const __nv_bfloat16* __restrict__ Al,
    const __nv_bfloat16* __restrict__ Bh, const __nv_bfloat16* __restrict__ Bl,
    const float* __restrict__ bias, float* __restrict__ C, int N) {
    extern __shared__ __align__(1024) char dsm[];
    const uint32_t base = smem_u32(dsm);

    const int tid = threadIdx.x;
    const int wid = tid >> 5, lane = tid & 31;
    const int mw = wid & 3;
    const int nw = wid >> 2;
    const int mt = blockIdx.y, nt = blockIdx.x;
    const int K = 2560;

    const int trow = tid >> 3;
    const int tkg = tid & 7;

    float acc[2][4][4];
#pragma unroll
    for (int a = 0; a < 2; a++)
#pragma unroll
        for (int b = 0; b < 4; b++)
#pragma unroll
            for (int c = 0; c < 4; c++) acc[a][b][c] = 0.0f;

    auto load_chunk = [&](int c, int st) {
        const int k0 = c * 64;
        const uint32_t s0 = base + st * 65536;
#pragma unroll
        for (int j = 0; j < 2; j++) {
            const int row = j * 64 + trow;
            const uint32_t so = SWZ(row * 128 + tkg * 16);
            CP16(s0 + so, Ah + (size_t)(mt * 128 + row) * K + k0 + tkg * 8);
            CP16(s0 + 16384 + so, Al + (size_t)(mt * 128 + row) * K + k0 + tkg * 8);
            CP16(s0 + 32768 + so, Bh + (size_t)(nt * 128 + row) * K + k0 + tkg * 8);
            CP16(s0 + 49152 + so, Bl + (size_t)(nt * 128 + row) * K + k0 + tkg * 8);
        }
        asm volatile("cp.async.commit_group;");
    };

    const int lr = lane & 15;
    const int lc = (lane >> 4) * 16;

    load_chunk(0, 0);
    load_chunk(1, 1);

    int st = 0;
    for (int c = 0; c < 40; c++) {
        if (c < 39) {
            asm volatile("cp.async.wait_group 1;");
        } else {
            asm volatile("cp.async.wait_group 0;");
        }
        __syncthreads();
        if (c + 2 < 40) {
            int st2 = st + 2;
            if (st2 >= 3) st2 -= 3;
            load_chunk(c + 2, st2);
        }

        const uint32_t sA = base + st * 65536;
#pragma unroll
        for (int ks = 0; ks < 4; ks++) {
            uint32_t ah[2][4], al[2][4];
#pragma unroll
            for (int mb = 0; mb < 2; mb++) {
                const uint32_t ro = (mw * 32 + mb * 16 + lr) * 128 + ks * 32 + lc;
                LDSM4(ah[mb], sA + SWZ(ro));
                LDSM4(al[mb], sA + 16384 + SWZ(ro));
            }
            uint32_t bh2[2][4], bl2[2][4];
#pragma unroll
            for (int nb = 0; nb < 2; nb++) {
                const uint32_t ro = (nw * 32 + nb * 16 + lr) * 128 + ks * 32 + lc;
                LDSM4(bh2[nb], sA + 32768 + SWZ(ro));
                LDSM4(bl2[nb], sA + 49152 + SWZ(ro));
            }
#pragma unroll
            for (int mb = 0; mb < 2; mb++)
#pragma unroll
                for (int nb = 0; nb < 2; nb++) {
                    MMA_BF16(acc[mb][nb * 2],     ah[mb], bh2[nb][0], bh2[nb][2]);
                    MMA_BF16(acc[mb][nb * 2 + 1], ah[mb], bh2[nb][1], bh2[nb][3]);
                }
#pragma unroll
            for (int mb = 0; mb < 2; mb++)
#pragma unroll
                for (int nb = 0; nb < 2; nb++) {
                    MMA_BF16(acc[mb][nb * 2],     ah[mb], bl2[nb][0], bl2[nb][2]);
                    MMA_BF16(acc[mb][nb * 2 + 1], ah[mb], bl2[nb][1], bl2[nb][3]);
                }
#pragma unroll
            for (int mb = 0; mb < 2; mb++)
#pragma unroll
                for (int nb = 0; nb < 2; nb++) {
                    MMA_BF16(acc[mb][nb * 2],     al[mb], bh2[nb][0], bh2[nb][2]);
                    MMA_BF16(acc[mb][nb * 2 + 1], al[mb], bh2[nb][1], bh2[nb][3]);
                }
        }
        st++;
        if (st >= 3) st -= 3;
    }

    const int row0 = mt * 128 + mw * 32 + (lane >> 2);
    const int col0 = nt * 128 + nw * 32 + 2 * (lane & 3);
#pragma unroll
    for (int mb = 0; mb < 2; mb++) {
#pragma unroll
        for (int n8 = 0; n8 < 4; n8++) {
            const int gc = col0 + n8 * 8;
            const float b0 = bias[gc], b1 = bias[gc + 1];
            const int r = row0 + mb * 16;
            float2 o0 = make_float2(acc[mb][n8][0] + b0, acc[mb][n8][1] + b1);
            float2 o1 = make_float2(acc[mb][n8][2] + b0, acc[mb][n8][3] + b1);
            *(float2*)&C[(size_t)r * N + gc] = o0;
            *(float2*)&C[(size_t)(r + 8) * N + gc] = o1;
        }
    }
}

// ---------------------------------------------------------------------------
// attn_mma v5: scores fp32 in registers; P fp16 packed post-softmax.
// smem: QH [0,11264) | QL [11264,22528) | K 2 stages [22528,112640) -> 2 CTAs/SM.
// Phase3: V 2 stages overlay [0,87040); RED overlay [0,43008).
// ---------------------------------------------------------------------------
#define AT_QH 0u
#define AT_QL 11264u
#define AT_K  22528u
#define AT_KSTG 45056u
#define AT_VSTG 43520u
#define AT_SMEM 112640

__global__ __launch_bounds__(256, 2) void attn_mma(
    const float* __restrict__ qsrc,
    const __nv_bfloat16* __restrict__ Kh, const __nv_bfloat16* __restrict__ Kl,
    const __half* __restrict__ Vh, const __half* __restrict__ Vl,
    const float* __restrict__ gm, const float* __restrict__ gp,
    const float* __restrict__ ga, const float* __restrict__ qp,
    const float* __restrict__ isr,
    __nv_bfloat16* __restrict__ out_hi, __nv_bfloat16* __restrict__ out_lo) {
    extern __shared__ __align__(128) char smc[];
    __shared__ float coeff[240];
    __shared__ float pbuf[128];
    __shared__ float rsum[16];
    char* sm = smc;
    const uint32_t base = smem_u32(smc);

    const int tid = threadIdx.x;
    const int wid = tid >> 5, lane = tid & 31;
    const int lr = lane & 15, lc = (lane >> 4) << 4;
    const int rr = lane >> 2, cc = (lane & 3) * 2;
    const int bh = blockIdx.y, b = bh >> 5, h = bh & 31;
    const int q0 = blockIdx.x * 16;

    const __nv_bfloat16* KhB = Kh + (size_t)bh * 90112;
    const __nv_bfloat16* KlB = Kl + (size_t)bh * 90112;
    auto load_k = [&](int kt, int stg) {
        const uint32_t sb = base + AT_K + (uint32_t)stg * AT_KSTG;
#pragma unroll
        for (int j = 0; j < 11; j++) {
            int idx = tid + j * 256;
            int m = idx >= 1408;
            int rem = m ? idx - 1408 : idx;
            int row = rem / 11, ch = rem - row * 11;
            const __nv_bfloat16* g =
                (m ? KlB : KhB) + (size_t)(kt * 128 + row) * 88 + ch * 8;
            CP16(sb + m * 22528u + row * 176 + ch * 16, g);
        }
        asm volatile("cp.async.commit_group;");
    };

    load_k(0, 0);

    if (tid < 240) {
        int g = tid / 80, d = tid - g * 80;
        float r0 = gm[g * 4 + 0] + gm[g * 4 + 1];
        float r1 = gm[g * 4 + 2] + gm[g * 4 + 3];
        float ph = gp[g * 80 + d];
        coeff[tid] = (cosf(ph) * r0 + sinf(ph) * r1) * ga[g * 80 + d];
    }
    __syncthreads();

    // build Qext (4 variants x 16 rows x 80 dims, scale folded in)
    const float scale = rsqrtf(80.0f);
    for (int idx = tid; idx < 1280; idx += 256) {
        int r = idx / 80, d = idx - r * 80;
        float v = qsrc[(size_t)(b * 1024 + q0 + r) * 2560 + h * 80 + d] * scale;
        float vv[4] = {v, v * coeff[d], v * coeff[80 + d], v * coeff[160 + d]};
#pragma unroll
        for (int g = 0; g < 4; g++) {
            uint32_t o = (g * 16 + r) * 176 + d * 2;
            __nv_bfloat16 hh = __float2bfloat16(vv[g]);
            *(__nv_bfloat16*)(sm + AT_QH + o) = hh;
            *(__nv_bfloat16*)(sm + AT_QL + o) =
                __float2bfloat16(vv[g] - __bfloat162float(hh));
        }
    }

    const float intf = isr[0] * (1.0f / 3.0f);
    float csf[64];     // fp32 scores: [kt*8 + n8*4 + j]

    // ---- Phase 1: scores; warp wid owns keys [kt*128 + wid*16, +16) ----
#pragma unroll
    for (int kt = 0; kt < 8; kt++) {
        const int stg = kt & 1;
        asm volatile("cp.async.wait_group 0;");
        __syncthreads();
        if (kt < 7) load_k(kt + 1, stg ^ 1);

        const uint32_t kbase = base + AT_K + (uint32_t)stg * AT_KSTG;
        float acc[4][2][4];
#pragma unroll
        for (int g = 0; g < 4; g++)
#pragma unroll
            for (int i = 0; i < 2; i++)
#pragma unroll
                for (int j = 0; j < 4; j++) acc[g][i][j] = 0.0f;

#pragma unroll
        for (int ks = 0; ks < 5; ks++) {
            uint32_t bH[4], bL[4];
            uint32_t rb = (wid * 16 + lr) * 176 + ks * 32 + lc;
            LDSM4(bH, kbase + rb);
            LDSM4(bL, kbase + 22528u + rb);
#pragma unroll
            for (int g = 0; g < 4; g++) {
                uint32_t aH[4], aL[4];
                uint32_t ro = (g * 16 + lr) * 176 + ks * 32 + lc;
                LDSM4(aH, base + AT_QH + ro);
                LDSM4(aL, base + AT_QL + ro);
                MMA_BF16(acc[g][0], aH, bH[0], bH[2]);
                MMA_BF16(acc[g][1], aH, bH[1], bH[3]);
                MMA_BF16(acc[g][0], aH, bL[0], bL[2]);
                MMA_BF16(acc[g][1], aH, bL[1], bL[3]);
                MMA_BF16(acc[g][0], aL, bH[0], bH[2]);
                MMA_BF16(acc[g][1], aL, bH[1], bH[3]);
            }
        }

        // combine interference in registers -> fp32 scores
#pragma unroll
        for (int n8 = 0; n8 < 2; n8++) {
#pragma unroll
            for (int j = 0; j < 4; j++) {
                float a0 = acc[1][n8][j], a1 = acc[2][n8][j], a2 = acc[3][n8][j];
                csf[kt * 8 + n8 * 4 + j] =
                    acc[0][n8][j] + (a0 * a1 + a0 * a2 + a1 * a2) * intf;
            }
        }
    }
    __syncthreads();   // all K/Q reads done before V overwrites the region

    // preload V stages (overlap with softmax)
    const __half* VhB = Vh + (size_t)bh * 81920;
    const __half* VlB = Vl + (size_t)bh * 81920;
    auto load_v = [&](int kt, int stg) {
#pragma unroll
        for (int j = 0; j < 10; j++) {
            int idx = tid + j * 256;
            int m = idx >= 1280;
            int rem = m ? idx - 1280 : idx;
            int dim = rem >> 4, ch = rem & 15;
            const __half* g =
                (m ? VlB : VhB) + (size_t)dim * 1024 + kt * 128 + ch * 8;
            CP16(base + stg * AT_VSTG + m * 21760 + dim * 272 + ch * 16, g);
        }
        asm volatile("cp.async.commit_group;");
    };
    load_v(0, 0);
    load_v(1, 1);

    // ---- Phase 2: softmax (fp32), then pack exp to fp16 fragments ----
    float m0 = -1e30f, m1 = -1e30f;
#pragma unroll
    for (int i = 0; i < 16; i++) {        // i = kt*2 + n8
        m0 = fmaxf(m0, fmaxf(csf[i * 4 + 0], csf[i * 4 + 1]));
        m1 = fmaxf(m1, fmaxf(csf[i * 4 + 2], csf[i * 4 + 3]));
    }
#pragma unroll
    for (int off = 1; off <= 2; off <<= 1) {
        m0 = fmaxf(m0, __shfl_xor_sync(0xffffffffu, m0, off));
        m1 = fmaxf(m1, __shfl_xor_sync(0xffffffffu, m1, off));
    }
    if ((lane & 3) == 0) {
        pbuf[wid * 16 + rr] = m0;
        pbuf[wid * 16 + rr + 8] = m1;
    }
    __syncthreads();
    float M0 = -1e30f, M1 = -1e30f;
#pragma unroll
    for (int w = 0; w < 8; w++) {
        M0 = fmaxf(M0, pbuf[w * 16 + rr]);
        M1 = fmaxf(M1, pbuf[w * 16 + rr + 8]);
    }
    __syncthreads();

    uint32_t ps[32];   // fp16x2 P fragments: [kt*4 + n8*2 + fr]
    float s0 = 0.0f, s1 = 0.0f;
#pragma unroll
    for (int i = 0; i < 16; i++) {
        float e0 = __expf(csf[i * 4 + 0] - M0);
        float e1 = __expf(csf[i * 4 + 1] - M0);
        float e2 = __expf(csf[i * 4 + 2] - M1);
        float e3 = __expf(csf[i * 4 + 3] - M1);
        s0 += e0 + e1;
        s1 += e2 + e3;
        ps[i * 2 + 0] = pack_h2(e0, e1);   // row rr
        ps[i * 2 + 1] = pack_h2(e2, e3);   // row rr+8
    }
#pragma unroll
    for (int off = 1; off <= 2; off <<= 1) {
        s0 += __shfl_xor_sync(0xffffffffu, s0, off);
        s1 += __shfl_xor_sync(0xffffffffu, s1, off);
    }
    if ((lane & 3) == 0) {
        pbuf[wid * 16 + rr] = s0;
        pbuf[wid * 16 + rr + 8] = s1;
    }
    __syncthreads();
    if (wid == 0 && lane < 16) {
        float S = 0.0f;
#pragma unroll
        for (int w = 0; w < 8; w++) S += pbuf[w * 16 + lane];
        rsum[lane] = S;
    }

    // ---- Phase 3: P @ (Vh + Vl), P fragments straight from ps ----
    float acc3[10][4];
#pragma unroll
    for (int i = 0; i < 10; i++)
#pragma unroll
        for (int j = 0; j < 4; j++) acc3[i][j] = 0.0f;

#pragma unroll
    for (int kt = 0; kt < 8; kt++) {
        if (kt < 7) {
            asm volatile("cp.async.wait_group 1;");
        } else {
            asm volatile("cp.async.wait_group 0;");
        }
        __syncthreads();

        const uint32_t vb = base + (uint32_t)(kt & 1) * AT_VSTG;
        uint32_t pA[4] = {ps[kt * 4 + 0], ps[kt * 4 + 1],
                          ps[kt * 4 + 2], ps[kt * 4 + 3]};
#pragma unroll
        for (int nd = 0; nd < 5; nd++) {
            uint32_t vh[4], vl[4];
            uint32_t rb = (nd * 16 + lr) * 272 + wid * 32 + lc;
            LDSM4(vh, vb + rb);
            LDSM4(vl, vb + 21760u + rb);
            MMA_F16(acc3[nd * 2],     pA, vh[0], vh[2]);
            MMA_F16(acc3[nd * 2 + 1], pA, vh[1], vh[3]);
            MMA_F16(acc3[nd * 2],     pA, vl[0], vl[2]);
            MMA_F16(acc3[nd * 2 + 1], pA, vl[1], vl[3]);
        }
        __syncthreads();
        if (kt < 6) load_v(kt + 2, kt & 1);
    }

    // cross-warp reduce (RED at smem offset 0; V buffers dead)
    float* red = (float*)sm;
    float* redw = red + wid * 1344;
#pragma unroll
    for (int j = 0; j < 10; j++) {
        int d = (j >> 1) * 16 + (j & 1) * 8 + cc;
        redw[rr * 84 + d]           = acc3[j][0];
        redw[rr * 84 + d + 1]       = acc3[j][1];
        redw[(rr + 8) * 84 + d]     = acc3[j][2];
        redw[(rr + 8) * 84 + d + 1] = acc3[j][3];
    }
    __syncthreads();

    const float cph = cosf(qp[h]);
    for (int idx = tid; idx < 1280; idx += 256) {
        int r = idx / 80, d = idx - r * 80;
        float s = 0.0f;
#pragma unroll
        for (int w = 0; w < 8; w++) s += red[w * 1344 + r * 84 + d];
        float o = s * cph / rsum[r];
        size_t go = (size_t)(b * 1024 + q0 + r) * 2560 + h * 80 + d;
        __nv_bfloat16 hh = __float2bfloat16(o);
        out_hi[go] = hh;
        out_lo[go] = __float2bfloat16(o - __bfloat162float(hh));
    }
}

// ---------------------------------------------------------------------------
extern "C" void kernel_launch(void* const* d_in, const int* in_sizes, int n_in,
                              void* d_out, int out_size) {
    const float* hidden = (const float*)d_in[0];
    const float* Wqkv   = (const float*)d_in[1];
    const float* bqkv   = (const float*)d_in[2];
    const float* Wproj  = (const float*)d_in[3];
    const float* bproj  = (const float*)d_in[4];
    const float* gm     = (const float*)d_in[5];
    const float* gp     = (const float*)d_in[6];
    const float* ga     = (const float*)d_in[7];
    const float* qp     = (const float*)d_in[8];
    const float* isr    = (const float*)d_in[9];
    float* out = (float*)d_out;

    void *p_q, *p_hh, *p_hl, *p_wqh, *p_wql, *p_wph, *p_wpl, *p_ah, *p_al;
    void *p_kh, *p_kl, *p_vh, *p_vl;
    cudaGetSymbolAddress(&p_q, g_q);
    cudaGetSymbolAddress(&p_hh, g_hid_hi);
    cudaGetSymbolAddress(&p_hl, g_hid_lo);
    cudaGetSymbolAddress(&p_wqh, g_wqkvT_hi);
    cudaGetSymbolAddress(&p_wql, g_wqkvT_lo);
    cudaGetSymbolAddress(&p_wph, g_wprojT_hi);
    cudaGetSymbolAddress(&p_wpl, g_wprojT_lo);
    cudaGetSymbolAddress(&p_ah, g_attn_hi);
    cudaGetSymbolAddress(&p_al, g_attn_lo);
    cudaGetSymbolAddress(&p_kh, g_Khi);
    cudaGetSymbolAddress(&p_kl, g_Klo);
    cudaGetSymbolAddress(&p_vh, g_Vthi);
    cudaGetSymbolAddress(&p_vl, g_Vtlo);

    const int GEMM_SMEM = 3 * 65536;
    cudaFuncSetAttribute(gemm_qkv,
                         cudaFuncAttributeMaxDynamicSharedMemorySize, GEMM_SMEM);
    cudaFuncSetAttribute(gemm_bf16x3,
                         cudaFuncAttributeMaxDynamicSharedMemorySize, GEMM_SMEM);
    cudaFuncSetAttribute(attn_mma,
                         cudaFuncAttributeMaxDynamicSharedMemorySize, AT_SMEM);

    // 1) input conversions
    conv_hilo<<<5120, 256>>>(hidden, (__nv_bfloat16*)p_hh, (__nv_bfloat16*)p_hl,
                             2048 * 2560 / 4);
    transpose_conv2<<<dim3(240, 80, 2), dim3(32, 8)>>>(
        Wqkv, Wproj,
        (__nv_bfloat16*)p_wqh, (__nv_bfloat16*)p_wql,
        (__nv_bfloat16*)p_wph, (__nv_bfloat16*)p_wpl);

    // 2) fused qkv GEMM: q fp32, k bf16 hi/lo, v fp16 hi/lo (transposed)
    gemm_qkv<<<dim3(60, 16), 512, GEMM_SMEM>>>(
        (const __nv_bfloat16*)p_hh, (const __nv_bfloat16*)p_hl,
        (const __nv_bfloat16*)p_wqh, (const __nv_bfloat16*)p_wql,
        bqkv, (float*)p_q,
        (__nv_bfloat16*)p_kh, (__nv_bfloat16*)p_kl,
        (__half*)p_vh, (__half*)p_vl);

    // 3) register-resident tensor-core quantum attention
    attn_mma<<<dim3(64, 64), 256, AT_SMEM>>>(
        (const float*)p_q,
        (const __nv_bfloat16*)p_kh, (const __nv_bfloat16*)p_kl,
        (const __half*)p_vh, (const __half*)p_vl,
        gm, gp, ga, qp, isr,
        (__nv_bfloat16*)p_ah, (__nv_bfloat16*)p_al);

    // 4) out = attn @ Wproj + bproj
    gemm_bf16x3<<<dim3(20, 16), 512, GEMM_SMEM>>>(
        (const __nv_bfloat16*)p_ah, (const __nv_bfloat16*)p_al,
        (const __nv_bfloat16*)p_wph, (const __nv_bfloat16*)p_wpl,
        bproj, out, 2560);
}

// round 12
// speedup vs baseline: 1.7476x; 1.0326x over previous
#include <cuda_runtime.h>
#include <cuda_bf16.h>
#include <cuda_fp16.h>
#include <stdint.h>
#include <math.h>

// Problem constants: B=2, S=1024, E=2560, H=32, D=80, 3E=7680, BS=2048, K=2560

// ---------------- device scratch ----------------
__device__ float g_q[2048ull * 2560];                  // q part, fp32 compact
__device__ __nv_bfloat16 g_hid_hi[2048ull * 2560];
__device__ __nv_bfloat16 g_hid_lo[2048ull * 2560];
__device__ __nv_bfloat16 g_wqkvT_hi[7680ull * 2560];   // (N,K)
__device__ __nv_bfloat16 g_wqkvT_lo[7680ull * 2560];
__device__ __nv_bfloat16 g_wprojT_hi[2560ull * 2560];
__device__ __nv_bfloat16 g_wprojT_lo[2560ull * 2560];
__device__ __nv_bfloat16 g_attn_hi[2048ull * 2560];
__device__ __nv_bfloat16 g_attn_lo[2048ull * 2560];
__device__ __nv_bfloat16 g_Khi[64ull * 1024 * 88];     // [bh][key][88]
__device__ __nv_bfloat16 g_Klo[64ull * 1024 * 88];
__device__ __half g_Vthi[64ull * 80 * 1024];           // [bh][dim][1024] fp16

__device__ __forceinline__ uint32_t smem_u32(const void* p) {
    uint32_t a;
    asm("{ .reg .u64 t; cvta.to.shared.u64 t, %1; cvt.u32.u64 %0, t; }"
        : "=r"(a) : "l"(p));
    return a;
}

#define SWZ(o) ((uint32_t)(o) ^ ((((uint32_t)(o)) >> 3) & 0x70u))

#define CP16(s, g) \
    asm volatile("cp.async.cg.shared.global [%0], [%1], 16;" :: "r"(s), "l"(g))

#define LDSM4(r, addr) \
    asm volatile("ldmatrix.sync.aligned.m8n8.x4.shared.b16 {%0,%1,%2,%3}, [%4];" \
                 : "=r"((r)[0]), "=r"((r)[1]), "=r"((r)[2]), "=r"((r)[3]) \
                 : "r"(addr))

#define MMA_BF16(acc, A, b0, b1) \
    asm volatile("mma.sync.aligned.m16n8k16.row.col.f32.bf16.bf16.f32 " \
                 "{%0,%1,%2,%3}, {%4,%5,%6,%7}, {%8,%9}, {%0,%1,%2,%3};" \
                 : "+f"((acc)[0]), "+f"((acc)[1]), "+f"((acc)[2]), "+f"((acc)[3]) \
                 : "r"((A)[0]), "r"((A)[1]), "r"((A)[2]), "r"((A)[3]), \
                   "r"(b0), "r"(b1))

#define MMA_F16(acc, A, b0, b1) \
    asm volatile("mma.sync.aligned.m16n8k16.row.col.f32.f16.f16.f32 " \
                 "{%0,%1,%2,%3}, {%4,%5,%6,%7}, {%8,%9}, {%0,%1,%2,%3};" \
                 : "+f"((acc)[0]), "+f"((acc)[1]), "+f"((acc)[2]), "+f"((acc)[3]) \
                 : "r"((A)[0]), "r"((A)[1]), "r"((A)[2]), "r"((A)[3]), \
                   "r"(b0), "r"(b1))

__device__ __forceinline__ uint32_t pack_h2(float a, float b) {
    __half2 h = __floats2half2_rn(a, b);
    return *(uint32_t*)&h;
}

// ---------------------------------------------------------------------------
// Conversion: fp32 -> bf16 hi/lo
// ---------------------------------------------------------------------------
__global__ void conv_hilo(const float* __restrict__ X,
                          __nv_bfloat16* __restrict__ Hh,
                          __nv_bfloat16* __restrict__ Ll, int n4) {
    int i = blockIdx.x * blockDim.x + threadIdx.x;
    if (i >= n4) return;
    float4 v = ((const float4*)X)[i];
    __nv_bfloat16 h0 = __float2bfloat16(v.x), h1 = __float2bfloat16(v.y);
    __nv_bfloat16 h2 = __float2bfloat16(v.z), h3 = __float2bfloat16(v.w);
    __nv_bfloat162 a, b;
    a.x = h0; a.y = h1; b.x = h2; b.y = h3;
    ((__nv_bfloat162*)Hh)[i * 2] = a;
    ((__nv_bfloat162*)Hh)[i * 2 + 1] = b;
    __nv_bfloat162 c, d;
    c.x = __float2bfloat16(v.x - __bfloat162float(h0));
    c.y = __float2bfloat16(v.y - __bfloat162float(h1));
    d.x = __float2bfloat16(v.z - __bfloat162float(h2));
    d.y = __float2bfloat16(v.w - __bfloat162float(h3));
    ((__nv_bfloat162*)Ll)[i * 2] = c;
    ((__nv_bfloat162*)Ll)[i * 2 + 1] = d;
}

// ---------------------------------------------------------------------------
// Transpose + convert both weights in one launch (z=0: Wqkv, z=1: Wproj)
// ---------------------------------------------------------------------------
__global__ void transpose_conv2(const float* __restrict__ Wq,
                                const float* __restrict__ Wp,
                                __nv_bfloat16* __restrict__ Tqh,
                                __nv_bfloat16* __restrict__ Tql,
                                __nv_bfloat16* __restrict__ Tph,
                                __nv_bfloat16* __restrict__ Tpl) {
    __shared__ float t[32][33];
    const int z = blockIdx.z;
    if (z == 1 && blockIdx.x >= 80) return;
    const float* W = z ? Wp : Wq;
    __nv_bfloat16* Th = z ? Tph : Tqh;
    __nv_bfloat16* Tl = z ? Tpl : Tql;
    const int N = z ? 2560 : 7680;
    const int K = 2560;
    int n0 = blockIdx.x * 32, k0 = blockIdx.y * 32;
    int tx = threadIdx.x, ty = threadIdx.y;
#pragma unroll
    for (int j = 0; j < 4; j++)
        t[ty + j * 8][tx] = W[(size_t)(k0 + ty + j * 8) * N + n0 + tx];
    __syncthreads();
#pragma unroll
    for (int j = 0; j < 4; j++) {
        float v = t[tx][ty + j * 8];
        __nv_bfloat16 h = __float2bfloat16(v);
        size_t o = (size_t)(n0 + ty + j * 8) * K + k0 + tx;
        Th[o] = h;
        Tl[o] = __float2bfloat16(v - __bfloat162float(h));
    }
}

// ---------------------------------------------------------------------------
// GEMM1 (fused): CTA 128x64, 256 threads (8 warps, 32x32 warp tiles),
// 3-stage cp.async (48KB/stage). Epilogue routes q/k/v.
// grid (120, 16): nt<40 -> q fp32; nt<80 -> K bf16 hi/lo; else V fp16 (hi only).
// ---------------------------------------------------------------------------
__global__ __launch_bounds__(256, 1) void gemm_qkv(
    const __nv_bfloat16* __restrict__ Ah, const __nv_bfloat16* __restrict__ Al,
    const __nv_bfloat16* __restrict__ Bh, const __nv_bfloat16* __restrict__ Bl,
    const float* __restrict__ bias, float* __restrict__ Qout,
    __nv_bfloat16* __restrict__ Kh, __nv_bfloat16* __restrict__ Kl,
    __half* __restrict__ Vh) {
    extern __shared__ __align__(1024) char dsm[];
    const uint32_t base = smem_u32(dsm);

    const int tid = threadIdx.x;
    const int wid = tid >> 5, lane = tid & 31;
    const int mw = wid & 3;       // 4 x 32 rows
    const int nw = wid >> 2;      // 2 x 32 cols
    const int mt = blockIdx.y, nt = blockIdx.x;
    const int K = 2560;

    const int trow = tid >> 3;    // 0..31
    const int tkg = tid & 7;

    float acc[2][4][4];
#pragma unroll
    for (int a = 0; a < 2; a++)
#pragma unroll
        for (int b = 0; b < 4; b++)
#pragma unroll
            for (int c = 0; c < 4; c++) acc[a][b][c] = 0.0f;

    auto load_chunk = [&](int c, int st) {
        const int k0 = c * 64;
        const uint32_t s0 = base + st * 49152;
#pragma unroll
        for (int j = 0; j < 4; j++) {
            const int row = j * 32 + trow;
            const uint32_t so = SWZ(row * 128 + tkg * 16);
            CP16(s0 + so, Ah + (size_t)(mt * 128 + row) * K + k0 + tkg * 8);
            CP16(s0 + 16384 + so, Al + (size_t)(mt * 128 + row) * K + k0 + tkg * 8);
        }
#pragma unroll
        for (int j = 0; j < 2; j++) {
            const int row = j * 32 + trow;
            const uint32_t so = SWZ(row * 128 + tkg * 16);
            CP16(s0 + 32768 + so, Bh + (size_t)(nt * 64 + row) * K + k0 + tkg * 8);
            CP16(s0 + 40960 + so, Bl + (size_t)(nt * 64 + row) * K + k0 + tkg * 8);
        }
        asm volatile("cp.async.commit_group;");
    };

    const int lr = lane & 15;
    const int lc = (lane >> 4) * 16;

    load_chunk(0, 0);
    load_chunk(1, 1);

    int st = 0;
    for (int c = 0; c < 40; c++) {
        if (c < 39) {
            asm volatile("cp.async.wait_group 1;");
        } else {
            asm volatile("cp.async.wait_group 0;");
        }
        __syncthreads();
        if (c + 2 < 40) {
            int st2 = st + 2;
            if (st2 >= 3) st2 -= 3;
            load_chunk(c + 2, st2);
        }

        const uint32_t sA = base + st * 49152;
#pragma unroll
        for (int ks = 0; ks < 4; ks++) {
            uint32_t ah[2][4], al[2][4];
#pragma unroll
            for (int mb = 0; mb < 2; mb++) {
                const uint32_t ro = (mw * 32 + mb * 16 + lr) * 128 + ks * 32 + lc;
                LDSM4(ah[mb], sA + SWZ(ro));
                LDSM4(al[mb], sA + 16384 + SWZ(ro));
            }
            uint32_t bh2[2][4], bl2[2][4];
#pragma unroll
            for (int nb = 0; nb < 2; nb++) {
                const uint32_t ro = (nw * 32 + nb * 16 + lr) * 128 + ks * 32 + lc;
                LDSM4(bh2[nb], sA + 32768 + SWZ(ro));
                LDSM4(bl2[nb], sA + 40960 + SWZ(ro));
            }
#pragma unroll
            for (int mb = 0; mb < 2; mb++)
#pragma unroll
                for (int nb = 0; nb < 2; nb++) {
                    MMA_BF16(acc[mb][nb * 2],     ah[mb], bh2[nb][0], bh2[nb][2]);
                    MMA_BF16(acc[mb][nb * 2 + 1], ah[mb], bh2[nb][1], bh2[nb][3]);
                }
#pragma unroll
            for (int mb = 0; mb < 2; mb++)
#pragma unroll
                for (int nb = 0; nb < 2; nb++) {
                    MMA_BF16(acc[mb][nb * 2],     ah[mb], bl2[nb][0], bl2[nb][2]);
                    MMA_BF16(acc[mb][nb * 2 + 1], ah[mb], bl2[nb][1], bl2[nb][3]);
                }
#pragma unroll
            for (int mb = 0; mb < 2; mb++)
#pragma unroll
                for (int nb = 0; nb < 2; nb++) {
                    MMA_BF16(acc[mb][nb * 2],     al[mb], bh2[nb][0], bh2[nb][2]);
                    MMA_BF16(acc[mb][nb * 2 + 1], al[mb], bh2[nb][1], bh2[nb][3]);
                }
        }
        st++;
        if (st >= 3) st -= 3;
    }

    const int row0 = mt * 128 + mw * 32 + (lane >> 2);
    const int col0 = nt * 64 + nw * 32 + 2 * (lane & 3);

    if (nt < 40) {
#pragma unroll
        for (int mb = 0; mb < 2; mb++) {
#pragma unroll
            for (int n8 = 0; n8 < 4; n8++) {
                const int gc = col0 + n8 * 8;
                const float b0 = bias[gc], b1 = bias[gc + 1];
                const int r = row0 + mb * 16;
                float2 o0 = make_float2(acc[mb][n8][0] + b0, acc[mb][n8][1] + b1);
                float2 o1 = make_float2(acc[mb][n8][2] + b0, acc[mb][n8][3] + b1);
                *(float2*)&Qout[(size_t)r * 2560 + gc] = o0;
                *(float2*)&Qout[(size_t)(r + 8) * 2560 + gc] = o1;
            }
        }
    } else if (nt < 80) {
        // K -> bf16 hi/lo [bh][key][88]
#pragma unroll
        for (int mb = 0; mb < 2; mb++) {
#pragma unroll
            for (int n8 = 0; n8 < 4; n8++) {
#pragma unroll
                for (int e = 0; e < 4; e++) {
                    const int gc = col0 + n8 * 8 + (e & 1);
                    const int r = row0 + mb * 16 + (e >> 1) * 8;
                    float val = acc[mb][n8][e] + bias[gc];
                    const int c2 = gc - 2560;
                    const int h = c2 / 80;
                    const int d = c2 - h * 80;
                    const int bb = r >> 10, key = r & 1023;
                    const size_t o = (size_t)(bb * 32 + h) * 90112 +
                                     (size_t)key * 88 + d;
                    __nv_bfloat16 hh = __float2bfloat16(val);
                    Kh[o] = hh;
                    Kl[o] = __float2bfloat16(val - __bfloat162float(hh));
                }
            }
        }
    } else {
        // V -> fp16 transposed [bh][dim][1024]
#pragma unroll
        for (int mb = 0; mb < 2; mb++) {
#pragma unroll
            for (int n8 = 0; n8 < 4; n8++) {
#pragma unroll
                for (int e = 0; e < 4; e++) {
                    const int gc = col0 + n8 * 8 + (e & 1);
                    const int r = row0 + mb * 16 + (e >> 1) * 8;
                    float val = acc[mb][n8][e] + bias[gc];
                    const int c2 = gc - 5120;
                    const int h = c2 / 80;
                    const int d = c2 - h * 80;
                    const int bb = r >> 10, key = r & 1023;
                    const size_t o = (size_t)(bb * 32 + h) * 81920 +
                                     (size_t)d * 1024 + key;
                    Vh[o] = __float2half(val);
                }
            }
        }
    }
}

// ---------------------------------------------------------------------------
// Generic mma.sync bf16x3 GEMM: CTA 128x64, 256 threads, 3-stage cp.async.
// C(2048,N) = A @ B^T + bias. grid (N/64, 16).
// ---------------------------------------------------------------------------
__global__ __launch_bounds__(256, 1) void gemm_bf16x3(
    const __nv_bfloat16* __restrict__ Ah, const __nv_bfloat16* __restrict__ Al,
    const __nv_bfloat16* __restrict__ Bh, const __nv_bfloat16* __restrict__ Bl,
    const float* __restrict__ bias, float* __restrict__ C, int N) {
    extern __shared__ __align__(1024) char dsm[];
    const uint32_t base = smem_u32(dsm);

    const int tid = threadIdx.x;
    const int wid = tid >> 5, lane = tid & 31;
    const int mw = wid & 3;
    const int nw = wid >> 2;
    const int mt = blockIdx.y, nt = blockIdx.x;
    const int K = 2560;

    const int trow = tid >> 3;
    const int tkg = tid & 7;

    float acc[2][4][4];
#pragma unroll
    for (int a = 0; a < 2; a++)
#pragma unroll
        for (int b = 0; b < 4; b++)
#pragma unroll
            for (int c = 0; c < 4; c++) acc[a][b][c] = 0.0f;

    auto load_chunk = [&](int c, int st) {
        const int k0 = c * 64;
        const uint32_t s0 = base + st * 49152;
#pragma unroll
        for (int j = 0; j < 4; j++) {
            const int row = j * 32 + trow;
            const uint32_t so = SWZ(row * 128 + tkg * 16);
            CP16(s0 + so, Ah + (size_t)(mt * 128 + row) * K + k0 + tkg * 8);
            CP16(s0 + 16384 + so, Al + (size_t)(mt * 128 + row) * K + k0 + tkg * 8);
        }
#pragma unroll
        for (int j = 0; j < 2; j++) {
            const int row = j * 32 + trow;
            const uint32_t so = SWZ(row * 128 + tkg * 16);
            CP16(s0 + 32768 + so, Bh + (size_t)(nt * 64 + row) * K + k0 + tkg * 8);
            CP16(s0 + 40960 + so, Bl + (size_t)(nt * 64 + row) * K + k0 + tkg * 8);
        }
        asm volatile("cp.async.commit_group;");
    };

    const int lr = lane & 15;
    const int lc = (lane >> 4) * 16;

    load_chunk(0, 0);
    load_chunk(1, 1);

    int st = 0;
    for (int c = 0; c < 40; c++) {
        if (c < 39) {
            asm volatile("cp.async.wait_group 1;");
        } else {
            asm volatile("cp.async.wait_group 0;");
        }
        __syncthreads();
        if (c + 2 < 40) {
            int st2 = st + 2;
            if (st2 >= 3) st2 -= 3;
            load_chunk(c + 2, st2);
        }

        const uint32_t sA = base + st * 49152;
#pragma unroll
        for (int ks = 0; ks < 4; ks++) {
            uint32_t ah[2][4], al[2][4];
#pragma unroll
            for (int mb = 0; mb < 2; mb++) {
                const uint32_t ro = (mw * 32 + mb * 16 + lr) * 128 + ks * 32 + lc;
                LDSM4(ah[mb], sA + SWZ(ro));
                LDSM4(al[mb], sA + 16384 + SWZ(ro));
            }
            uint32_t bh2[2][4], bl2[2][4];
#pragma unroll
            for (int nb = 0; nb < 2; nb++) {
                const uint32_t ro = (nw * 32 + nb * 16 + lr) * 128 + ks * 32 + lc;
                LDSM4(bh2[nb], sA + 32768 + SWZ(ro));
                LDSM4(bl2[nb], sA + 40960 + SWZ(ro));
            }
#pragma unroll
            for (int mb = 0; mb < 2; mb++)
#pragma unroll
                for (int nb = 0; nb < 2; nb++) {
                    MMA_BF16(acc[mb][nb * 2],     ah[mb], bh2[nb][0], bh2[nb][2]);
                    MMA_BF16(acc[mb][nb * 2 + 1], ah[mb], bh2[nb][1], bh2[nb][3]);
                }
#pragma unroll
            for (int mb = 0; mb < 2; mb++)
#pragma unroll
                for (int nb = 0; nb < 2; nb++) {
                    MMA_BF16(acc[mb][nb * 2],     ah[mb], bl2[nb][0], bl2[nb][2]);
                    MMA_BF16(acc[mb][nb * 2 + 1], ah[mb], bl2[nb][1], bl2[nb][3]);
                }
#pragma unroll
            for (int mb = 0; mb < 2; mb++)
#pragma unroll
                for (int nb = 0; nb < 2; nb++) {
                    MMA_BF16(acc[mb][nb * 2],     al[mb], bh2[nb][0], bh2[nb][2]);
                    MMA_BF16(acc[mb][nb * 2 + 1], al[mb], bh2[nb][1], bh2[nb][3]);
                }
        }
        st++;
        if (st >= 3) st -= 3;
    }

    const int row0 = mt * 128 + mw * 32 + (lane >> 2);
    const int col0 = nt * 64 + nw * 32 + 2 * (lane & 3);
#pragma unroll
    for (int mb = 0; mb < 2; mb++) {
#pragma unroll
        for (int n8 = 0; n8 < 4; n8++) {
            const int gc = col0 + n8 * 8;
            const float b0 = bias[gc], b1 = bias[gc + 1];
            const int r = row0 + mb * 16;
            float2 o0 = make_float2(acc[mb][n8][0] + b0, acc[mb][n8][1] + b1);
            float2 o1 = make_float2(acc[mb][n8][2] + b0, acc[mb][n8][3] + b1);
            *(float2*)&C[(size_t)r * N + gc] = o0;
            *(float2*)&C[(size_t)(r + 8) * N + gc] = o1;
        }
    }
}

// ---------------------------------------------------------------------------
// attn_mma v6: scores fp32 in registers; P fp16; V fp16 single-term.
// smem: QH [0,11264) | QL [11264,22528) | K 2 stages [22528,112640) -> 2 CTAs/SM.
// Phase3: V 2 stages overlay [0,43520); RED overlay [0,43008).
// ---------------------------------------------------------------------------
#define AT_QH 0u
#define AT_QL 11264u
#define AT_K  22528u
#define AT_KSTG 45056u
#define AT_VSTG 21760u
#define AT_SMEM 112640

__global__ __launch_bounds__(256, 2) void attn_mma(
    const float* __restrict__ qsrc,
    const __nv_bfloat16* __restrict__ Kh, const __nv_bfloat16* __restrict__ Kl,
    const __half* __restrict__ Vh,
    const float* __restrict__ gm, const float* __restrict__ gp,
    const float* __restrict__ ga, const float* __restrict__ qp,
    const float* __restrict__ isr,
    __nv_bfloat16* __restrict__ out_hi, __nv_bfloat16* __restrict__ out_lo) {
    extern __shared__ __align__(128) char smc[];
    __shared__ float coeff[240];
    __shared__ float pbuf[128];
    __shared__ float rsum[16];
    char* sm = smc;
    const uint32_t base = smem_u32(smc);

    const int tid = threadIdx.x;
    const int wid = tid >> 5, lane = tid & 31;
    const int lr = lane & 15, lc = (lane >> 4) << 4;
    const int rr = lane >> 2, cc = (lane & 3) * 2;
    const int bh = blockIdx.y, b = bh >> 5, h = bh & 31;
    const int q0 = blockIdx.x * 16;

    const __nv_bfloat16* KhB = Kh + (size_t)bh * 90112;
    const __nv_bfloat16* KlB = Kl + (size_t)bh * 90112;
    auto load_k = [&](int kt, int stg) {
        const uint32_t sb = base + AT_K + (uint32_t)stg * AT_KSTG;
#pragma unroll
        for (int j = 0; j < 11; j++) {
            int idx = tid + j * 256;
            int m = idx >= 1408;
            int rem = m ? idx - 1408 : idx;
            int row = rem / 11, ch = rem - row * 11;
            const __nv_bfloat16* g =
                (m ? KlB : KhB) + (size_t)(kt * 128 + row) * 88 + ch * 8;
            CP16(sb + m * 22528u + row * 176 + ch * 16, g);
        }
        asm volatile("cp.async.commit_group;");
    };

    load_k(0, 0);

    if (tid < 240) {
        int g = tid / 80, d = tid - g * 80;
        float r0 = gm[g * 4 + 0] + gm[g * 4 + 1];
        float r1 = gm[g * 4 + 2] + gm[g * 4 + 3];
        float ph = gp[g * 80 + d];
        coeff[tid] = (cosf(ph) * r0 + sinf(ph) * r1) * ga[g * 80 + d];
    }
    __syncthreads();

    // build Qext (4 variants x 16 rows x 80 dims, scale folded in)
    const float scale = rsqrtf(80.0f);
    for (int idx = tid; idx < 1280; idx += 256) {
        int r = idx / 80, d = idx - r * 80;
        float v = qsrc[(size_t)(b * 1024 + q0 + r) * 2560 + h * 80 + d] * scale;
        float vv[4] = {v, v * coeff[d], v * coeff[80 + d], v * coeff[160 + d]};
#pragma unroll
        for (int g = 0; g < 4; g++) {
            uint32_t o = (g * 16 + r) * 176 + d * 2;
            __nv_bfloat16 hh = __float2bfloat16(vv[g]);
            *(__nv_bfloat16*)(sm + AT_QH + o) = hh;
            *(__nv_bfloat16*)(sm + AT_QL + o) =
                __float2bfloat16(vv[g] - __bfloat162float(hh));
        }
    }

    const float intf = isr[0] * (1.0f / 3.0f);
    float csf[64];     // fp32 scores: [kt*8 + n8*4 + j]

    // ---- Phase 1: scores; warp wid owns keys [kt*128 + wid*16, +16) ----
#pragma unroll
    for (int kt = 0; kt < 8; kt++) {
        const int stg = kt & 1;
        asm volatile("cp.async.wait_group 0;");
        __syncthreads();
        if (kt < 7) load_k(kt + 1, stg ^ 1);

        const uint32_t kbase = base + AT_K + (uint32_t)stg * AT_KSTG;
        float acc[4][2][4];
#pragma unroll
        for (int g = 0; g < 4; g++)
#pragma unroll
            for (int i = 0; i < 2; i++)
#pragma unroll
                for (int j = 0; j < 4; j++) acc[g][i][j] = 0.0f;

#pragma unroll
        for (int ks = 0; ks < 5; ks++) {
            uint32_t bH[4], bL[4];
            uint32_t rb = (wid * 16 + lr) * 176 + ks * 32 + lc;
            LDSM4(bH, kbase + rb);
            LDSM4(bL, kbase + 22528u + rb);
#pragma unroll
            for (int g = 0; g < 4; g++) {
                uint32_t aH[4], aL[4];
                uint32_t ro = (g * 16 + lr) * 176 + ks * 32 + lc;
                LDSM4(aH, base + AT_QH + ro);
                LDSM4(aL, base + AT_QL + ro);
                MMA_BF16(acc[g][0], aH, bH[0], bH[2]);
                MMA_BF16(acc[g][1], aH, bH[1], bH[3]);
                MMA_BF16(acc[g][0], aH, bL[0], bL[2]);
                MMA_BF16(acc[g][1], aH, bL[1], bL[3]);
                MMA_BF16(acc[g][0], aL, bH[0], bH[2]);
                MMA_BF16(acc[g][1], aL, bH[1], bH[3]);
            }
        }

        // combine interference in registers -> fp32 scores
#pragma unroll
        for (int n8 = 0; n8 < 2; n8++) {
#pragma unroll
            for (int j = 0; j < 4; j++) {
                float a0 = acc[1][n8][j], a1 = acc[2][n8][j], a2 = acc[3][n8][j];
                csf[kt * 8 + n8 * 4 + j] =
                    acc[0][n8][j] + (a0 * a1 + a0 * a2 + a1 * a2) * intf;
            }
        }
    }
    __syncthreads();   // all K/Q reads done before V overwrites the region

    // preload V stages (overlap with softmax)
    const __half* VhB = Vh + (size_t)bh * 81920;
    auto load_v = [&](int kt, int stg) {
#pragma unroll
        for (int j = 0; j < 5; j++) {
            int idx = tid + j * 256;
            int dim = idx >> 4, ch = idx & 15;
            const __half* g = VhB + (size_t)dim * 1024 + kt * 128 + ch * 8;
            CP16(base + stg * AT_VSTG + dim * 272 + ch * 16, g);
        }
        asm volatile("cp.async.commit_group;");
    };
    load_v(0, 0);
    load_v(1, 1);

    // ---- Phase 2: softmax (fp32), then pack exp to fp16 fragments ----
    float m0 = -1e30f, m1 = -1e30f;
#pragma unroll
    for (int i = 0; i < 16; i++) {
        m0 = fmaxf(m0, fmaxf(csf[i * 4 + 0], csf[i * 4 + 1]));
        m1 = fmaxf(m1, fmaxf(csf[i * 4 + 2], csf[i * 4 + 3]));
    }
#pragma unroll
    for (int off = 1; off <= 2; off <<= 1) {
        m0 = fmaxf(m0, __shfl_xor_sync(0xffffffffu, m0, off));
        m1 = fmaxf(m1, __shfl_xor_sync(0xffffffffu, m1, off));
    }
    if ((lane & 3) == 0) {
        pbuf[wid * 16 + rr] = m0;
        pbuf[wid * 16 + rr + 8] = m1;
    }
    __syncthreads();
    float M0 = -1e30f, M1 = -1e30f;
#pragma unroll
    for (int w = 0; w < 8; w++) {
        M0 = fmaxf(M0, pbuf[w * 16 + rr]);
        M1 = fmaxf(M1, pbuf[w * 16 + rr + 8]);
    }
    __syncthreads();

    uint32_t ps[32];   // fp16x2 P fragments
    float s0 = 0.0f, s1 = 0.0f;
#pragma unroll
    for (int i = 0; i < 16; i++) {
        float e0 = __expf(csf[i * 4 + 0] - M0);
        float e1 = __expf(csf[i * 4 + 1] - M0);
        float e2 = __expf(csf[i * 4 + 2] - M1);
        float e3 = __expf(csf[i * 4 + 3] - M1);
        s0 += e0 + e1;
        s1 += e2 + e3;
        ps[i * 2 + 0] = pack_h2(e0, e1);
        ps[i * 2 + 1] = pack_h2(e2, e3);
    }
#pragma unroll
    for (int off = 1; off <= 2; off <<= 1) {
        s0 += __shfl_xor_sync(0xffffffffu, s0, off);
        s1 += __shfl_xor_sync(0xffffffffu, s1, off);
    }
    if ((lane & 3) == 0) {
        pbuf[wid * 16 + rr] = s0;
        pbuf[wid * 16 + rr + 8] = s1;
    }
    __syncthreads();
    if (wid == 0 && lane < 16) {
        float S = 0.0f;
#pragma unroll
        for (int w = 0; w < 8; w++) S += pbuf[w * 16 + lane];
        rsum[lane] = S;
    }

    // ---- Phase 3: P @ Vh (single term) ----
    float acc3[10][4];
#pragma unroll
    for (int i = 0; i < 10; i++)
#pragma unroll
        for (int j = 0; j < 4; j++) acc3[i][j] = 0.0f;

#pragma unroll
    for (int kt = 0; kt < 8; kt++) {
        if (kt < 7) {
            asm volatile("cp.async.wait_group 1;");
        } else {
            asm volatile("cp.async.wait_group 0;");
        }
        __syncthreads();

        const uint32_t vb = base + (uint32_t)(kt & 1) * AT_VSTG;
        uint32_t pA[4] = {ps[kt * 4 + 0], ps[kt * 4 + 1],
                          ps[kt * 4 + 2], ps[kt * 4 + 3]};
#pragma unroll
        for (int nd = 0; nd < 5; nd++) {
            uint32_t vh[4];
            uint32_t rb = (nd * 16 + lr) * 272 + wid * 32 + lc;
            LDSM4(vh, vb + rb);
            MMA_F16(acc3[nd * 2],     pA, vh[0], vh[2]);
            MMA_F16(acc3[nd * 2 + 1], pA, vh[1], vh[3]);
        }
        __syncthreads();
        if (kt < 6) load_v(kt + 2, kt & 1);
    }

    // cross-warp reduce (RED at smem offset 0; V buffers dead)
    float* red = (float*)sm;
    float* redw = red + wid * 1344;
#pragma unroll
    for (int j = 0; j < 10; j++) {
        int d = (j >> 1) * 16 + (j & 1) * 8 + cc;
        redw[rr * 84 + d]           = acc3[j][0];
        redw[rr * 84 + d + 1]       = acc3[j][1];
        redw[(rr + 8) * 84 + d]     = acc3[j][2];
        redw[(rr + 8) * 84 + d + 1] = acc3[j][3];
    }
    __syncthreads();

    const float cph = cosf(qp[h]);
    for (int idx = tid; idx < 1280; idx += 256) {
        int r = idx / 80, d = idx - r * 80;
        float s = 0.0f;
#pragma unroll
        for (int w = 0; w < 8; w++) s += red[w * 1344 + r * 84 + d];
        float o = s * cph / rsum[r];
        size_t go = (size_t)(b * 1024 + q0 + r) * 2560 + h * 80 + d;
        __nv_bfloat16 hh = __float2bfloat16(o);
        out_hi[go] = hh;
        out_lo[go] = __float2bfloat16(o - __bfloat162float(hh));
    }
}

// ---------------------------------------------------------------------------
extern "C" void kernel_launch(void* const* d_in, const int* in_sizes, int n_in,
                              void* d_out, int out_size) {
    const float* hidden = (const float*)d_in[0];
    const float* Wqkv   = (const float*)d_in[1];
    const float* bqkv   = (const float*)d_in[2];
    const float* Wproj  = (const float*)d_in[3];
    const float* bproj  = (const float*)d_in[4];
    const float* gm     = (const float*)d_in[5];
    const float* gp     = (const float*)d_in[6];
    const float* ga     = (const float*)d_in[7];
    const float* qp     = (const float*)d_in[8];
    const float* isr    = (const float*)d_in[9];
    float* out = (float*)d_out;

    void *p_q, *p_hh, *p_hl, *p_wqh, *p_wql, *p_wph, *p_wpl, *p_ah, *p_al;
    void *p_kh, *p_kl, *p_vh;
    cudaGetSymbolAddress(&p_q, g_q);
    cudaGetSymbolAddress(&p_hh, g_hid_hi);
    cudaGetSymbolAddress(&p_hl, g_hid_lo);
    cudaGetSymbolAddress(&p_wqh, g_wqkvT_hi);
    cudaGetSymbolAddress(&p_wql, g_wqkvT_lo);
    cudaGetSymbolAddress(&p_wph, g_wprojT_hi);
    cudaGetSymbolAddress(&p_wpl, g_wprojT_lo);
    cudaGetSymbolAddress(&p_ah, g_attn_hi);
    cudaGetSymbolAddress(&p_al, g_attn_lo);
    cudaGetSymbolAddress(&p_kh, g_Khi);
    cudaGetSymbolAddress(&p_kl, g_Klo);
    cudaGetSymbolAddress(&p_vh, g_Vthi);

    const int GEMM_SMEM = 3 * 49152;
    cudaFuncSetAttribute(gemm_qkv,
                         cudaFuncAttributeMaxDynamicSharedMemorySize, GEMM_SMEM);
    cudaFuncSetAttribute(gemm_bf16x3,
                         cudaFuncAttributeMaxDynamicSharedMemorySize, GEMM_SMEM);
    cudaFuncSetAttribute(attn_mma,
                         cudaFuncAttributeMaxDynamicSharedMemorySize, AT_SMEM);

    // 1) input conversions
    conv_hilo<<<5120, 256>>>(hidden, (__nv_bfloat16*)p_hh, (__nv_bfloat16*)p_hl,
                             2048 * 2560 / 4);
    transpose_conv2<<<dim3(240, 80, 2), dim3(32, 8)>>>(
        Wqkv, Wproj,
        (__nv_bfloat16*)p_wqh, (__nv_bfloat16*)p_wql,
        (__nv_bfloat16*)p_wph, (__nv_bfloat16*)p_wpl);

    // 2) fused qkv GEMM (N-tile 64): q fp32, k bf16 hi/lo, v fp16
    gemm_qkv<<<dim3(120, 16), 256, GEMM_SMEM>>>(
        (const __nv_bfloat16*)p_hh, (const __nv_bfloat16*)p_hl,
        (const __nv_bfloat16*)p_wqh, (const __nv_bfloat16*)p_wql,
        bqkv, (float*)p_q,
        (__nv_bfloat16*)p_kh, (__nv_bfloat16*)p_kl,
        (__half*)p_vh);

    // 3) register-resident tensor-core quantum attention
    attn_mma<<<dim3(64, 64), 256, AT_SMEM>>>(
        (const float*)p_q,
        (const __nv_bfloat16*)p_kh, (const __nv_bfloat16*)p_kl,
        (const __half*)p_vh,
        gm, gp, ga, qp, isr,
        (__nv_bfloat16*)p_ah, (__nv_bfloat16*)p_al);

    // 4) out = attn @ Wproj + bproj (N-tile 64)
    gemm_bf16x3<<<dim3(40, 16), 256, GEMM_SMEM>>>(
        (const __nv_bfloat16*)p_ah, (const __nv_bfloat16*)p_al,
        (const __nv_bfloat16*)p_wph, (const __nv_bfloat16*)p_wpl,
        bproj, out, 2560);
}

// round 13
// speedup vs baseline: 1.8935x; 1.0835x over previous
#include <cuda_runtime.h>
#include <cuda_bf16.h>
#include <cuda_fp16.h>
#include <stdint.h>
#include <math.h>

// Problem constants: B=2, S=1024, E=2560, H=32, D=80, 3E=7680, BS=2048, K=2560

// ---------------- device scratch ----------------
__device__ float g_q[2048ull * 2560];                  // q part, fp32 compact
__device__ __nv_bfloat16 g_hid_hi[2048ull * 2560];
__device__ __nv_bfloat16 g_hid_lo[2048ull * 2560];
__device__ __nv_bfloat16 g_wqkvT_hi[7680ull * 2560];   // (N,K)
__device__ __nv_bfloat16 g_wqkvT_lo[7680ull * 2560];
__device__ __half g_wprojT_hi[2560ull * 2560];         // fp16 (N,K)
__device__ __half g_wprojT_lo[2560ull * 2560];
__device__ __half g_attn[2048ull * 2560];              // fp16 single
__device__ __nv_bfloat16 g_Khi[64ull * 1024 * 88];     // [bh][key][88]
__device__ __nv_bfloat16 g_Klo[64ull * 1024 * 88];
__device__ __half g_Vthi[64ull * 80 * 1024];           // [bh][dim][1024] fp16

__device__ __forceinline__ uint32_t smem_u32(const void* p) {
    uint32_t a;
    asm("{ .reg .u64 t; cvta.to.shared.u64 t, %1; cvt.u32.u64 %0, t; }"
        : "=r"(a) : "l"(p));
    return a;
}

#define SWZ(o) ((uint32_t)(o) ^ ((((uint32_t)(o)) >> 3) & 0x70u))

#define CP16(s, g) \
    asm volatile("cp.async.cg.shared.global [%0], [%1], 16;" :: "r"(s), "l"(g))

#define LDSM4(r, addr) \
    asm volatile("ldmatrix.sync.aligned.m8n8.x4.shared.b16 {%0,%1,%2,%3}, [%4];" \
                 : "=r"((r)[0]), "=r"((r)[1]), "=r"((r)[2]), "=r"((r)[3]) \
                 : "r"(addr))

#define MMA_BF16(acc, A, b0, b1) \
    asm volatile("mma.sync.aligned.m16n8k16.row.col.f32.bf16.bf16.f32 " \
                 "{%0,%1,%2,%3}, {%4,%5,%6,%7}, {%8,%9}, {%0,%1,%2,%3};" \
                 : "+f"((acc)[0]), "+f"((acc)[1]), "+f"((acc)[2]), "+f"((acc)[3]) \
                 : "r"((A)[0]), "r"((A)[1]), "r"((A)[2]), "r"((A)[3]), \
                   "r"(b0), "r"(b1))

#define MMA_F16(acc, A, b0, b1) \
    asm volatile("mma.sync.aligned.m16n8k16.row.col.f32.f16.f16.f32 " \
                 "{%0,%1,%2,%3}, {%4,%5,%6,%7}, {%8,%9}, {%0,%1,%2,%3};" \
                 : "+f"((acc)[0]), "+f"((acc)[1]), "+f"((acc)[2]), "+f"((acc)[3]) \
                 : "r"((A)[0]), "r"((A)[1]), "r"((A)[2]), "r"((A)[3]), \
                   "r"(b0), "r"(b1))

__device__ __forceinline__ uint32_t pack_h2(float a, float b) {
    __half2 h = __floats2half2_rn(a, b);
    return *(uint32_t*)&h;
}

// ---------------------------------------------------------------------------
// Conversion: fp32 -> bf16 hi/lo
// ---------------------------------------------------------------------------
__global__ void conv_hilo(const float* __restrict__ X,
                          __nv_bfloat16* __restrict__ Hh,
                          __nv_bfloat16* __restrict__ Ll, int n4) {
    int i = blockIdx.x * blockDim.x + threadIdx.x;
    if (i >= n4) return;
    float4 v = ((const float4*)X)[i];
    __nv_bfloat16 h0 = __float2bfloat16(v.x), h1 = __float2bfloat16(v.y);
    __nv_bfloat16 h2 = __float2bfloat16(v.z), h3 = __float2bfloat16(v.w);
    __nv_bfloat162 a, b;
    a.x = h0; a.y = h1; b.x = h2; b.y = h3;
    ((__nv_bfloat162*)Hh)[i * 2] = a;
    ((__nv_bfloat162*)Hh)[i * 2 + 1] = b;
    __nv_bfloat162 c, d;
    c.x = __float2bfloat16(v.x - __bfloat162float(h0));
    c.y = __float2bfloat16(v.y - __bfloat162float(h1));
    d.x = __float2bfloat16(v.z - __bfloat162float(h2));
    d.y = __float2bfloat16(v.w - __bfloat162float(h3));
    ((__nv_bfloat162*)Ll)[i * 2] = c;
    ((__nv_bfloat162*)Ll)[i * 2 + 1] = d;
}

// ---------------------------------------------------------------------------
// Transpose + convert both weights (z=0: Wqkv -> bf16 hi/lo, z=1: Wproj -> fp16 hi/lo)
// ---------------------------------------------------------------------------
__global__ void transpose_conv2(const float* __restrict__ Wq,
                                const float* __restrict__ Wp,
                                __nv_bfloat16* __restrict__ Tqh,
                                __nv_bfloat16* __restrict__ Tql,
                                __half* __restrict__ Tph,
                                __half* __restrict__ Tpl) {
    __shared__ float t[32][33];
    const int z = blockIdx.z;
    if (z == 1 && blockIdx.x >= 80) return;
    const float* W = z ? Wp : Wq;
    const int N = z ? 2560 : 7680;
    const int K = 2560;
    int n0 = blockIdx.x * 32, k0 = blockIdx.y * 32;
    int tx = threadIdx.x, ty = threadIdx.y;
#pragma unroll
    for (int j = 0; j < 4; j++)
        t[ty + j * 8][tx] = W[(size_t)(k0 + ty + j * 8) * N + n0 + tx];
    __syncthreads();
#pragma unroll
    for (int j = 0; j < 4; j++) {
        float v = t[tx][ty + j * 8];
        size_t o = (size_t)(n0 + ty + j * 8) * K + k0 + tx;
        if (z == 0) {
            __nv_bfloat16 h = __float2bfloat16(v);
            Tqh[o] = h;
            Tql[o] = __float2bfloat16(v - __bfloat162float(h));
        } else {
            __half h = __float2half(v);
            Tph[o] = h;
            Tpl[o] = __float2half(v - __half2float(h));
        }
    }
}

// ---------------------------------------------------------------------------
// GEMM1 (fused): CTA 128x64, 256 threads (8 warps, 32x32 warp tiles),
// 3-stage cp.async (48KB/stage). Epilogue routes q/k/v.
// ---------------------------------------------------------------------------
__global__ __launch_bounds__(256, 1) void gemm_qkv(
    const __nv_bfloat16* __restrict__ Ah, const __nv_bfloat16* __restrict__ Al,
    const __nv_bfloat16* __restrict__ Bh, const __nv_bfloat16* __restrict__ Bl,
    const float* __restrict__ bias, float* __restrict__ Qout,
    __nv_bfloat16* __restrict__ Kh, __nv_bfloat16* __restrict__ Kl,
    __half* __restrict__ Vh) {
    extern __shared__ __align__(1024) char dsm[];
    const uint32_t base = smem_u32(dsm);

    const int tid = threadIdx.x;
    const int wid = tid >> 5, lane = tid & 31;
    const int mw = wid & 3;
    const int nw = wid >> 2;
    const int mt = blockIdx.y, nt = blockIdx.x;
    const int K = 2560;

    const int trow = tid >> 3;
    const int tkg = tid & 7;

    float acc[2][4][4];
#pragma unroll
    for (int a = 0; a < 2; a++)
#pragma unroll
        for (int b = 0; b < 4; b++)
#pragma unroll
            for (int c = 0; c < 4; c++) acc[a][b][c] = 0.0f;

    auto load_chunk = [&](int c, int st) {
        const int k0 = c * 64;
        const uint32_t s0 = base + st * 49152;
#pragma unroll
        for (int j = 0; j < 4; j++) {
            const int row = j * 32 + trow;
            const uint32_t so = SWZ(row * 128 + tkg * 16);
            CP16(s0 + so, Ah + (size_t)(mt * 128 + row) * K + k0 + tkg * 8);
            CP16(s0 + 16384 + so, Al + (size_t)(mt * 128 + row) * K + k0 + tkg * 8);
        }
#pragma unroll
        for (int j = 0; j < 2; j++) {
            const int row = j * 32 + trow;
            const uint32_t so = SWZ(row * 128 + tkg * 16);
            CP16(s0 + 32768 + so, Bh + (size_t)(nt * 64 + row) * K + k0 + tkg * 8);
            CP16(s0 + 40960 + so, Bl + (size_t)(nt * 64 + row) * K + k0 + tkg * 8);
        }
        asm volatile("cp.async.commit_group;");
    };

    const int lr = lane & 15;
    const int lc = (lane >> 4) * 16;

    load_chunk(0, 0);
    load_chunk(1, 1);

    int st = 0;
    for (int c = 0; c < 40; c++) {
        if (c < 39) {
            asm volatile("cp.async.wait_group 1;");
        } else {
            asm volatile("cp.async.wait_group 0;");
        }
        __syncthreads();
        if (c + 2 < 40) {
            int st2 = st + 2;
            if (st2 >= 3) st2 -= 3;
            load_chunk(c + 2, st2);
        }

        const uint32_t sA = base + st * 49152;
#pragma unroll
        for (int ks = 0; ks < 4; ks++) {
            uint32_t ah[2][4], al[2][4];
#pragma unroll
            for (int mb = 0; mb < 2; mb++) {
                const uint32_t ro = (mw * 32 + mb * 16 + lr) * 128 + ks * 32 + lc;
                LDSM4(ah[mb], sA + SWZ(ro));
                LDSM4(al[mb], sA + 16384 + SWZ(ro));
            }
            uint32_t bh2[2][4], bl2[2][4];
#pragma unroll
            for (int nb = 0; nb < 2; nb++) {
                const uint32_t ro = (nw * 32 + nb * 16 + lr) * 128 + ks * 32 + lc;
                LDSM4(bh2[nb], sA + 32768 + SWZ(ro));
                LDSM4(bl2[nb], sA + 40960 + SWZ(ro));
            }
#pragma unroll
            for (int mb = 0; mb < 2; mb++)
#pragma unroll
                for (int nb = 0; nb < 2; nb++) {
                    MMA_BF16(acc[mb][nb * 2],     ah[mb], bh2[nb][0], bh2[nb][2]);
                    MMA_BF16(acc[mb][nb * 2 + 1], ah[mb], bh2[nb][1], bh2[nb][3]);
                }
#pragma unroll
            for (int mb = 0; mb < 2; mb++)
#pragma unroll
                for (int nb = 0; nb < 2; nb++) {
                    MMA_BF16(acc[mb][nb * 2],     ah[mb], bl2[nb][0], bl2[nb][2]);
                    MMA_BF16(acc[mb][nb * 2 + 1], ah[mb], bl2[nb][1], bl2[nb][3]);
                }
#pragma unroll
            for (int mb = 0; mb < 2; mb++)
#pragma unroll
                for (int nb = 0; nb < 2; nb++) {
                    MMA_BF16(acc[mb][nb * 2],     al[mb], bh2[nb][0], bh2[nb][2]);
                    MMA_BF16(acc[mb][nb * 2 + 1], al[mb], bh2[nb][1], bh2[nb][3]);
                }
        }
        st++;
        if (st >= 3) st -= 3;
    }

    const int row0 = mt * 128 + mw * 32 + (lane >> 2);
    const int col0 = nt * 64 + nw * 32 + 2 * (lane & 3);

    if (nt < 40) {
#pragma unroll
        for (int mb = 0; mb < 2; mb++) {
#pragma unroll
            for (int n8 = 0; n8 < 4; n8++) {
                const int gc = col0 + n8 * 8;
                const float b0 = bias[gc], b1 = bias[gc + 1];
                const int r = row0 + mb * 16;
                float2 o0 = make_float2(acc[mb][n8][0] + b0, acc[mb][n8][1] + b1);
                float2 o1 = make_float2(acc[mb][n8][2] + b0, acc[mb][n8][3] + b1);
                *(float2*)&Qout[(size_t)r * 2560 + gc] = o0;
                *(float2*)&Qout[(size_t)(r + 8) * 2560 + gc] = o1;
            }
        }
    } else if (nt < 80) {
        // K -> bf16 hi/lo [bh][key][88]
#pragma unroll
        for (int mb = 0; mb < 2; mb++) {
#pragma unroll
            for (int n8 = 0; n8 < 4; n8++) {
#pragma unroll
                for (int e = 0; e < 4; e++) {
                    const int gc = col0 + n8 * 8 + (e & 1);
                    const int r = row0 + mb * 16 + (e >> 1) * 8;
                    float val = acc[mb][n8][e] + bias[gc];
                    const int c2 = gc - 2560;
                    const int h = c2 / 80;
                    const int d = c2 - h * 80;
                    const int bb = r >> 10, key = r & 1023;
                    const size_t o = (size_t)(bb * 32 + h) * 90112 +
                                     (size_t)key * 88 + d;
                    __nv_bfloat16 hh = __float2bfloat16(val);
                    Kh[o] = hh;
                    Kl[o] = __float2bfloat16(val - __bfloat162float(hh));
                }
            }
        }
    } else {
        // V -> fp16 transposed [bh][dim][1024]
#pragma unroll
        for (int mb = 0; mb < 2; mb++) {
#pragma unroll
            for (int n8 = 0; n8 < 4; n8++) {
#pragma unroll
                for (int e = 0; e < 4; e++) {
                    const int gc = col0 + n8 * 8 + (e & 1);
                    const int r = row0 + mb * 16 + (e >> 1) * 8;
                    float val = acc[mb][n8][e] + bias[gc];
                    const int c2 = gc - 5120;
                    const int h = c2 / 80;
                    const int d = c2 - h * 80;
                    const int bb = r >> 10, key = r & 1023;
                    const size_t o = (size_t)(bb * 32 + h) * 81920 +
                                     (size_t)d * 1024 + key;
                    Vh[o] = __float2half(val);
                }
            }
        }
    }
}

// ---------------------------------------------------------------------------
// GEMM2: fp16 2-term. C(2048,2560) = A(fp16) @ (Bh+Bl)(fp16)^T + bias.
// CTA 128x64, 256 threads, 3-stage cp.async (32KB/stage). grid (40, 16).
// ---------------------------------------------------------------------------
__global__ __launch_bounds__(256, 1) void gemm_proj_f16(
    const __half* __restrict__ Ah,
    const __half* __restrict__ Bh, const __half* __restrict__ Bl,
    const float* __restrict__ bias, float* __restrict__ C, int N) {
    extern __shared__ __align__(1024) char dsm[];
    const uint32_t base = smem_u32(dsm);

    const int tid = threadIdx.x;
    const int wid = tid >> 5, lane = tid & 31;
    const int mw = wid & 3;
    const int nw = wid >> 2;
    const int mt = blockIdx.y, nt = blockIdx.x;
    const int K = 2560;

    const int trow = tid >> 3;
    const int tkg = tid & 7;

    float acc[2][4][4];
#pragma unroll
    for (int a = 0; a < 2; a++)
#pragma unroll
        for (int b = 0; b < 4; b++)
#pragma unroll
            for (int c = 0; c < 4; c++) acc[a][b][c] = 0.0f;

    auto load_chunk = [&](int c, int st) {
        const int k0 = c * 64;
        const uint32_t s0 = base + st * 32768;
#pragma unroll
        for (int j = 0; j < 4; j++) {
            const int row = j * 32 + trow;
            const uint32_t so = SWZ(row * 128 + tkg * 16);
            CP16(s0 + so, Ah + (size_t)(mt * 128 + row) * K + k0 + tkg * 8);
        }
#pragma unroll
        for (int j = 0; j < 2; j++) {
            const int row = j * 32 + trow;
            const uint32_t so = SWZ(row * 128 + tkg * 16);
            CP16(s0 + 16384 + so, Bh + (size_t)(nt * 64 + row) * K + k0 + tkg * 8);
            CP16(s0 + 24576 + so, Bl + (size_t)(nt * 64 + row) * K + k0 + tkg * 8);
        }
        asm volatile("cp.async.commit_group;");
    };

    const int lr = lane & 15;
    const int lc = (lane >> 4) * 16;

    load_chunk(0, 0);
    load_chunk(1, 1);

    int st = 0;
    for (int c = 0; c < 40; c++) {
        if (c < 39) {
            asm volatile("cp.async.wait_group 1;");
        } else {
            asm volatile("cp.async.wait_group 0;");
        }
        __syncthreads();
        if (c + 2 < 40) {
            int st2 = st + 2;
            if (st2 >= 3) st2 -= 3;
            load_chunk(c + 2, st2);
        }

        const uint32_t sA = base + st * 32768;
#pragma unroll
        for (int ks = 0; ks < 4; ks++) {
            uint32_t ah[2][4];
#pragma unroll
            for (int mb = 0; mb < 2; mb++) {
                const uint32_t ro = (mw * 32 + mb * 16 + lr) * 128 + ks * 32 + lc;
                LDSM4(ah[mb], sA + SWZ(ro));
            }
            uint32_t bh2[2][4], bl2[2][4];
#pragma unroll
            for (int nb = 0; nb < 2; nb++) {
                const uint32_t ro = (nw * 32 + nb * 16 + lr) * 128 + ks * 32 + lc;
                LDSM4(bh2[nb], sA + 16384 + SWZ(ro));
                LDSM4(bl2[nb], sA + 24576 + SWZ(ro));
            }
#pragma unroll
            for (int mb = 0; mb < 2; mb++)
#pragma unroll
                for (int nb = 0; nb < 2; nb++) {
                    MMA_F16(acc[mb][nb * 2],     ah[mb], bh2[nb][0], bh2[nb][2]);
                    MMA_F16(acc[mb][nb * 2 + 1], ah[mb], bh2[nb][1], bh2[nb][3]);
                }
#pragma unroll
            for (int mb = 0; mb < 2; mb++)
#pragma unroll
                for (int nb = 0; nb < 2; nb++) {
                    MMA_F16(acc[mb][nb * 2],     ah[mb], bl2[nb][0], bl2[nb][2]);
                    MMA_F16(acc[mb][nb * 2 + 1], ah[mb], bl2[nb][1], bl2[nb][3]);
                }
        }
        st++;
        if (st >= 3) st -= 3;
    }

    const int row0 = mt * 128 + mw * 32 + (lane >> 2);
    const int col0 = nt * 64 + nw * 32 + 2 * (lane & 3);
#pragma unroll
    for (int mb = 0; mb < 2; mb++) {
#pragma unroll
        for (int n8 = 0; n8 < 4; n8++) {
            const int gc = col0 + n8 * 8;
            const float b0 = bias[gc], b1 = bias[gc + 1];
            const int r = row0 + mb * 16;
            float2 o0 = make_float2(acc[mb][n8][0] + b0, acc[mb][n8][1] + b1);
            float2 o1 = make_float2(acc[mb][n8][2] + b0, acc[mb][n8][3] + b1);
            *(float2*)&C[(size_t)r * N + gc] = o0;
            *(float2*)&C[(size_t)(r + 8) * N + gc] = o1;
        }
    }
}

// ---------------------------------------------------------------------------
// attn_mma v6: scores fp32 in registers; P fp16; V fp16 single-term.
// Output: fp16 single (feeds fp16 GEMM2).
// smem: QH [0,11264) | QL [11264,22528) | K 2 stages [22528,112640) -> 2 CTAs/SM.
// ---------------------------------------------------------------------------
#define AT_QH 0u
#define AT_QL 11264u
#define AT_K  22528u
#define AT_KSTG 45056u
#define AT_VSTG 21760u
#define AT_SMEM 112640

__global__ __launch_bounds__(256, 2) void attn_mma(
    const float* __restrict__ qsrc,
    const __nv_bfloat16* __restrict__ Kh, const __nv_bfloat16* __restrict__ Kl,
    const __half* __restrict__ Vh,
    const float* __restrict__ gm, const float* __restrict__ gp,
    const float* __restrict__ ga, const float* __restrict__ qp,
    const float* __restrict__ isr,
    __half* __restrict__ out_h) {
    extern __shared__ __align__(128) char smc[];
    __shared__ float coeff[240];
    __shared__ float pbuf[128];
    __shared__ float rsum[16];
    char* sm = smc;
    const uint32_t base = smem_u32(smc);

    const int tid = threadIdx.x;
    const int wid = tid >> 5, lane = tid & 31;
    const int lr = lane & 15, lc = (lane >> 4) << 4;
    const int rr = lane >> 2, cc = (lane & 3) * 2;
    const int bh = blockIdx.y, b = bh >> 5, h = bh & 31;
    const int q0 = blockIdx.x * 16;

    const __nv_bfloat16* KhB = Kh + (size_t)bh * 90112;
    const __nv_bfloat16* KlB = Kl + (size_t)bh * 90112;
    auto load_k = [&](int kt, int stg) {
        const uint32_t sb = base + AT_K + (uint32_t)stg * AT_KSTG;
#pragma unroll
        for (int j = 0; j < 11; j++) {
            int idx = tid + j * 256;
            int m = idx >= 1408;
            int rem = m ? idx - 1408 : idx;
            int row = rem / 11, ch = rem - row * 11;
            const __nv_bfloat16* g =
                (m ? KlB : KhB) + (size_t)(kt * 128 + row) * 88 + ch * 8;
            CP16(sb + m * 22528u + row * 176 + ch * 16, g);
        }
        asm volatile("cp.async.commit_group;");
    };

    load_k(0, 0);

    if (tid < 240) {
        int g = tid / 80, d = tid - g * 80;
        float r0 = gm[g * 4 + 0] + gm[g * 4 + 1];
        float r1 = gm[g * 4 + 2] + gm[g * 4 + 3];
        float ph = gp[g * 80 + d];
        coeff[tid] = (cosf(ph) * r0 + sinf(ph) * r1) * ga[g * 80 + d];
    }
    __syncthreads();

    // build Qext (4 variants x 16 rows x 80 dims, scale folded in)
    const float scale = rsqrtf(80.0f);
    for (int idx = tid; idx < 1280; idx += 256) {
        int r = idx / 80, d = idx - r * 80;
        float v = qsrc[(size_t)(b * 1024 + q0 + r) * 2560 + h * 80 + d] * scale;
        float vv[4] = {v, v * coeff[d], v * coeff[80 + d], v * coeff[160 + d]};
#pragma unroll
        for (int g = 0; g < 4; g++) {
            uint32_t o = (g * 16 + r) * 176 + d * 2;
            __nv_bfloat16 hh = __float2bfloat16(vv[g]);
            *(__nv_bfloat16*)(sm + AT_QH + o) = hh;
            *(__nv_bfloat16*)(sm + AT_QL + o) =
                __float2bfloat16(vv[g] - __bfloat162float(hh));
        }
    }

    const float intf = isr[0] * (1.0f / 3.0f);
    float csf[64];     // fp32 scores

    // ---- Phase 1: scores; warp wid owns keys [kt*128 + wid*16, +16) ----
#pragma unroll
    for (int kt = 0; kt < 8; kt++) {
        const int stg = kt & 1;
        asm volatile("cp.async.wait_group 0;");
        __syncthreads();
        if (kt < 7) load_k(kt + 1, stg ^ 1);

        const uint32_t kbase = base + AT_K + (uint32_t)stg * AT_KSTG;
        float acc[4][2][4];
#pragma unroll
        for (int g = 0; g < 4; g++)
#pragma unroll
            for (int i = 0; i < 2; i++)
#pragma unroll
                for (int j = 0; j < 4; j++) acc[g][i][j] = 0.0f;

#pragma unroll
        for (int ks = 0; ks < 5; ks++) {
            uint32_t bH[4], bL[4];
            uint32_t rb = (wid * 16 + lr) * 176 + ks * 32 + lc;
            LDSM4(bH, kbase + rb);
            LDSM4(bL, kbase + 22528u + rb);
#pragma unroll
            for (int g = 0; g < 4; g++) {
                uint32_t aH[4], aL[4];
                uint32_t ro = (g * 16 + lr) * 176 + ks * 32 + lc;
                LDSM4(aH, base + AT_QH + ro);
                LDSM4(aL, base + AT_QL + ro);
                MMA_BF16(acc[g][0], aH, bH[0], bH[2]);
                MMA_BF16(acc[g][1], aH, bH[1], bH[3]);
                MMA_BF16(acc[g][0], aH, bL[0], bL[2]);
                MMA_BF16(acc[g][1], aH, bL[1], bL[3]);
                MMA_BF16(acc[g][0], aL, bH[0], bH[2]);
                MMA_BF16(acc[g][1], aL, bH[1], bH[3]);
            }
        }

#pragma unroll
        for (int n8 = 0; n8 < 2; n8++) {
#pragma unroll
            for (int j = 0; j < 4; j++) {
                float a0 = acc[1][n8][j], a1 = acc[2][n8][j], a2 = acc[3][n8][j];
                csf[kt * 8 + n8 * 4 + j] =
                    acc[0][n8][j] + (a0 * a1 + a0 * a2 + a1 * a2) * intf;
            }
        }
    }
    __syncthreads();

    // preload V stages (overlap with softmax)
    const __half* VhB = Vh + (size_t)bh * 81920;
    auto load_v = [&](int kt, int stg) {
#pragma unroll
        for (int j = 0; j < 5; j++) {
            int idx = tid + j * 256;
            int dim = idx >> 4, ch = idx & 15;
            const __half* g = VhB + (size_t)dim * 1024 + kt * 128 + ch * 8;
            CP16(base + stg * AT_VSTG + dim * 272 + ch * 16, g);
        }
        asm volatile("cp.async.commit_group;");
    };
    load_v(0, 0);
    load_v(1, 1);

    // ---- Phase 2: softmax (fp32), pack exp to fp16 fragments ----
    float m0 = -1e30f, m1 = -1e30f;
#pragma unroll
    for (int i = 0; i < 16; i++) {
        m0 = fmaxf(m0, fmaxf(csf[i * 4 + 0], csf[i * 4 + 1]));
        m1 = fmaxf(m1, fmaxf(csf[i * 4 + 2], csf[i * 4 + 3]));
    }
#pragma unroll
    for (int off = 1; off <= 2; off <<= 1) {
        m0 = fmaxf(m0, __shfl_xor_sync(0xffffffffu, m0, off));
        m1 = fmaxf(m1, __shfl_xor_sync(0xffffffffu, m1, off));
    }
    if ((lane & 3) == 0) {
        pbuf[wid * 16 + rr] = m0;
        pbuf[wid * 16 + rr + 8] = m1;
    }
    __syncthreads();
    float M0 = -1e30f, M1 = -1e30f;
#pragma unroll
    for (int w = 0; w < 8; w++) {
        M0 = fmaxf(M0, pbuf[w * 16 + rr]);
        M1 = fmaxf(M1, pbuf[w * 16 + rr + 8]);
    }
    __syncthreads();

    uint32_t ps[32];
    float s0 = 0.0f, s1 = 0.0f;
#pragma unroll
    for (int i = 0; i < 16; i++) {
        float e0 = __expf(csf[i * 4 + 0] - M0);
        float e1 = __expf(csf[i * 4 + 1] - M0);
        float e2 = __expf(csf[i * 4 + 2] - M1);
        float e3 = __expf(csf[i * 4 + 3] - M1);
        s0 += e0 + e1;
        s1 += e2 + e3;
        ps[i * 2 + 0] = pack_h2(e0, e1);
        ps[i * 2 + 1] = pack_h2(e2, e3);
    }
#pragma unroll
    for (int off = 1; off <= 2; off <<= 1) {
        s0 += __shfl_xor_sync(0xffffffffu, s0, off);
        s1 += __shfl_xor_sync(0xffffffffu, s1, off);
    }
    if ((lane & 3) == 0) {
        pbuf[wid * 16 + rr] = s0;
        pbuf[wid * 16 + rr + 8] = s1;
    }
    __syncthreads();
    if (wid == 0 && lane < 16) {
        float S = 0.0f;
#pragma unroll
        for (int w = 0; w < 8; w++) S += pbuf[w * 16 + lane];
        rsum[lane] = S;
    }

    // ---- Phase 3: P @ Vh ----
    float acc3[10][4];
#pragma unroll
    for (int i = 0; i < 10; i++)
#pragma unroll
        for (int j = 0; j < 4; j++) acc3[i][j] = 0.0f;

#pragma unroll
    for (int kt = 0; kt < 8; kt++) {
        if (kt < 7) {
            asm volatile("cp.async.wait_group 1;");
        } else {
            asm volatile("cp.async.wait_group 0;");
        }
        __syncthreads();

        const uint32_t vb = base + (uint32_t)(kt & 1) * AT_VSTG;
        uint32_t pA[4] = {ps[kt * 4 + 0], ps[kt * 4 + 1],
                          ps[kt * 4 + 2], ps[kt * 4 + 3]};
#pragma unroll
        for (int nd = 0; nd < 5; nd++) {
            uint32_t vh[4];
            uint32_t rb = (nd * 16 + lr) * 272 + wid * 32 + lc;
            LDSM4(vh, vb + rb);
            MMA_F16(acc3[nd * 2],     pA, vh[0], vh[2]);
            MMA_F16(acc3[nd * 2 + 1], pA, vh[1], vh[3]);
        }
        __syncthreads();
        if (kt < 6) load_v(kt + 2, kt & 1);
    }

    // cross-warp reduce
    float* red = (float*)sm;
    float* redw = red + wid * 1344;
#pragma unroll
    for (int j = 0; j < 10; j++) {
        int d = (j >> 1) * 16 + (j & 1) * 8 + cc;
        redw[rr * 84 + d]           = acc3[j][0];
        redw[rr * 84 + d + 1]       = acc3[j][1];
        redw[(rr + 8) * 84 + d]     = acc3[j][2];
        redw[(rr + 8) * 84 + d + 1] = acc3[j][3];
    }
    __syncthreads();

    const float cph = cosf(qp[h]);
    for (int idx = tid; idx < 1280; idx += 256) {
        int r = idx / 80, d = idx - r * 80;
        float s = 0.0f;
#pragma unroll
        for (int w = 0; w < 8; w++) s += red[w * 1344 + r * 84 + d];
        float o = s * cph / rsum[r];
        size_t go = (size_t)(b * 1024 + q0 + r) * 2560 + h * 80 + d;
        out_h[go] = __float2half(o);
    }
}

// ---------------------------------------------------------------------------
extern "C" void kernel_launch(void* const* d_in, const int* in_sizes, int n_in,
                              void* d_out, int out_size) {
    const float* hidden = (const float*)d_in[0];
    const float* Wqkv   = (const float*)d_in[1];
    const float* bqkv   = (const float*)d_in[2];
    const float* Wproj  = (const float*)d_in[3];
    const float* bproj  = (const float*)d_in[4];
    const float* gm     = (const float*)d_in[5];
    const float* gp     = (const float*)d_in[6];
    const float* ga     = (const float*)d_in[7];
    const float* qp     = (const float*)d_in[8];
    const float* isr    = (const float*)d_in[9];
    float* out = (float*)d_out;

    void *p_q, *p_hh, *p_hl, *p_wqh, *p_wql, *p_wph, *p_wpl, *p_at;
    void *p_kh, *p_kl, *p_vh;
    cudaGetSymbolAddress(&p_q, g_q);
    cudaGetSymbolAddress(&p_hh, g_hid_hi);
    cudaGetSymbolAddress(&p_hl, g_hid_lo);
    cudaGetSymbolAddress(&p_wqh, g_wqkvT_hi);
    cudaGetSymbolAddress(&p_wql, g_wqkvT_lo);
    cudaGetSymbolAddress(&p_wph, g_wprojT_hi);
    cudaGetSymbolAddress(&p_wpl, g_wprojT_lo);
    cudaGetSymbolAddress(&p_at, g_attn);
    cudaGetSymbolAddress(&p_kh, g_Khi);
    cudaGetSymbolAddress(&p_kl, g_Klo);
    cudaGetSymbolAddress(&p_vh, g_Vthi);

    const int QKV_SMEM = 3 * 49152;
    const int PROJ_SMEM = 3 * 32768;
    cudaFuncSetAttribute(gemm_qkv,
                         cudaFuncAttributeMaxDynamicSharedMemorySize, QKV_SMEM);
    cudaFuncSetAttribute(gemm_proj_f16,
                         cudaFuncAttributeMaxDynamicSharedMemorySize, PROJ_SMEM);
    cudaFuncSetAttribute(attn_mma,
                         cudaFuncAttributeMaxDynamicSharedMemorySize, AT_SMEM);

    // 1) input conversions
    conv_hilo<<<5120, 256>>>(hidden, (__nv_bfloat16*)p_hh, (__nv_bfloat16*)p_hl,
                             2048 * 2560 / 4);
    transpose_conv2<<<dim3(240, 80, 2), dim3(32, 8)>>>(
        Wqkv, Wproj,
        (__nv_bfloat16*)p_wqh, (__nv_bfloat16*)p_wql,
        (__half*)p_wph, (__half*)p_wpl);

    // 2) fused qkv GEMM (N-tile 64): q fp32, k bf16 hi/lo, v fp16
    gemm_qkv<<<dim3(120, 16), 256, QKV_SMEM>>>(
        (const __nv_bfloat16*)p_hh, (const __nv_bfloat16*)p_hl,
        (const __nv_bfloat16*)p_wqh, (const __nv_bfloat16*)p_wql,
        bqkv, (float*)p_q,
        (__nv_bfloat16*)p_kh, (__nv_bfloat16*)p_kl,
        (__half*)p_vh);

    // 3) register-resident tensor-core quantum attention -> fp16
    attn_mma<<<dim3(64, 64), 256, AT_SMEM>>>(
        (const float*)p_q,
        (const __nv_bfloat16*)p_kh, (const __nv_bfloat16*)p_kl,
        (const __half*)p_vh,
        gm, gp, ga, qp, isr,
        (__half*)p_at);

    // 4) out = attn @ Wproj + bproj (fp16 2-term)
    gemm_proj_f16<<<dim3(40, 16), 256, PROJ_SMEM>>>(
        (const __half*)p_at,
        (const __half*)p_wph, (const __half*)p_wpl,
        bproj, out, 2560);
}

// round 14
// speedup vs baseline: 1.8975x; 1.0022x over previous
#include <cuda_runtime.h>
#include <cuda_bf16.h>
#include <cuda_fp16.h>
#include <stdint.h>
#include <math.h>

// Problem constants: B=2, S=1024, E=2560, H=32, D=80, 3E=7680, BS=2048, K=2560

// ---------------- device scratch ----------------
__device__ float g_q[2048ull * 2560];
__device__ __nv_bfloat16 g_hid_hi[2048ull * 2560];
__device__ __nv_bfloat16 g_hid_lo[2048ull * 2560];
__device__ __nv_bfloat16 g_wqkvT_hi[7680ull * 2560];   // (N,K)
__device__ __nv_bfloat16 g_wqkvT_lo[7680ull * 2560];
__device__ __half g_wprojT_hi[2560ull * 2560];         // fp16 (N,K)
__device__ __half g_wprojT_lo[2560ull * 2560];
__device__ __half g_attn[2048ull * 2560];              // fp16 single
__device__ __nv_bfloat16 g_Khi[64ull * 1024 * 88];     // [bh][key][88]
__device__ __nv_bfloat16 g_Klo[64ull * 1024 * 88];
__device__ __half g_Vthi[64ull * 80 * 1024];           // [bh][dim][1024] fp16

__device__ __forceinline__ uint32_t smem_u32(const void* p) {
    uint32_t a;
    asm("{ .reg .u64 t; cvta.to.shared.u64 t, %1; cvt.u32.u64 %0, t; }"
        : "=r"(a) : "l"(p));
    return a;
}

#define SWZ(o) ((uint32_t)(o) ^ ((((uint32_t)(o)) >> 3) & 0x70u))

#define CP16(s, g) \
    asm volatile("cp.async.cg.shared.global [%0], [%1], 16;" :: "r"(s), "l"(g))

#define LDSM4(r, addr) \
    asm volatile("ldmatrix.sync.aligned.m8n8.x4.shared.b16 {%0,%1,%2,%3}, [%4];" \
                 : "=r"((r)[0]), "=r"((r)[1]), "=r"((r)[2]), "=r"((r)[3]) \
                 : "r"(addr))

#define MMA_BF16(acc, A, b0, b1) \
    asm volatile("mma.sync.aligned.m16n8k16.row.col.f32.bf16.bf16.f32 " \
                 "{%0,%1,%2,%3}, {%4,%5,%6,%7}, {%8,%9}, {%0,%1,%2,%3};" \
                 : "+f"((acc)[0]), "+f"((acc)[1]), "+f"((acc)[2]), "+f"((acc)[3]) \
                 : "r"((A)[0]), "r"((A)[1]), "r"((A)[2]), "r"((A)[3]), \
                   "r"(b0), "r"(b1))

#define MMA_F16(acc, A, b0, b1) \
    asm volatile("mma.sync.aligned.m16n8k16.row.col.f32.f16.f16.f32 " \
                 "{%0,%1,%2,%3}, {%4,%5,%6,%7}, {%8,%9}, {%0,%1,%2,%3};" \
                 : "+f"((acc)[0]), "+f"((acc)[1]), "+f"((acc)[2]), "+f"((acc)[3]) \
                 : "r"((A)[0]), "r"((A)[1]), "r"((A)[2]), "r"((A)[3]), \
                   "r"(b0), "r"(b1))

__device__ __forceinline__ uint32_t pack_h2(float a, float b) {
    __half2 h = __floats2half2_rn(a, b);
    return *(uint32_t*)&h;
}

// ---------------------------------------------------------------------------
// prep_inputs: z=0 transpose Wqkv -> bf16 hi/lo, z=1 transpose Wproj -> fp16
// hi/lo, z=2 hidden -> bf16 hi/lo. grid (240, 80, 3), block (32, 8).
// ---------------------------------------------------------------------------
__global__ void prep_inputs(const float* __restrict__ hid,
                            const float* __restrict__ Wq,
                            const float* __restrict__ Wp,
                            __nv_bfloat16* __restrict__ Hh,
                            __nv_bfloat16* __restrict__ Hl,
                            __nv_bfloat16* __restrict__ Tqh,
                            __nv_bfloat16* __restrict__ Tql,
                            __half* __restrict__ Tph,
                            __half* __restrict__ Tpl) {
    const int z = blockIdx.z;
    const int tx = threadIdx.x, ty = threadIdx.y;
    const int t = ty * 32 + tx;

    if (z == 2) {
        int bid = blockIdx.y * 240 + blockIdx.x;
        if (bid >= 5120) return;
        int i = bid * 256 + t;   // < 2048*2560/4 = 1310720
        float4 v = ((const float4*)hid)[i];
        __nv_bfloat16 h0 = __float2bfloat16(v.x), h1 = __float2bfloat16(v.y);
        __nv_bfloat16 h2 = __float2bfloat16(v.z), h3 = __float2bfloat16(v.w);
        __nv_bfloat162 a, b;
        a.x = h0; a.y = h1; b.x = h2; b.y = h3;
        ((__nv_bfloat162*)Hh)[i * 2] = a;
        ((__nv_bfloat162*)Hh)[i * 2 + 1] = b;
        __nv_bfloat162 c, d;
        c.x = __float2bfloat16(v.x - __bfloat162float(h0));
        c.y = __float2bfloat16(v.y - __bfloat162float(h1));
        d.x = __float2bfloat16(v.z - __bfloat162float(h2));
        d.y = __float2bfloat16(v.w - __bfloat162float(h3));
        ((__nv_bfloat162*)Hl)[i * 2] = c;
        ((__nv_bfloat162*)Hl)[i * 2 + 1] = d;
        return;
    }

    __shared__ float tb[32][33];
    if (z == 1 && blockIdx.x >= 80) return;
    const float* W = z ? Wp : Wq;
    const int N = z ? 2560 : 7680;
    const int K = 2560;
    int n0 = blockIdx.x * 32, k0 = blockIdx.y * 32;
#pragma unroll
    for (int j = 0; j < 4; j++)
        tb[ty + j * 8][tx] = W[(size_t)(k0 + ty + j * 8) * N + n0 + tx];
    __syncthreads();
#pragma unroll
    for (int j = 0; j < 4; j++) {
        float v = tb[tx][ty + j * 8];
        size_t o = (size_t)(n0 + ty + j * 8) * K + k0 + tx;
        if (z == 0) {
            __nv_bfloat16 h = __float2bfloat16(v);
            Tqh[o] = h;
            Tql[o] = __float2bfloat16(v - __bfloat162float(h));
        } else {
            __half h = __float2half(v);
            Tph[o] = h;
            Tpl[o] = __float2half(v - __half2float(h));
        }
    }
}

// ---------------------------------------------------------------------------
// GEMM1 (fused): CTA 128x64, 256 threads, K-chunk 128 (2 x 64 sub-tiles),
// 2-stage cp.async (96KB/stage). Epilogue routes q/k/v.
// Stage: Ah[0,32K) Al[32K,64K) Bh[64K,80K) Bl[80K,96K); sub-tile kk at +kk*16K
// (A) / +kk*8K (B).
// ---------------------------------------------------------------------------
__global__ __launch_bounds__(256, 1) void gemm_qkv(
    const __nv_bfloat16* __restrict__ Ah, const __nv_bfloat16* __restrict__ Al,
    const __nv_bfloat16* __restrict__ Bh, const __nv_bfloat16* __restrict__ Bl,
    const float* __restrict__ bias, float* __restrict__ Qout,
    __nv_bfloat16* __restrict__ Kh, __nv_bfloat16* __restrict__ Kl,
    __half* __restrict__ Vh) {
    extern __shared__ __align__(1024) char dsm[];
    const uint32_t base = smem_u32(dsm);

    const int tid = threadIdx.x;
    const int wid = tid >> 5, lane = tid & 31;
    const int mw = wid & 3;
    const int nw = wid >> 2;
    const int mt = blockIdx.y, nt = blockIdx.x;
    const int K = 2560;

    const int trow = tid >> 3;
    const int tkg = tid & 7;

    float acc[2][4][4];
#pragma unroll
    for (int a = 0; a < 2; a++)
#pragma unroll
        for (int b = 0; b < 4; b++)
#pragma unroll
            for (int c = 0; c < 4; c++) acc[a][b][c] = 0.0f;

    auto load_chunk = [&](int c, int st) {
        const uint32_t s0 = base + st * 98304;
#pragma unroll
        for (int kk = 0; kk < 2; kk++) {
            const int k0 = c * 128 + kk * 64;
#pragma unroll
            for (int j = 0; j < 4; j++) {
                const int row = j * 32 + trow;
                const uint32_t so = SWZ(row * 128 + tkg * 16) + kk * 16384;
                CP16(s0 + so, Ah + (size_t)(mt * 128 + row) * K + k0 + tkg * 8);
                CP16(s0 + 32768 + so,
                     Al + (size_t)(mt * 128 + row) * K + k0 + tkg * 8);
            }
#pragma unroll
            for (int j = 0; j < 2; j++) {
                const int row = j * 32 + trow;
                const uint32_t so = SWZ(row * 128 + tkg * 16) + kk * 8192;
                CP16(s0 + 65536 + so,
                     Bh + (size_t)(nt * 64 + row) * K + k0 + tkg * 8);
                CP16(s0 + 81920 + so,
                     Bl + (size_t)(nt * 64 + row) * K + k0 + tkg * 8);
            }
        }
        asm volatile("cp.async.commit_group;");
    };

    const int lr = lane & 15;
    const int lc = (lane >> 4) * 16;

    load_chunk(0, 0);

    for (int c = 0; c < 20; c++) {
        const int st = c & 1;
        asm volatile("cp.async.wait_group 0;");
        __syncthreads();
        if (c < 19) load_chunk(c + 1, st ^ 1);

        const uint32_t s0 = base + st * 98304;
#pragma unroll
        for (int kk = 0; kk < 2; kk++) {
            const uint32_t sA = s0 + kk * 16384;
            const uint32_t sB = s0 + 65536 + kk * 8192;
#pragma unroll
            for (int ks = 0; ks < 4; ks++) {
                uint32_t ah[2][4], al[2][4];
#pragma unroll
                for (int mb = 0; mb < 2; mb++) {
                    const uint32_t ro = (mw * 32 + mb * 16 + lr) * 128 + ks * 32 + lc;
                    LDSM4(ah[mb], sA + SWZ(ro));
                    LDSM4(al[mb], sA + 32768 + SWZ(ro));
                }
                uint32_t bh2[2][4], bl2[2][4];
#pragma unroll
                for (int nb = 0; nb < 2; nb++) {
                    const uint32_t ro = (nw * 32 + nb * 16 + lr) * 128 + ks * 32 + lc;
                    LDSM4(bh2[nb], sB + SWZ(ro));
                    LDSM4(bl2[nb], sB + 16384 + SWZ(ro));
                }
#pragma unroll
                for (int mb = 0; mb < 2; mb++)
#pragma unroll
                    for (int nb = 0; nb < 2; nb++) {
                        MMA_BF16(acc[mb][nb * 2],     ah[mb], bh2[nb][0], bh2[nb][2]);
                        MMA_BF16(acc[mb][nb * 2 + 1], ah[mb], bh2[nb][1], bh2[nb][3]);
                    }
#pragma unroll
                for (int mb = 0; mb < 2; mb++)
#pragma unroll
                    for (int nb = 0; nb < 2; nb++) {
                        MMA_BF16(acc[mb][nb * 2],     ah[mb], bl2[nb][0], bl2[nb][2]);
                        MMA_BF16(acc[mb][nb * 2 + 1], ah[mb], bl2[nb][1], bl2[nb][3]);
                    }
#pragma unroll
                for (int mb = 0; mb < 2; mb++)
#pragma unroll
                    for (int nb = 0; nb < 2; nb++) {
                        MMA_BF16(acc[mb][nb * 2],     al[mb], bh2[nb][0], bh2[nb][2]);
                        MMA_BF16(acc[mb][nb * 2 + 1], al[mb], bh2[nb][1], bh2[nb][3]);
                    }
            }
        }
    }

    const int row0 = mt * 128 + mw * 32 + (lane >> 2);
    const int col0 = nt * 64 + nw * 32 + 2 * (lane & 3);

    if (nt < 40) {
#pragma unroll
        for (int mb = 0; mb < 2; mb++) {
#pragma unroll
            for (int n8 = 0; n8 < 4; n8++) {
                const int gc = col0 + n8 * 8;
                const float b0 = bias[gc], b1 = bias[gc + 1];
                const int r = row0 + mb * 16;
                float2 o0 = make_float2(acc[mb][n8][0] + b0, acc[mb][n8][1] + b1);
                float2 o1 = make_float2(acc[mb][n8][2] + b0, acc[mb][n8][3] + b1);
                *(float2*)&Qout[(size_t)r * 2560 + gc] = o0;
                *(float2*)&Qout[(size_t)(r + 8) * 2560 + gc] = o1;
            }
        }
    } else if (nt < 80) {
#pragma unroll
        for (int mb = 0; mb < 2; mb++) {
#pragma unroll
            for (int n8 = 0; n8 < 4; n8++) {
#pragma unroll
                for (int e = 0; e < 4; e++) {
                    const int gc = col0 + n8 * 8 + (e & 1);
                    const int r = row0 + mb * 16 + (e >> 1) * 8;
                    float val = acc[mb][n8][e] + bias[gc];
                    const int c2 = gc - 2560;
                    const int h = c2 / 80;
                    const int d = c2 - h * 80;
                    const int bb = r >> 10, key = r & 1023;
                    const size_t o = (size_t)(bb * 32 + h) * 90112 +
                                     (size_t)key * 88 + d;
                    __nv_bfloat16 hh = __float2bfloat16(val);
                    Kh[o] = hh;
                    Kl[o] = __float2bfloat16(val - __bfloat162float(hh));
                }
            }
        }
    } else {
#pragma unroll
        for (int mb = 0; mb < 2; mb++) {
#pragma unroll
            for (int n8 = 0; n8 < 4; n8++) {
#pragma unroll
                for (int e = 0; e < 4; e++) {
                    const int gc = col0 + n8 * 8 + (e & 1);
                    const int r = row0 + mb * 16 + (e >> 1) * 8;
                    float val = acc[mb][n8][e] + bias[gc];
                    const int c2 = gc - 5120;
                    const int h = c2 / 80;
                    const int d = c2 - h * 80;
                    const int bb = r >> 10, key = r & 1023;
                    const size_t o = (size_t)(bb * 32 + h) * 81920 +
                                     (size_t)d * 1024 + key;
                    Vh[o] = __float2half(val);
                }
            }
        }
    }
}

// ---------------------------------------------------------------------------
// GEMM2: fp16 2-term, CTA 128x64, K-chunk 128, 2-stage (64KB/stage).
// Stage: A[0,32K) Bh[32K,48K) Bl[48K,64K); sub-tile kk at +kk*16K / +kk*8K.
// ---------------------------------------------------------------------------
__global__ __launch_bounds__(256, 1) void gemm_proj_f16(
    const __half* __restrict__ Ah,
    const __half* __restrict__ Bh, const __half* __restrict__ Bl,
    const float* __restrict__ bias, float* __restrict__ C, int N) {
    extern __shared__ __align__(1024) char dsm[];
    const uint32_t base = smem_u32(dsm);

    const int tid = threadIdx.x;
    const int wid = tid >> 5, lane = tid & 31;
    const int mw = wid & 3;
    const int nw = wid >> 2;
    const int mt = blockIdx.y, nt = blockIdx.x;
    const int K = 2560;

    const int trow = tid >> 3;
    const int tkg = tid & 7;

    float acc[2][4][4];
#pragma unroll
    for (int a = 0; a < 2; a++)
#pragma unroll
        for (int b = 0; b < 4; b++)
#pragma unroll
            for (int c = 0; c < 4; c++) acc[a][b][c] = 0.0f;

    auto load_chunk = [&](int c, int st) {
        const uint32_t s0 = base + st * 65536;
#pragma unroll
        for (int kk = 0; kk < 2; kk++) {
            const int k0 = c * 128 + kk * 64;
#pragma unroll
            for (int j = 0; j < 4; j++) {
                const int row = j * 32 + trow;
                const uint32_t so = SWZ(row * 128 + tkg * 16) + kk * 16384;
                CP16(s0 + so, Ah + (size_t)(mt * 128 + row) * K + k0 + tkg * 8);
            }
#pragma unroll
            for (int j = 0; j < 2; j++) {
                const int row = j * 32 + trow;
                const uint32_t so = SWZ(row * 128 + tkg * 16) + kk * 8192;
                CP16(s0 + 32768 + so,
                     Bh + (size_t)(nt * 64 + row) * K + k0 + tkg * 8);
                CP16(s0 + 49152 + so,
                     Bl + (size_t)(nt * 64 + row) * K + k0 + tkg * 8);
            }
        }
        asm volatile("cp.async.commit_group;");
    };

    const int lr = lane & 15;
    const int lc = (lane >> 4) * 16;

    load_chunk(0, 0);

    for (int c = 0; c < 20; c++) {
        const int st = c & 1;
        asm volatile("cp.async.wait_group 0;");
        __syncthreads();
        if (c < 19) load_chunk(c + 1, st ^ 1);

        const uint32_t s0 = base + st * 65536;
#pragma unroll
        for (int kk = 0; kk < 2; kk++) {
            const uint32_t sA = s0 + kk * 16384;
            const uint32_t sB = s0 + 32768 + kk * 8192;
#pragma unroll
            for (int ks = 0; ks < 4; ks++) {
                uint32_t ah[2][4];
#pragma unroll
                for (int mb = 0; mb < 2; mb++) {
                    const uint32_t ro = (mw * 32 + mb * 16 + lr) * 128 + ks * 32 + lc;
                    LDSM4(ah[mb], sA + SWZ(ro));
                }
                uint32_t bh2[2][4], bl2[2][4];
#pragma unroll
                for (int nb = 0; nb < 2; nb++) {
                    const uint32_t ro = (nw * 32 + nb * 16 + lr) * 128 + ks * 32 + lc;
                    LDSM4(bh2[nb], sB + SWZ(ro));
                    LDSM4(bl2[nb], sB + 16384 + SWZ(ro));
                }
#pragma unroll
                for (int mb = 0; mb < 2; mb++)
#pragma unroll
                    for (int nb = 0; nb < 2; nb++) {
                        MMA_F16(acc[mb][nb * 2],     ah[mb], bh2[nb][0], bh2[nb][2]);
                        MMA_F16(acc[mb][nb * 2 + 1], ah[mb], bh2[nb][1], bh2[nb][3]);
                    }
#pragma unroll
                for (int mb = 0; mb < 2; mb++)
#pragma unroll
                    for (int nb = 0; nb < 2; nb++) {
                        MMA_F16(acc[mb][nb * 2],     ah[mb], bl2[nb][0], bl2[nb][2]);
                        MMA_F16(acc[mb][nb * 2 + 1], ah[mb], bl2[nb][1], bl2[nb][3]);
                    }
            }
        }
    }

    const int row0 = mt * 128 + mw * 32 + (lane >> 2);
    const int col0 = nt * 64 + nw * 32 + 2 * (lane & 3);
#pragma unroll
    for (int mb = 0; mb < 2; mb++) {
#pragma unroll
        for (int n8 = 0; n8 < 4; n8++) {
            const int gc = col0 + n8 * 8;
            const float b0 = bias[gc], b1 = bias[gc + 1];
            const int r = row0 + mb * 16;
            float2 o0 = make_float2(acc[mb][n8][0] + b0, acc[mb][n8][1] + b1);
            float2 o1 = make_float2(acc[mb][n8][2] + b0, acc[mb][n8][3] + b1);
            *(float2*)&C[(size_t)r * N + gc] = o0;
            *(float2*)&C[(size_t)(r + 8) * N + gc] = o1;
        }
    }
}

// ---------------------------------------------------------------------------
// attn_mma v6 (unchanged from R13): scores fp32 in regs; P fp16; V fp16.
// ---------------------------------------------------------------------------
#define AT_QH 0u
#define AT_QL 11264u
#define AT_K  22528u
#define AT_KSTG 45056u
#define AT_VSTG 21760u
#define AT_SMEM 112640

__global__ __launch_bounds__(256, 2) void attn_mma(
    const float* __restrict__ qsrc,
    const __nv_bfloat16* __restrict__ Kh, const __nv_bfloat16* __restrict__ Kl,
    const __half* __restrict__ Vh,
    const float* __restrict__ gm, const float* __restrict__ gp,
    const float* __restrict__ ga, const float* __restrict__ qp,
    const float* __restrict__ isr,
    __half* __restrict__ out_h) {
    extern __shared__ __align__(128) char smc[];
    __shared__ float coeff[240];
    __shared__ float pbuf[128];
    __shared__ float rsum[16];
    char* sm = smc;
    const uint32_t base = smem_u32(smc);

    const int tid = threadIdx.x;
    const int wid = tid >> 5, lane = tid & 31;
    const int lr = lane & 15, lc = (lane >> 4) << 4;
    const int rr = lane >> 2, cc = (lane & 3) * 2;
    const int bh = blockIdx.y, b = bh >> 5, h = bh & 31;
    const int q0 = blockIdx.x * 16;

    const __nv_bfloat16* KhB = Kh + (size_t)bh * 90112;
    const __nv_bfloat16* KlB = Kl + (size_t)bh * 90112;
    auto load_k = [&](int kt, int stg) {
        const uint32_t sb = base + AT_K + (uint32_t)stg * AT_KSTG;
#pragma unroll
        for (int j = 0; j < 11; j++) {
            int idx = tid + j * 256;
            int m = idx >= 1408;
            int rem = m ? idx - 1408 : idx;
            int row = rem / 11, ch = rem - row * 11;
            const __nv_bfloat16* g =
                (m ? KlB : KhB) + (size_t)(kt * 128 + row) * 88 + ch * 8;
            CP16(sb + m * 22528u + row * 176 + ch * 16, g);
        }
        asm volatile("cp.async.commit_group;");
    };

    load_k(0, 0);

    if (tid < 240) {
        int g = tid / 80, d = tid - g * 80;
        float r0 = gm[g * 4 + 0] + gm[g * 4 + 1];
        float r1 = gm[g * 4 + 2] + gm[g * 4 + 3];
        float ph = gp[g * 80 + d];
        coeff[tid] = (cosf(ph) * r0 + sinf(ph) * r1) * ga[g * 80 + d];
    }
    __syncthreads();

    const float scale = rsqrtf(80.0f);
    for (int idx = tid; idx < 1280; idx += 256) {
        int r = idx / 80, d = idx - r * 80;
        float v = qsrc[(size_t)(b * 1024 + q0 + r) * 2560 + h * 80 + d] * scale;
        float vv[4] = {v, v * coeff[d], v * coeff[80 + d], v * coeff[160 + d]};
#pragma unroll
        for (int g = 0; g < 4; g++) {
            uint32_t o = (g * 16 + r) * 176 + d * 2;
            __nv_bfloat16 hh = __float2bfloat16(vv[g]);
            *(__nv_bfloat16*)(sm + AT_QH + o) = hh;
            *(__nv_bfloat16*)(sm + AT_QL + o) =
                __float2bfloat16(vv[g] - __bfloat162float(hh));
        }
    }

    const float intf = isr[0] * (1.0f / 3.0f);
    float csf[64];

#pragma unroll
    for (int kt = 0; kt < 8; kt++) {
        const int stg = kt & 1;
        asm volatile("cp.async.wait_group 0;");
        __syncthreads();
        if (kt < 7) load_k(kt + 1, stg ^ 1);

        const uint32_t kbase = base + AT_K + (uint32_t)stg * AT_KSTG;
        float acc[4][2][4];
#pragma unroll
        for (int g = 0; g < 4; g++)
#pragma unroll
            for (int i = 0; i < 2; i++)
#pragma unroll
                for (int j = 0; j < 4; j++) acc[g][i][j] = 0.0f;

#pragma unroll
        for (int ks = 0; ks < 5; ks++) {
            uint32_t bH[4], bL[4];
            uint32_t rb = (wid * 16 + lr) * 176 + ks * 32 + lc;
            LDSM4(bH, kbase + rb);
            LDSM4(bL, kbase + 22528u + rb);
#pragma unroll
            for (int g = 0; g < 4; g++) {
                uint32_t aH[4], aL[4];
                uint32_t ro = (g * 16 + lr) * 176 + ks * 32 + lc;
                LDSM4(aH, base + AT_QH + ro);
                LDSM4(aL, base + AT_QL + ro);
                MMA_BF16(acc[g][0], aH, bH[0], bH[2]);
                MMA_BF16(acc[g][1], aH, bH[1], bH[3]);
                MMA_BF16(acc[g][0], aH, bL[0], bL[2]);
                MMA_BF16(acc[g][1], aH, bL[1], bL[3]);
                MMA_BF16(acc[g][0], aL, bH[0], bH[2]);
                MMA_BF16(acc[g][1], aL, bH[1], bH[3]);
            }
        }

#pragma unroll
        for (int n8 = 0; n8 < 2; n8++) {
#pragma unroll
            for (int j = 0; j < 4; j++) {
                float a0 = acc[1][n8][j], a1 = acc[2][n8][j], a2 = acc[3][n8][j];
                csf[kt * 8 + n8 * 4 + j] =
                    acc[0][n8][j] + (a0 * a1 + a0 * a2 + a1 * a2) * intf;
            }
        }
    }
    __syncthreads();

    const __half* VhB = Vh + (size_t)bh * 81920;
    auto load_v = [&](int kt, int stg) {
#pragma unroll
        for (int j = 0; j < 5; j++) {
            int idx = tid + j * 256;
            int dim = idx >> 4, ch = idx & 15;
            const __half* g = VhB + (size_t)dim * 1024 + kt * 128 + ch * 8;
            CP16(base + stg * AT_VSTG + dim * 272 + ch * 16, g);
        }
        asm volatile("cp.async.commit_group;");
    };
    load_v(0, 0);
    load_v(1, 1);

    float m0 = -1e30f, m1 = -1e30f;
#pragma unroll
    for (int i = 0; i < 16; i++) {
        m0 = fmaxf(m0, fmaxf(csf[i * 4 + 0], csf[i * 4 + 1]));
        m1 = fmaxf(m1, fmaxf(csf[i * 4 + 2], csf[i * 4 + 3]));
    }
#pragma unroll
    for (int off = 1; off <= 2; off <<= 1) {
        m0 = fmaxf(m0, __shfl_xor_sync(0xffffffffu, m0, off));
        m1 = fmaxf(m1, __shfl_xor_sync(0xffffffffu, m1, off));
    }
    if ((lane & 3) == 0) {
        pbuf[wid * 16 + rr] = m0;
        pbuf[wid * 16 + rr + 8] = m1;
    }
    __syncthreads();
    float M0 = -1e30f, M1 = -1e30f;
#pragma unroll
    for (int w = 0; w < 8; w++) {
        M0 = fmaxf(M0, pbuf[w * 16 + rr]);
        M1 = fmaxf(M1, pbuf[w * 16 + rr + 8]);
    }
    __syncthreads();

    uint32_t ps[32];
    float s0 = 0.0f, s1 = 0.0f;
#pragma unroll
    for (int i = 0; i < 16; i++) {
        float e0 = __expf(csf[i * 4 + 0] - M0);
        float e1 = __expf(csf[i * 4 + 1] - M0);
        float e2 = __expf(csf[i * 4 + 2] - M1);
        float e3 = __expf(csf[i * 4 + 3] - M1);
        s0 += e0 + e1;
        s1 += e2 + e3;
        ps[i * 2 + 0] = pack_h2(e0, e1);
        ps[i * 2 + 1] = pack_h2(e2, e3);
    }
#pragma unroll
    for (int off = 1; off <= 2; off <<= 1) {
        s0 += __shfl_xor_sync(0xffffffffu, s0, off);
        s1 += __shfl_xor_sync(0xffffffffu, s1, off);
    }
    if ((lane & 3) == 0) {
        pbuf[wid * 16 + rr] = s0;
        pbuf[wid * 16 + rr + 8] = s1;
    }
    __syncthreads();
    if (wid == 0 && lane < 16) {
        float S = 0.0f;
#pragma unroll
        for (int w = 0; w < 8; w++) S += pbuf[w * 16 + lane];
        rsum[lane] = S;
    }

    float acc3[10][4];
#pragma unroll
    for (int i = 0; i < 10; i++)
#pragma unroll
        for (int j = 0; j < 4; j++) acc3[i][j] = 0.0f;

#pragma unroll
    for (int kt = 0; kt < 8; kt++) {
        if (kt < 7) {
            asm volatile("cp.async.wait_group 1;");
        } else {
            asm volatile("cp.async.wait_group 0;");
        }
        __syncthreads();

        const uint32_t vb = base + (uint32_t)(kt & 1) * AT_VSTG;
        uint32_t pA[4] = {ps[kt * 4 + 0], ps[kt * 4 + 1],
                          ps[kt * 4 + 2], ps[kt * 4 + 3]};
#pragma unroll
        for (int nd = 0; nd < 5; nd++) {
            uint32_t vh[4];
            uint32_t rb = (nd * 16 + lr) * 272 + wid * 32 + lc;
            LDSM4(vh, vb + rb);
            MMA_F16(acc3[nd * 2],     pA, vh[0], vh[2]);
            MMA_F16(acc3[nd * 2 + 1], pA, vh[1], vh[3]);
        }
        __syncthreads();
        if (kt < 6) load_v(kt + 2, kt & 1);
    }

    float* red = (float*)sm;
    float* redw = red + wid * 1344;
#pragma unroll
    for (int j = 0; j < 10; j++) {
        int d = (j >> 1) * 16 + (j & 1) * 8 + cc;
        redw[rr * 84 + d]           = acc3[j][0];
        redw[rr * 84 + d + 1]       = acc3[j][1];
        redw[(rr + 8) * 84 + d]     = acc3[j][2];
        redw[(rr + 8) * 84 + d + 1] = acc3[j][3];
    }
    __syncthreads();

    const float cph = cosf(qp[h]);
    for (int idx = tid; idx < 1280; idx += 256) {
        int r = idx / 80, d = idx - r * 80;
        float s = 0.0f;
#pragma unroll
        for (int w = 0; w < 8; w++) s += red[w * 1344 + r * 84 + d];
        float o = s * cph / rsum[r];
        size_t go = (size_t)(b * 1024 + q0 + r) * 2560 + h * 80 + d;
        out_h[go] = __float2half(o);
    }
}

// ---------------------------------------------------------------------------
extern "C" void kernel_launch(void* const* d_in, const int* in_sizes, int n_in,
                              void* d_out, int out_size) {
    const float* hidden = (const float*)d_in[0];
    const float* Wqkv   = (const float*)d_in[1];
    const float* bqkv   = (const float*)d_in[2];
    const float* Wproj  = (const float*)d_in[3];
    const float* bproj  = (const float*)d_in[4];
    const float* gm     = (const float*)d_in[5];
    const float* gp     = (const float*)d_in[6];
    const float* ga     = (const float*)d_in[7];
    const float* qp     = (const float*)d_in[8];
    const float* isr    = (const float*)d_in[9];
    float* out = (float*)d_out;

    void *p_q, *p_hh, *p_hl, *p_wqh, *p_wql, *p_wph, *p_wpl, *p_at;
    void *p_kh, *p_kl, *p_vh;
    cudaGetSymbolAddress(&p_q, g_q);
    cudaGetSymbolAddress(&p_hh, g_hid_hi);
    cudaGetSymbolAddress(&p_hl, g_hid_lo);
    cudaGetSymbolAddress(&p_wqh, g_wqkvT_hi);
    cudaGetSymbolAddress(&p_wql, g_wqkvT_lo);
    cudaGetSymbolAddress(&p_wph, g_wprojT_hi);
    cudaGetSymbolAddress(&p_wpl, g_wprojT_lo);
    cudaGetSymbolAddress(&p_at, g_attn);
    cudaGetSymbolAddress(&p_kh, g_Khi);
    cudaGetSymbolAddress(&p_kl, g_Klo);
    cudaGetSymbolAddress(&p_vh, g_Vthi);

    const int QKV_SMEM = 2 * 98304;
    const int PROJ_SMEM = 2 * 65536;
    cudaFuncSetAttribute(gemm_qkv,
                         cudaFuncAttributeMaxDynamicSharedMemorySize, QKV_SMEM);
    cudaFuncSetAttribute(gemm_proj_f16,
                         cudaFuncAttributeMaxDynamicSharedMemorySize, PROJ_SMEM);
    cudaFuncSetAttribute(attn_mma,
                         cudaFuncAttributeMaxDynamicSharedMemorySize, AT_SMEM);

    // 1) input conversions (single launch)
    prep_inputs<<<dim3(240, 80, 3), dim3(32, 8)>>>(
        hidden, Wqkv, Wproj,
        (__nv_bfloat16*)p_hh, (__nv_bfloat16*)p_hl,
        (__nv_bfloat16*)p_wqh, (__nv_bfloat16*)p_wql,
        (__half*)p_wph, (__half*)p_wpl);

    // 2) fused qkv GEMM: q fp32, k bf16 hi/lo, v fp16
    gemm_qkv<<<dim3(120, 16), 256, QKV_SMEM>>>(
        (const __nv_bfloat16*)p_hh, (const __nv_bfloat16*)p_hl,
        (const __nv_bfloat16*)p_wqh, (const __nv_bfloat16*)p_wql,
        bqkv, (float*)p_q,
        (__nv_bfloat16*)p_kh, (__nv_bfloat16*)p_kl,
        (__half*)p_vh);

    // 3) register-resident tensor-core quantum attention -> fp16
    attn_mma<<<dim3(64, 64), 256, AT_SMEM>>>(
        (const float*)p_q,
        (const __nv_bfloat16*)p_kh, (const __nv_bfloat16*)p_kl,
        (const __half*)p_vh,
        gm, gp, ga, qp, isr,
        (__half*)p_at);

    // 4) out = attn @ Wproj + bproj (fp16 2-term)
    gemm_proj_f16<<<dim3(40, 16), 256, PROJ_SMEM>>>(
        (const __half*)p_at,
        (const __half*)p_wph, (const __half*)p_wpl,
        bproj, out, 2560);
}

// round 15
// speedup vs baseline: 1.9181x; 1.0108x over previous
#include <cuda_runtime.h>
#include <cuda_bf16.h>
#include <cuda_fp16.h>
#include <stdint.h>
#include <math.h>

// Problem constants: B=2, S=1024, E=2560, H=32, D=80, 3E=7680, BS=2048, K=2560

// ---------------- device scratch ----------------
__device__ float g_q[2048ull * 2560];
__device__ __nv_bfloat16 g_hid_hi[2048ull * 2560];
__device__ __nv_bfloat16 g_hid_lo[2048ull * 2560];
__device__ __nv_bfloat16 g_wqkvT_hi[7680ull * 2560];   // (N,K)
__device__ __nv_bfloat16 g_wqkvT_lo[7680ull * 2560];
__device__ __half g_wprojT_hi[2560ull * 2560];         // fp16 (N,K)
__device__ __half g_wprojT_lo[2560ull * 2560];
__device__ __half g_attn[2048ull * 2560];              // fp16 single
__device__ __nv_bfloat16 g_Khi[64ull * 1024 * 88];     // [bh][key][88]
__device__ __nv_bfloat16 g_Klo[64ull * 1024 * 88];
__device__ __half g_Vthi[64ull * 80 * 1024];           // [bh][dim][1024] fp16

__device__ __forceinline__ uint32_t smem_u32(const void* p) {
    uint32_t a;
    asm("{ .reg .u64 t; cvta.to.shared.u64 t, %1; cvt.u32.u64 %0, t; }"
        : "=r"(a) : "l"(p));
    return a;
}

#define SWZ(o) ((uint32_t)(o) ^ ((((uint32_t)(o)) >> 3) & 0x70u))

#define CP16(s, g) \
    asm volatile("cp.async.cg.shared.global [%0], [%1], 16;" :: "r"(s), "l"(g))

#define LDSM4(r, addr) \
    asm volatile("ldmatrix.sync.aligned.m8n8.x4.shared.b16 {%0,%1,%2,%3}, [%4];" \
                 : "=r"((r)[0]), "=r"((r)[1]), "=r"((r)[2]), "=r"((r)[3]) \
                 : "r"(addr))

#define MMA_BF16(acc, A, b0, b1) \
    asm volatile("mma.sync.aligned.m16n8k16.row.col.f32.bf16.bf16.f32 " \
                 "{%0,%1,%2,%3}, {%4,%5,%6,%7}, {%8,%9}, {%0,%1,%2,%3};" \
                 : "+f"((acc)[0]), "+f"((acc)[1]), "+f"((acc)[2]), "+f"((acc)[3]) \
                 : "r"((A)[0]), "r"((A)[1]), "r"((A)[2]), "r"((A)[3]), \
                   "r"(b0), "r"(b1))

#define MMA_F16(acc, A, b0, b1) \
    asm volatile("mma.sync.aligned.m16n8k16.row.col.f32.f16.f16.f32 " \
                 "{%0,%1,%2,%3}, {%4,%5,%6,%7}, {%8,%9}, {%0,%1,%2,%3};" \
                 : "+f"((acc)[0]), "+f"((acc)[1]), "+f"((acc)[2]), "+f"((acc)[3]) \
                 : "r"((A)[0]), "r"((A)[1]), "r"((A)[2]), "r"((A)[3]), \
                   "r"(b0), "r"(b1))

__device__ __forceinline__ uint32_t pack_h2(float a, float b) {
    __half2 h = __floats2half2_rn(a, b);
    return *(uint32_t*)&h;
}

// ---------------------------------------------------------------------------
// prep_inputs: z=0 transpose Wqkv -> bf16 hi/lo, z=1 transpose Wproj -> fp16
// hi/lo, z=2 hidden -> bf16 hi/lo. grid (240, 80, 3), block (32, 8).
// ---------------------------------------------------------------------------
__global__ void prep_inputs(const float* __restrict__ hid,
                            const float* __restrict__ Wq,
                            const float* __restrict__ Wp,
                            __nv_bfloat16* __restrict__ Hh,
                            __nv_bfloat16* __restrict__ Hl,
                            __nv_bfloat16* __restrict__ Tqh,
                            __nv_bfloat16* __restrict__ Tql,
                            __half* __restrict__ Tph,
                            __half* __restrict__ Tpl) {
    const int z = blockIdx.z;
    const int tx = threadIdx.x, ty = threadIdx.y;
    const int t = ty * 32 + tx;

    if (z == 2) {
        int bid = blockIdx.y * 240 + blockIdx.x;
        if (bid >= 5120) return;
        int i = bid * 256 + t;
        float4 v = ((const float4*)hid)[i];
        __nv_bfloat16 h0 = __float2bfloat16(v.x), h1 = __float2bfloat16(v.y);
        __nv_bfloat16 h2 = __float2bfloat16(v.z), h3 = __float2bfloat16(v.w);
        __nv_bfloat162 a, b;
        a.x = h0; a.y = h1; b.x = h2; b.y = h3;
        ((__nv_bfloat162*)Hh)[i * 2] = a;
        ((__nv_bfloat162*)Hh)[i * 2 + 1] = b;
        __nv_bfloat162 c, d;
        c.x = __float2bfloat16(v.x - __bfloat162float(h0));
        c.y = __float2bfloat16(v.y - __bfloat162float(h1));
        d.x = __float2bfloat16(v.z - __bfloat162float(h2));
        d.y = __float2bfloat16(v.w - __bfloat162float(h3));
        ((__nv_bfloat162*)Hl)[i * 2] = c;
        ((__nv_bfloat162*)Hl)[i * 2 + 1] = d;
        return;
    }

    __shared__ float tb[32][33];
    if (z == 1 && blockIdx.x >= 80) return;
    const float* W = z ? Wp : Wq;
    const int N = z ? 2560 : 7680;
    const int K = 2560;
    int n0 = blockIdx.x * 32, k0 = blockIdx.y * 32;
#pragma unroll
    for (int j = 0; j < 4; j++)
        tb[ty + j * 8][tx] = W[(size_t)(k0 + ty + j * 8) * N + n0 + tx];
    __syncthreads();
#pragma unroll
    for (int j = 0; j < 4; j++) {
        float v = tb[tx][ty + j * 8];
        size_t o = (size_t)(n0 + ty + j * 8) * K + k0 + tx;
        if (z == 0) {
            __nv_bfloat16 h = __float2bfloat16(v);
            Tqh[o] = h;
            Tql[o] = __float2bfloat16(v - __bfloat162float(h));
        } else {
            __half h = __float2half(v);
            Tph[o] = h;
            Tpl[o] = __float2half(v - __half2float(h));
        }
    }
}

// ---------------------------------------------------------------------------
// GEMM1 (fused): CTA 128x64, 256 threads, K-chunk 128 (2 x 64 sub-tiles),
// 2-stage cp.async (96KB/stage). Epilogue routes q/k/v.
// ---------------------------------------------------------------------------
__global__ __launch_bounds__(256, 1) void gemm_qkv(
    const __nv_bfloat16* __restrict__ Ah, const __nv_bfloat16* __restrict__ Al,
    const __nv_bfloat16* __restrict__ Bh, const __nv_bfloat16* __restrict__ Bl,
    const float* __restrict__ bias, float* __restrict__ Qout,
    __nv_bfloat16* __restrict__ Kh, __nv_bfloat16* __restrict__ Kl,
    __half* __restrict__ Vh) {
    extern __shared__ __align__(1024) char dsm[];
    const uint32_t base = smem_u32(dsm);

    const int tid = threadIdx.x;
    const int wid = tid >> 5, lane = tid & 31;
    const int mw = wid & 3;
    const int nw = wid >> 2;
    const int mt = blockIdx.y, nt = blockIdx.x;
    const int K = 2560;

    const int trow = tid >> 3;
    const int tkg = tid & 7;

    float acc[2][4][4];
#pragma unroll
    for (int a = 0; a < 2; a++)
#pragma unroll
        for (int b = 0; b < 4; b++)
#pragma unroll
            for (int c = 0; c < 4; c++) acc[a][b][c] = 0.0f;

    auto load_chunk = [&](int c, int st) {
        const uint32_t s0 = base + st * 98304;
#pragma unroll
        for (int kk = 0; kk < 2; kk++) {
            const int k0 = c * 128 + kk * 64;
#pragma unroll
            for (int j = 0; j < 4; j++) {
                const int row = j * 32 + trow;
                const uint32_t so = SWZ(row * 128 + tkg * 16) + kk * 16384;
                CP16(s0 + so, Ah + (size_t)(mt * 128 + row) * K + k0 + tkg * 8);
                CP16(s0 + 32768 + so,
                     Al + (size_t)(mt * 128 + row) * K + k0 + tkg * 8);
            }
#pragma unroll
            for (int j = 0; j < 2; j++) {
                const int row = j * 32 + trow;
                const uint32_t so = SWZ(row * 128 + tkg * 16) + kk * 8192;
                CP16(s0 + 65536 + so,
                     Bh + (size_t)(nt * 64 + row) * K + k0 + tkg * 8);
                CP16(s0 + 81920 + so,
                     Bl + (size_t)(nt * 64 + row) * K + k0 + tkg * 8);
            }
        }
        asm volatile("cp.async.commit_group;");
    };

    const int lr = lane & 15;
    const int lc = (lane >> 4) * 16;

    load_chunk(0, 0);

    for (int c = 0; c < 20; c++) {
        const int st = c & 1;
        asm volatile("cp.async.wait_group 0;");
        __syncthreads();
        if (c < 19) load_chunk(c + 1, st ^ 1);

        const uint32_t s0 = base + st * 98304;
#pragma unroll
        for (int kk = 0; kk < 2; kk++) {
            const uint32_t sA = s0 + kk * 16384;
            const uint32_t sB = s0 + 65536 + kk * 8192;
#pragma unroll
            for (int ks = 0; ks < 4; ks++) {
                uint32_t ah[2][4], al[2][4];
#pragma unroll
                for (int mb = 0; mb < 2; mb++) {
                    const uint32_t ro = (mw * 32 + mb * 16 + lr) * 128 + ks * 32 + lc;
                    LDSM4(ah[mb], sA + SWZ(ro));
                    LDSM4(al[mb], sA + 32768 + SWZ(ro));
                }
                uint32_t bh2[2][4], bl2[2][4];
#pragma unroll
                for (int nb = 0; nb < 2; nb++) {
                    const uint32_t ro = (nw * 32 + nb * 16 + lr) * 128 + ks * 32 + lc;
                    LDSM4(bh2[nb], sB + SWZ(ro));
                    LDSM4(bl2[nb], sB + 16384 + SWZ(ro));
                }
#pragma unroll
                for (int mb = 0; mb < 2; mb++)
#pragma unroll
                    for (int nb = 0; nb < 2; nb++) {
                        MMA_BF16(acc[mb][nb * 2],     ah[mb], bh2[nb][0], bh2[nb][2]);
                        MMA_BF16(acc[mb][nb * 2 + 1], ah[mb], bh2[nb][1], bh2[nb][3]);
                    }
#pragma unroll
                for (int mb = 0; mb < 2; mb++)
#pragma unroll
                    for (int nb = 0; nb < 2; nb++) {
                        MMA_BF16(acc[mb][nb * 2],     ah[mb], bl2[nb][0], bl2[nb][2]);
                        MMA_BF16(acc[mb][nb * 2 + 1], ah[mb], bl2[nb][1], bl2[nb][3]);
                    }
#pragma unroll
                for (int mb = 0; mb < 2; mb++)
#pragma unroll
                    for (int nb = 0; nb < 2; nb++) {
                        MMA_BF16(acc[mb][nb * 2],     al[mb], bh2[nb][0], bh2[nb][2]);
                        MMA_BF16(acc[mb][nb * 2 + 1], al[mb], bh2[nb][1], bh2[nb][3]);
                    }
            }
        }
    }

    const int row0 = mt * 128 + mw * 32 + (lane >> 2);
    const int col0 = nt * 64 + nw * 32 + 2 * (lane & 3);

    if (nt < 40) {
#pragma unroll
        for (int mb = 0; mb < 2; mb++) {
#pragma unroll
            for (int n8 = 0; n8 < 4; n8++) {
                const int gc = col0 + n8 * 8;
                const float b0 = bias[gc], b1 = bias[gc + 1];
                const int r = row0 + mb * 16;
                float2 o0 = make_float2(acc[mb][n8][0] + b0, acc[mb][n8][1] + b1);
                float2 o1 = make_float2(acc[mb][n8][2] + b0, acc[mb][n8][3] + b1);
                *(float2*)&Qout[(size_t)r * 2560 + gc] = o0;
                *(float2*)&Qout[(size_t)(r + 8) * 2560 + gc] = o1;
            }
        }
    } else if (nt < 80) {
#pragma unroll
        for (int mb = 0; mb < 2; mb++) {
#pragma unroll
            for (int n8 = 0; n8 < 4; n8++) {
#pragma unroll
                for (int e = 0; e < 4; e++) {
                    const int gc = col0 + n8 * 8 + (e & 1);
                    const int r = row0 + mb * 16 + (e >> 1) * 8;
                    float val = acc[mb][n8][e] + bias[gc];
                    const int c2 = gc - 2560;
                    const int h = c2 / 80;
                    const int d = c2 - h * 80;
                    const int bb = r >> 10, key = r & 1023;
                    const size_t o = (size_t)(bb * 32 + h) * 90112 +
                                     (size_t)key * 88 + d;
                    __nv_bfloat16 hh = __float2bfloat16(val);
                    Kh[o] = hh;
                    Kl[o] = __float2bfloat16(val - __bfloat162float(hh));
                }
            }
        }
    } else {
#pragma unroll
        for (int mb = 0; mb < 2; mb++) {
#pragma unroll
            for (int n8 = 0; n8 < 4; n8++) {
#pragma unroll
                for (int e = 0; e < 4; e++) {
                    const int gc = col0 + n8 * 8 + (e & 1);
                    const int r = row0 + mb * 16 + (e >> 1) * 8;
                    float val = acc[mb][n8][e] + bias[gc];
                    const int c2 = gc - 5120;
                    const int h = c2 / 80;
                    const int d = c2 - h * 80;
                    const int bb = r >> 10, key = r & 1023;
                    const size_t o = (size_t)(bb * 32 + h) * 81920 +
                                     (size_t)d * 1024 + key;
                    Vh[o] = __float2half(val);
                }
            }
        }
    }
}

// ---------------------------------------------------------------------------
// GEMM2: fp16 2-term, CTA 128x64, K-chunk 64, 3-stage (32KB/stage) -> 96KB
// smem, 2 CTAs/SM. grid (40, 16).
// ---------------------------------------------------------------------------
__global__ __launch_bounds__(256, 2) void gemm_proj_f16(
    const __half* __restrict__ Ah,
    const __half* __restrict__ Bh, const __half* __restrict__ Bl,
    const float* __restrict__ bias, float* __restrict__ C, int N) {
    extern __shared__ __align__(1024) char dsm[];
    const uint32_t base = smem_u32(dsm);

    const int tid = threadIdx.x;
    const int wid = tid >> 5, lane = tid & 31;
    const int mw = wid & 3;
    const int nw = wid >> 2;
    const int mt = blockIdx.y, nt = blockIdx.x;
    const int K = 2560;

    const int trow = tid >> 3;
    const int tkg = tid & 7;

    float acc[2][4][4];
#pragma unroll
    for (int a = 0; a < 2; a++)
#pragma unroll
        for (int b = 0; b < 4; b++)
#pragma unroll
            for (int c = 0; c < 4; c++) acc[a][b][c] = 0.0f;

    auto load_chunk = [&](int c, int st) {
        const int k0 = c * 64;
        const uint32_t s0 = base + st * 32768;
#pragma unroll
        for (int j = 0; j < 4; j++) {
            const int row = j * 32 + trow;
            const uint32_t so = SWZ(row * 128 + tkg * 16);
            CP16(s0 + so, Ah + (size_t)(mt * 128 + row) * K + k0 + tkg * 8);
        }
#pragma unroll
        for (int j = 0; j < 2; j++) {
            const int row = j * 32 + trow;
            const uint32_t so = SWZ(row * 128 + tkg * 16);
            CP16(s0 + 16384 + so, Bh + (size_t)(nt * 64 + row) * K + k0 + tkg * 8);
            CP16(s0 + 24576 + so, Bl + (size_t)(nt * 64 + row) * K + k0 + tkg * 8);
        }
        asm volatile("cp.async.commit_group;");
    };

    const int lr = lane & 15;
    const int lc = (lane >> 4) * 16;

    load_chunk(0, 0);
    load_chunk(1, 1);

    int st = 0;
    for (int c = 0; c < 40; c++) {
        if (c < 39) {
            asm volatile("cp.async.wait_group 1;");
        } else {
            asm volatile("cp.async.wait_group 0;");
        }
        __syncthreads();
        if (c + 2 < 40) {
            int st2 = st + 2;
            if (st2 >= 3) st2 -= 3;
            load_chunk(c + 2, st2);
        }

        const uint32_t sA = base + st * 32768;
#pragma unroll
        for (int ks = 0; ks < 4; ks++) {
            uint32_t ah[2][4];
#pragma unroll
            for (int mb = 0; mb < 2; mb++) {
                const uint32_t ro = (mw * 32 + mb * 16 + lr) * 128 + ks * 32 + lc;
                LDSM4(ah[mb], sA + SWZ(ro));
            }
            uint32_t bh2[2][4], bl2[2][4];
#pragma unroll
            for (int nb = 0; nb < 2; nb++) {
                const uint32_t ro = (nw * 32 + nb * 16 + lr) * 128 + ks * 32 + lc;
                LDSM4(bh2[nb], sA + 16384 + SWZ(ro));
                LDSM4(bl2[nb], sA + 24576 + SWZ(ro));
            }
#pragma unroll
            for (int mb = 0; mb < 2; mb++)
#pragma unroll
                for (int nb = 0; nb < 2; nb++) {
                    MMA_F16(acc[mb][nb * 2],     ah[mb], bh2[nb][0], bh2[nb][2]);
                    MMA_F16(acc[mb][nb * 2 + 1], ah[mb], bh2[nb][1], bh2[nb][3]);
                }
#pragma unroll
            for (int mb = 0; mb < 2; mb++)
#pragma unroll
                for (int nb = 0; nb < 2; nb++) {
                    MMA_F16(acc[mb][nb * 2],     ah[mb], bl2[nb][0], bl2[nb][2]);
                    MMA_F16(acc[mb][nb * 2 + 1], ah[mb], bl2[nb][1], bl2[nb][3]);
                }
        }
        st++;
        if (st >= 3) st -= 3;
    }

    const int row0 = mt * 128 + mw * 32 + (lane >> 2);
    const int col0 = nt * 64 + nw * 32 + 2 * (lane & 3);
#pragma unroll
    for (int mb = 0; mb < 2; mb++) {
#pragma unroll
        for (int n8 = 0; n8 < 4; n8++) {
            const int gc = col0 + n8 * 8;
            const float b0 = bias[gc], b1 = bias[gc + 1];
            const int r = row0 + mb * 16;
            float2 o0 = make_float2(acc[mb][n8][0] + b0, acc[mb][n8][1] + b1);
            float2 o1 = make_float2(acc[mb][n8][2] + b0, acc[mb][n8][3] + b1);
            *(float2*)&C[(size_t)r * N + gc] = o0;
            *(float2*)&C[(size_t)(r + 8) * N + gc] = o1;
        }
    }
}

// ---------------------------------------------------------------------------
// attn_mma v6 (unchanged): scores fp32 in regs; P fp16; V fp16.
// ---------------------------------------------------------------------------
#define AT_QH 0u
#define AT_QL 11264u
#define AT_K  22528u
#define AT_KSTG 45056u
#define AT_VSTG 21760u
#define AT_SMEM 112640

__global__ __launch_bounds__(256, 2) void attn_mma(
    const float* __restrict__ qsrc,
    const __nv_bfloat16* __restrict__ Kh, const __nv_bfloat16* __restrict__ Kl,
    const __half* __restrict__ Vh,
    const float* __restrict__ gm, const float* __restrict__ gp,
    const float* __restrict__ ga, const float* __restrict__ qp,
    const float* __restrict__ isr,
    __half* __restrict__ out_h) {
    extern __shared__ __align__(128) char smc[];
    __shared__ float coeff[240];
    __shared__ float pbuf[128];
    __shared__ float rsum[16];
    char* sm = smc;
    const uint32_t base = smem_u32(smc);

    const int tid = threadIdx.x;
    const int wid = tid >> 5, lane = tid & 31;
    const int lr = lane & 15, lc = (lane >> 4) << 4;
    const int rr = lane >> 2, cc = (lane & 3) * 2;
    const int bh = blockIdx.y, b = bh >> 5, h = bh & 31;
    const int q0 = blockIdx.x * 16;

    const __nv_bfloat16* KhB = Kh + (size_t)bh * 90112;
    const __nv_bfloat16* KlB = Kl + (size_t)bh * 90112;
    auto load_k = [&](int kt, int stg) {
        const uint32_t sb = base + AT_K + (uint32_t)stg * AT_KSTG;
#pragma unroll
        for (int j = 0; j < 11; j++) {
            int idx = tid + j * 256;
            int m = idx >= 1408;
            int rem = m ? idx - 1408 : idx;
            int row = rem / 11, ch = rem - row * 11;
            const __nv_bfloat16* g =
                (m ? KlB : KhB) + (size_t)(kt * 128 + row) * 88 + ch * 8;
            CP16(sb + m * 22528u + row * 176 + ch * 16, g);
        }
        asm volatile("cp.async.commit_group;");
    };

    load_k(0, 0);

    if (tid < 240) {
        int g = tid / 80, d = tid - g * 80;
        float r0 = gm[g * 4 + 0] + gm[g * 4 + 1];
        float r1 = gm[g * 4 + 2] + gm[g * 4 + 3];
        float ph = gp[g * 80 + d];
        coeff[tid] = (cosf(ph) * r0 + sinf(ph) * r1) * ga[g * 80 + d];
    }
    __syncthreads();

    const float scale = rsqrtf(80.0f);
    for (int idx = tid; idx < 1280; idx += 256) {
        int r = idx / 80, d = idx - r * 80;
        float v = qsrc[(size_t)(b * 1024 + q0 + r) * 2560 + h * 80 + d] * scale;
        float vv[4] = {v, v * coeff[d], v * coeff[80 + d], v * coeff[160 + d]};
#pragma unroll
        for (int g = 0; g < 4; g++) {
            uint32_t o = (g * 16 + r) * 176 + d * 2;
            __nv_bfloat16 hh = __float2bfloat16(vv[g]);
            *(__nv_bfloat16*)(sm + AT_QH + o) = hh;
            *(__nv_bfloat16*)(sm + AT_QL + o) =
                __float2bfloat16(vv[g] - __bfloat162float(hh));
        }
    }

    const float intf = isr[0] * (1.0f / 3.0f);
    float csf[64];

#pragma unroll
    for (int kt = 0; kt < 8; kt++) {
        const int stg = kt & 1;
        asm volatile("cp.async.wait_group 0;");
        __syncthreads();
        if (kt < 7) load_k(kt + 1, stg ^ 1);

        const uint32_t kbase = base + AT_K + (uint32_t)stg * AT_KSTG;
        float acc[4][2][4];
#pragma unroll
        for (int g = 0; g < 4; g++)
#pragma unroll
            for (int i = 0; i < 2; i++)
#pragma unroll
                for (int j = 0; j < 4; j++) acc[g][i][j] = 0.0f;

#pragma unroll
        for (int ks = 0; ks < 5; ks++) {
            uint32_t bH[4], bL[4];
            uint32_t rb = (wid * 16 + lr) * 176 + ks * 32 + lc;
            LDSM4(bH, kbase + rb);
            LDSM4(bL, kbase + 22528u + rb);
#pragma unroll
            for (int g = 0; g < 4; g++) {
                uint32_t aH[4], aL[4];
                uint32_t ro = (g * 16 + lr) * 176 + ks * 32 + lc;
                LDSM4(aH, base + AT_QH + ro);
                LDSM4(aL, base + AT_QL + ro);
                MMA_BF16(acc[g][0], aH, bH[0], bH[2]);
                MMA_BF16(acc[g][1], aH, bH[1], bH[3]);
                MMA_BF16(acc[g][0], aH, bL[0], bL[2]);
                MMA_BF16(acc[g][1], aH, bL[1], bL[3]);
                MMA_BF16(acc[g][0], aL, bH[0], bH[2]);
                MMA_BF16(acc[g][1], aL, bH[1], bH[3]);
            }
        }

#pragma unroll
        for (int n8 = 0; n8 < 2; n8++) {
#pragma unroll
            for (int j = 0; j < 4; j++) {
                float a0 = acc[1][n8][j], a1 = acc[2][n8][j], a2 = acc[3][n8][j];
                csf[kt * 8 + n8 * 4 + j] =
                    acc[0][n8][j] + (a0 * a1 + a0 * a2 + a1 * a2) * intf;
            }
        }
    }
    __syncthreads();

    const __half* VhB = Vh + (size_t)bh * 81920;
    auto load_v = [&](int kt, int stg) {
#pragma unroll
        for (int j = 0; j < 5; j++) {
            int idx = tid + j * 256;
            int dim = idx >> 4, ch = idx & 15;
            const __half* g = VhB + (size_t)dim * 1024 + kt * 128 + ch * 8;
            CP16(base + stg * AT_VSTG + dim * 272 + ch * 16, g);
        }
        asm volatile("cp.async.commit_group;");
    };
    load_v(0, 0);
    load_v(1, 1);

    float m0 = -1e30f, m1 = -1e30f;
#pragma unroll
    for (int i = 0; i < 16; i++) {
        m0 = fmaxf(m0, fmaxf(csf[i * 4 + 0], csf[i * 4 + 1]));
        m1 = fmaxf(m1, fmaxf(csf[i * 4 + 2], csf[i * 4 + 3]));
    }
#pragma unroll
    for (int off = 1; off <= 2; off <<= 1) {
        m0 = fmaxf(m0, __shfl_xor_sync(0xffffffffu, m0, off));
        m1 = fmaxf(m1, __shfl_xor_sync(0xffffffffu, m1, off));
    }
    if ((lane & 3) == 0) {
        pbuf[wid * 16 + rr] = m0;
        pbuf[wid * 16 + rr + 8] = m1;
    }
    __syncthreads();
    float M0 = -1e30f, M1 = -1e30f;
#pragma unroll
    for (int w = 0; w < 8; w++) {
        M0 = fmaxf(M0, pbuf[w * 16 + rr]);
        M1 = fmaxf(M1, pbuf[w * 16 + rr + 8]);
    }
    __syncthreads();

    uint32_t ps[32];
    float s0 = 0.0f, s1 = 0.0f;
#pragma unroll
    for (int i = 0; i < 16; i++) {
        float e0 = __expf(csf[i * 4 + 0] - M0);
        float e1 = __expf(csf[i * 4 + 1] - M0);
        float e2 = __expf(csf[i * 4 + 2] - M1);
        float e3 = __expf(csf[i * 4 + 3] - M1);
        s0 += e0 + e1;
        s1 += e2 + e3;
        ps[i * 2 + 0] = pack_h2(e0, e1);
        ps[i * 2 + 1] = pack_h2(e2, e3);
    }
#pragma unroll
    for (int off = 1; off <= 2; off <<= 1) {
        s0 += __shfl_xor_sync(0xffffffffu, s0, off);
        s1 += __shfl_xor_sync(0xffffffffu, s1, off);
    }
    if ((lane & 3) == 0) {
        pbuf[wid * 16 + rr] = s0;
        pbuf[wid * 16 + rr + 8] = s1;
    }
    __syncthreads();
    if (wid == 0 && lane < 16) {
        float S = 0.0f;
#pragma unroll
        for (int w = 0; w < 8; w++) S += pbuf[w * 16 + lane];
        rsum[lane] = S;
    }

    float acc3[10][4];
#pragma unroll
    for (int i = 0; i < 10; i++)
#pragma unroll
        for (int j = 0; j < 4; j++) acc3[i][j] = 0.0f;

#pragma unroll
    for (int kt = 0; kt < 8; kt++) {
        if (kt < 7) {
            asm volatile("cp.async.wait_group 1;");
        } else {
            asm volatile("cp.async.wait_group 0;");
        }
        __syncthreads();

        const uint32_t vb = base + (uint32_t)(kt & 1) * AT_VSTG;
        uint32_t pA[4] = {ps[kt * 4 + 0], ps[kt * 4 + 1],
                          ps[kt * 4 + 2], ps[kt * 4 + 3]};
#pragma unroll
        for (int nd = 0; nd < 5; nd++) {
            uint32_t vh[4];
            uint32_t rb = (nd * 16 + lr) * 272 + wid * 32 + lc;
            LDSM4(vh, vb + rb);
            MMA_F16(acc3[nd * 2],     pA, vh[0], vh[2]);
            MMA_F16(acc3[nd * 2 + 1], pA, vh[1], vh[3]);
        }
        __syncthreads();
        if (kt < 6) load_v(kt + 2, kt & 1);
    }

    float* red = (float*)sm;
    float* redw = red + wid * 1344;
#pragma unroll
    for (int j = 0; j < 10; j++) {
        int d = (j >> 1) * 16 + (j & 1) * 8 + cc;
        redw[rr * 84 + d]           = acc3[j][0];
        redw[rr * 84 + d + 1]       = acc3[j][1];
        redw[(rr + 8) * 84 + d]     = acc3[j][2];
        redw[(rr + 8) * 84 + d + 1] = acc3[j][3];
    }
    __syncthreads();

    const float cph = cosf(qp[h]);
    for (int idx = tid; idx < 1280; idx += 256) {
        int r = idx / 80, d = idx - r * 80;
        float s = 0.0f;
#pragma unroll
        for (int w = 0; w < 8; w++) s += red[w * 1344 + r * 84 + d];
        float o = s * cph / rsum[r];
        size_t go = (size_t)(b * 1024 + q0 + r) * 2560 + h * 80 + d;
        out_h[go] = __float2half(o);
    }
}

// ---------------------------------------------------------------------------
extern "C" void kernel_launch(void* const* d_in, const int* in_sizes, int n_in,
                              void* d_out, int out_size) {
    const float* hidden = (const float*)d_in[0];
    const float* Wqkv   = (const float*)d_in[1];
    const float* bqkv   = (const float*)d_in[2];
    const float* Wproj  = (const float*)d_in[3];
    const float* bproj  = (const float*)d_in[4];
    const float* gm     = (const float*)d_in[5];
    const float* gp     = (const float*)d_in[6];
    const float* ga     = (const float*)d_in[7];
    const float* qp     = (const float*)d_in[8];
    const float* isr    = (const float*)d_in[9];
    float* out = (float*)d_out;

    void *p_q, *p_hh, *p_hl, *p_wqh, *p_wql, *p_wph, *p_wpl, *p_at;
    void *p_kh, *p_kl, *p_vh;
    cudaGetSymbolAddress(&p_q, g_q);
    cudaGetSymbolAddress(&p_hh, g_hid_hi);
    cudaGetSymbolAddress(&p_hl, g_hid_lo);
    cudaGetSymbolAddress(&p_wqh, g_wqkvT_hi);
    cudaGetSymbolAddress(&p_wql, g_wqkvT_lo);
    cudaGetSymbolAddress(&p_wph, g_wprojT_hi);
    cudaGetSymbolAddress(&p_wpl, g_wprojT_lo);
    cudaGetSymbolAddress(&p_at, g_attn);
    cudaGetSymbolAddress(&p_kh, g_Khi);
    cudaGetSymbolAddress(&p_kl, g_Klo);
    cudaGetSymbolAddress(&p_vh, g_Vthi);

    const int QKV_SMEM = 2 * 98304;
    const int PROJ_SMEM = 3 * 32768;
    cudaFuncSetAttribute(gemm_qkv,
                         cudaFuncAttributeMaxDynamicSharedMemorySize, QKV_SMEM);
    cudaFuncSetAttribute(gemm_proj_f16,
                         cudaFuncAttributeMaxDynamicSharedMemorySize, PROJ_SMEM);
    cudaFuncSetAttribute(attn_mma,
                         cudaFuncAttributeMaxDynamicSharedMemorySize, AT_SMEM);

    // 1) input conversions (single launch)
    prep_inputs<<<dim3(240, 80, 3), dim3(32, 8)>>>(
        hidden, Wqkv, Wproj,
        (__nv_bfloat16*)p_hh, (__nv_bfloat16*)p_hl,
        (__nv_bfloat16*)p_wqh, (__nv_bfloat16*)p_wql,
        (__half*)p_wph, (__half*)p_wpl);

    // 2) fused qkv GEMM: q fp32, k bf16 hi/lo, v fp16
    gemm_qkv<<<dim3(120, 16), 256, QKV_SMEM>>>(
        (const __nv_bfloat16*)p_hh, (const __nv_bfloat16*)p_hl,
        (const __nv_bfloat16*)p_wqh, (const __nv_bfloat16*)p_wql,
        bqkv, (float*)p_q,
        (__nv_bfloat16*)p_kh, (__nv_bfloat16*)p_kl,
        (__half*)p_vh);

    // 3) register-resident tensor-core quantum attention -> fp16
    attn_mma<<<dim3(64, 64), 256, AT_SMEM>>>(
        (const float*)p_q,
        (const __nv_bfloat16*)p_kh, (const __nv_bfloat16*)p_kl,
        (const __half*)p_vh,
        gm, gp, ga, qp, isr,
        (__half*)p_at);

    // 4) out = attn @ Wproj + bproj (fp16 2-term, 2 CTAs/SM)
    gemm_proj_f16<<<dim3(40, 16), 256, PROJ_SMEM>>>(
        (const __half*)p_at,
        (const __half*)p_wph, (const __half*)p_wpl,
        bproj, out, 2560);
}

// round 16
// speedup vs baseline: 2.0428x; 1.0650x over previous
#include <cuda_runtime.h>
#include <cuda_bf16.h>
#include <cuda_fp16.h>
#include <stdint.h>
#include <math.h>

// Problem constants: B=2, S=1024, E=2560, H=32, D=80, 3E=7680, BS=2048, K=2560

// ---------------- device scratch ----------------
__device__ float g_q[2048ull * 2560];
__device__ __nv_bfloat16 g_hid_hi[2048ull * 2560];
__device__ __nv_bfloat16 g_hid_lo[2048ull * 2560];
__device__ __nv_bfloat16 g_wqkvT_hi[7680ull * 2560];   // (N,K)
__device__ __nv_bfloat16 g_wqkvT_lo[7680ull * 2560];
__device__ __half g_wprojT_hi[2560ull * 2560];         // fp16 (N,K)
__device__ __half g_wprojT_lo[2560ull * 2560];
__device__ __half g_attn[2048ull * 2560];              // fp16 single
__device__ __nv_bfloat16 g_Khi[64ull * 1024 * 88];     // [bh][key][88]
__device__ __nv_bfloat16 g_Klo[64ull * 1024 * 88];
__device__ __half g_Vthi[64ull * 80 * 1024];           // [bh][dim][1024] fp16

__device__ __forceinline__ uint32_t smem_u32(const void* p) {
    uint32_t a;
    asm("{ .reg .u64 t; cvta.to.shared.u64 t, %1; cvt.u32.u64 %0, t; }"
        : "=r"(a) : "l"(p));
    return a;
}

#define SWZ(o) ((uint32_t)(o) ^ ((((uint32_t)(o)) >> 3) & 0x70u))

#define CP16(s, g) \
    asm volatile("cp.async.cg.shared.global [%0], [%1], 16;" :: "r"(s), "l"(g))

#define LDSM4(r, addr) \
    asm volatile("ldmatrix.sync.aligned.m8n8.x4.shared.b16 {%0,%1,%2,%3}, [%4];" \
                 : "=r"((r)[0]), "=r"((r)[1]), "=r"((r)[2]), "=r"((r)[3]) \
                 : "r"(addr))

#define MMA_BF16(acc, A, b0, b1) \
    asm volatile("mma.sync.aligned.m16n8k16.row.col.f32.bf16.bf16.f32 " \
                 "{%0,%1,%2,%3}, {%4,%5,%6,%7}, {%8,%9}, {%0,%1,%2,%3};" \
                 : "+f"((acc)[0]), "+f"((acc)[1]), "+f"((acc)[2]), "+f"((acc)[3]) \
                 : "r"((A)[0]), "r"((A)[1]), "r"((A)[2]), "r"((A)[3]), \
                   "r"(b0), "r"(b1))

#define MMA_F16(acc, A, b0, b1) \
    asm volatile("mma.sync.aligned.m16n8k16.row.col.f32.f16.f16.f32 " \
                 "{%0,%1,%2,%3}, {%4,%5,%6,%7}, {%8,%9}, {%0,%1,%2,%3};" \
                 : "+f"((acc)[0]), "+f"((acc)[1]), "+f"((acc)[2]), "+f"((acc)[3]) \
                 : "r"((A)[0]), "r"((A)[1]), "r"((A)[2]), "r"((A)[3]), \
                   "r"(b0), "r"(b1))

__device__ __forceinline__ uint32_t pack_h2(float a, float b) {
    __half2 h = __floats2half2_rn(a, b);
    return *(uint32_t*)&h;
}

// ---------------------------------------------------------------------------
// prep_inputs: z=0 transpose Wqkv -> bf16 hi/lo, z=1 transpose Wproj -> fp16
// hi/lo, z=2 hidden -> bf16 hi/lo. grid (240, 80, 3), block (32, 8).
// ---------------------------------------------------------------------------
__global__ void prep_inputs(const float* __restrict__ hid,
                            const float* __restrict__ Wq,
                            const float* __restrict__ Wp,
                            __nv_bfloat16* __restrict__ Hh,
                            __nv_bfloat16* __restrict__ Hl,
                            __nv_bfloat16* __restrict__ Tqh,
                            __nv_bfloat16* __restrict__ Tql,
                            __half* __restrict__ Tph,
                            __half* __restrict__ Tpl) {
    const int z = blockIdx.z;
    const int tx = threadIdx.x, ty = threadIdx.y;
    const int t = ty * 32 + tx;

    if (z == 2) {
        int bid = blockIdx.y * 240 + blockIdx.x;
        if (bid >= 5120) return;
        int i = bid * 256 + t;
        float4 v = ((const float4*)hid)[i];
        __nv_bfloat16 h0 = __float2bfloat16(v.x), h1 = __float2bfloat16(v.y);
        __nv_bfloat16 h2 = __float2bfloat16(v.z), h3 = __float2bfloat16(v.w);
        __nv_bfloat162 a, b;
        a.x = h0; a.y = h1; b.x = h2; b.y = h3;
        ((__nv_bfloat162*)Hh)[i * 2] = a;
        ((__nv_bfloat162*)Hh)[i * 2 + 1] = b;
        __nv_bfloat162 c, d;
        c.x = __float2bfloat16(v.x - __bfloat162float(h0));
        c.y = __float2bfloat16(v.y - __bfloat162float(h1));
        d.x = __float2bfloat16(v.z - __bfloat162float(h2));
        d.y = __float2bfloat16(v.w - __bfloat162float(h3));
        ((__nv_bfloat162*)Hl)[i * 2] = c;
        ((__nv_bfloat162*)Hl)[i * 2 + 1] = d;
        return;
    }

    __shared__ float tb[32][33];
    if (z == 1 && blockIdx.x >= 80) return;
    const float* W = z ? Wp : Wq;
    const int N = z ? 2560 : 7680;
    const int K = 2560;
    int n0 = blockIdx.x * 32, k0 = blockIdx.y * 32;
#pragma unroll
    for (int j = 0; j < 4; j++)
        tb[ty + j * 8][tx] = W[(size_t)(k0 + ty + j * 8) * N + n0 + tx];
    __syncthreads();
#pragma unroll
    for (int j = 0; j < 4; j++) {
        float v = tb[tx][ty + j * 8];
        size_t o = (size_t)(n0 + ty + j * 8) * K + k0 + tx;
        if (z == 0) {
            __nv_bfloat16 h = __float2bfloat16(v);
            Tqh[o] = h;
            Tql[o] = __float2bfloat16(v - __bfloat162float(h));
        } else {
            __half h = __float2half(v);
            Tph[o] = h;
            Tpl[o] = __float2half(v - __half2float(h));
        }
    }
}

// ---------------------------------------------------------------------------
// GEMM1 (fused): CTA 128x64, 256 threads, K-chunk 64, 2-stage cp.async
// (48KB/stage -> 96KB total -> 2 CTAs/SM). Epilogue routes q/k/v.
// ---------------------------------------------------------------------------
__global__ __launch_bounds__(256, 2) void gemm_qkv(
    const __nv_bfloat16* __restrict__ Ah, const __nv_bfloat16* __restrict__ Al,
    const __nv_bfloat16* __restrict__ Bh, const __nv_bfloat16* __restrict__ Bl,
    const float* __restrict__ bias, float* __restrict__ Qout,
    __nv_bfloat16* __restrict__ Kh, __nv_bfloat16* __restrict__ Kl,
    __half* __restrict__ Vh) {
    extern __shared__ __align__(1024) char dsm[];
    const uint32_t base = smem_u32(dsm);

    const int tid = threadIdx.x;
    const int wid = tid >> 5, lane = tid & 31;
    const int mw = wid & 3;
    const int nw = wid >> 2;
    const int mt = blockIdx.y, nt = blockIdx.x;
    const int K = 2560;

    const int trow = tid >> 3;
    const int tkg = tid & 7;

    float acc[2][4][4];
#pragma unroll
    for (int a = 0; a < 2; a++)
#pragma unroll
        for (int b = 0; b < 4; b++)
#pragma unroll
            for (int c = 0; c < 4; c++) acc[a][b][c] = 0.0f;

    auto load_chunk = [&](int c, int st) {
        const int k0 = c * 64;
        const uint32_t s0 = base + st * 49152;
#pragma unroll
        for (int j = 0; j < 4; j++) {
            const int row = j * 32 + trow;
            const uint32_t so = SWZ(row * 128 + tkg * 16);
            CP16(s0 + so, Ah + (size_t)(mt * 128 + row) * K + k0 + tkg * 8);
            CP16(s0 + 16384 + so, Al + (size_t)(mt * 128 + row) * K + k0 + tkg * 8);
        }
#pragma unroll
        for (int j = 0; j < 2; j++) {
            const int row = j * 32 + trow;
            const uint32_t so = SWZ(row * 128 + tkg * 16);
            CP16(s0 + 32768 + so, Bh + (size_t)(nt * 64 + row) * K + k0 + tkg * 8);
            CP16(s0 + 40960 + so, Bl + (size_t)(nt * 64 + row) * K + k0 + tkg * 8);
        }
        asm volatile("cp.async.commit_group;");
    };

    const int lr = lane & 15;
    const int lc = (lane >> 4) * 16;

    load_chunk(0, 0);

    for (int c = 0; c < 40; c++) {
        const int st = c & 1;
        asm volatile("cp.async.wait_group 0;");
        __syncthreads();
        if (c < 39) load_chunk(c + 1, st ^ 1);

        const uint32_t sA = base + st * 49152;
#pragma unroll
        for (int ks = 0; ks < 4; ks++) {
            uint32_t ah[2][4], al[2][4];
#pragma unroll
            for (int mb = 0; mb < 2; mb++) {
                const uint32_t ro = (mw * 32 + mb * 16 + lr) * 128 + ks * 32 + lc;
                LDSM4(ah[mb], sA + SWZ(ro));
                LDSM4(al[mb], sA + 16384 + SWZ(ro));
            }
            uint32_t bh2[2][4], bl2[2][4];
#pragma unroll
            for (int nb = 0; nb < 2; nb++) {
                const uint32_t ro = (nw * 32 + nb * 16 + lr) * 128 + ks * 32 + lc;
                LDSM4(bh2[nb], sA + 32768 + SWZ(ro));
                LDSM4(bl2[nb], sA + 40960 + SWZ(ro));
            }
#pragma unroll
            for (int mb = 0; mb < 2; mb++)
#pragma unroll
                for (int nb = 0; nb < 2; nb++) {
                    MMA_BF16(acc[mb][nb * 2],     ah[mb], bh2[nb][0], bh2[nb][2]);
                    MMA_BF16(acc[mb][nb * 2 + 1], ah[mb], bh2[nb][1], bh2[nb][3]);
                }
#pragma unroll
            for (int mb = 0; mb < 2; mb++)
#pragma unroll
                for (int nb = 0; nb < 2; nb++) {
                    MMA_BF16(acc[mb][nb * 2],     ah[mb], bl2[nb][0], bl2[nb][2]);
                    MMA_BF16(acc[mb][nb * 2 + 1], ah[mb], bl2[nb][1], bl2[nb][3]);
                }
#pragma unroll
            for (int mb = 0; mb < 2; mb++)
#pragma unroll
                for (int nb = 0; nb < 2; nb++) {
                    MMA_BF16(acc[mb][nb * 2],     al[mb], bh2[nb][0], bh2[nb][2]);
                    MMA_BF16(acc[mb][nb * 2 + 1], al[mb], bh2[nb][1], bh2[nb][3]);
                }
        }
    }

    const int row0 = mt * 128 + mw * 32 + (lane >> 2);
    const int col0 = nt * 64 + nw * 32 + 2 * (lane & 3);

    if (nt < 40) {
#pragma unroll
        for (int mb = 0; mb < 2; mb++) {
#pragma unroll
            for (int n8 = 0; n8 < 4; n8++) {
                const int gc = col0 + n8 * 8;
                const float b0 = bias[gc], b1 = bias[gc + 1];
                const int r = row0 + mb * 16;
                float2 o0 = make_float2(acc[mb][n8][0] + b0, acc[mb][n8][1] + b1);
                float2 o1 = make_float2(acc[mb][n8][2] + b0, acc[mb][n8][3] + b1);
                *(float2*)&Qout[(size_t)r * 2560 + gc] = o0;
                *(float2*)&Qout[(size_t)(r + 8) * 2560 + gc] = o1;
            }
        }
    } else if (nt < 80) {
#pragma unroll
        for (int mb = 0; mb < 2; mb++) {
#pragma unroll
            for (int n8 = 0; n8 < 4; n8++) {
#pragma unroll
                for (int e = 0; e < 4; e++) {
                    const int gc = col0 + n8 * 8 + (e & 1);
                    const int r = row0 + mb * 16 + (e >> 1) * 8;
                    float val = acc[mb][n8][e] + bias[gc];
                    const int c2 = gc - 2560;
                    const int h = c2 / 80;
                    const int d = c2 - h * 80;
                    const int bb = r >> 10, key = r & 1023;
                    const size_t o = (size_t)(bb * 32 + h) * 90112 +
                                     (size_t)key * 88 + d;
                    __nv_bfloat16 hh = __float2bfloat16(val);
                    Kh[o] = hh;
                    Kl[o] = __float2bfloat16(val - __bfloat162float(hh));
                }
            }
        }
    } else {
#pragma unroll
        for (int mb = 0; mb < 2; mb++) {
#pragma unroll
            for (int n8 = 0; n8 < 4; n8++) {
#pragma unroll
                for (int e = 0; e < 4; e++) {
                    const int gc = col0 + n8 * 8 + (e & 1);
                    const int r = row0 + mb * 16 + (e >> 1) * 8;
                    float val = acc[mb][n8][e] + bias[gc];
                    const int c2 = gc - 5120;
                    const int h = c2 / 80;
                    const int d = c2 - h * 80;
                    const int bb = r >> 10, key = r & 1023;
                    const size_t o = (size_t)(bb * 32 + h) * 81920 +
                                     (size_t)d * 1024 + key;
                    Vh[o] = __float2half(val);
                }
            }
        }
    }
}

// ---------------------------------------------------------------------------
// GEMM2: fp16 2-term, CTA 128x64, K-chunk 64, 3-stage (32KB/stage) -> 96KB
// smem, 2 CTAs/SM. grid (40, 16).
// ---------------------------------------------------------------------------
__global__ __launch_bounds__(256, 2) void gemm_proj_f16(
    const __half* __restrict__ Ah,
    const __half* __restrict__ Bh, const __half* __restrict__ Bl,
    const float* __restrict__ bias, float* __restrict__ C, int N) {
    extern __shared__ __align__(1024) char dsm[];
    const uint32_t base = smem_u32(dsm);

    const int tid = threadIdx.x;
    const int wid = tid >> 5, lane = tid & 31;
    const int mw = wid & 3;
    const int nw = wid >> 2;
    const int mt = blockIdx.y, nt = blockIdx.x;
    const int K = 2560;

    const int trow = tid >> 3;
    const int tkg = tid & 7;

    float acc[2][4][4];
#pragma unroll
    for (int a = 0; a < 2; a++)
#pragma unroll
        for (int b = 0; b < 4; b++)
#pragma unroll
            for (int c = 0; c < 4; c++) acc[a][b][c] = 0.0f;

    auto load_chunk = [&](int c, int st) {
        const int k0 = c * 64;
        const uint32_t s0 = base + st * 32768;
#pragma unroll
        for (int j = 0; j < 4; j++) {
            const int row = j * 32 + trow;
            const uint32_t so = SWZ(row * 128 + tkg * 16);
            CP16(s0 + so, Ah + (size_t)(mt * 128 + row) * K + k0 + tkg * 8);
        }
#pragma unroll
        for (int j = 0; j < 2; j++) {
            const int row = j * 32 + trow;
            const uint32_t so = SWZ(row * 128 + tkg * 16);
            CP16(s0 + 16384 + so, Bh + (size_t)(nt * 64 + row) * K + k0 + tkg * 8);
            CP16(s0 + 24576 + so, Bl + (size_t)(nt * 64 + row) * K + k0 + tkg * 8);
        }
        asm volatile("cp.async.commit_group;");
    };

    const int lr = lane & 15;
    const int lc = (lane >> 4) * 16;

    load_chunk(0, 0);
    load_chunk(1, 1);

    int st = 0;
    for (int c = 0; c < 40; c++) {
        if (c < 39) {
            asm volatile("cp.async.wait_group 1;");
        } else {
            asm volatile("cp.async.wait_group 0;");
        }
        __syncthreads();
        if (c + 2 < 40) {
            int st2 = st + 2;
            if (st2 >= 3) st2 -= 3;
            load_chunk(c + 2, st2);
        }

        const uint32_t sA = base + st * 32768;
#pragma unroll
        for (int ks = 0; ks < 4; ks++) {
            uint32_t ah[2][4];
#pragma unroll
            for (int mb = 0; mb < 2; mb++) {
                const uint32_t ro = (mw * 32 + mb * 16 + lr) * 128 + ks * 32 + lc;
                LDSM4(ah[mb], sA + SWZ(ro));
            }
            uint32_t bh2[2][4], bl2[2][4];
#pragma unroll
            for (int nb = 0; nb < 2; nb++) {
                const uint32_t ro = (nw * 32 + nb * 16 + lr) * 128 + ks * 32 + lc;
                LDSM4(bh2[nb], sA + 16384 + SWZ(ro));
                LDSM4(bl2[nb], sA + 24576 + SWZ(ro));
            }
#pragma unroll
            for (int mb = 0; mb < 2; mb++)
#pragma unroll
                for (int nb = 0; nb < 2; nb++) {
                    MMA_F16(acc[mb][nb * 2],     ah[mb], bh2[nb][0], bh2[nb][2]);
                    MMA_F16(acc[mb][nb * 2 + 1], ah[mb], bh2[nb][1], bh2[nb][3]);
                }
#pragma unroll
            for (int mb = 0; mb < 2; mb++)
#pragma unroll
                for (int nb = 0; nb < 2; nb++) {
                    MMA_F16(acc[mb][nb * 2],     ah[mb], bl2[nb][0], bl2[nb][2]);
                    MMA_F16(acc[mb][nb * 2 + 1], ah[mb], bl2[nb][1], bl2[nb][3]);
                }
        }
        st++;
        if (st >= 3) st -= 3;
    }

    const int row0 = mt * 128 + mw * 32 + (lane >> 2);
    const int col0 = nt * 64 + nw * 32 + 2 * (lane & 3);
#pragma unroll
    for (int mb = 0; mb < 2; mb++) {
#pragma unroll
        for (int n8 = 0; n8 < 4; n8++) {
            const int gc = col0 + n8 * 8;
            const float b0 = bias[gc], b1 = bias[gc + 1];
            const int r = row0 + mb * 16;
            float2 o0 = make_float2(acc[mb][n8][0] + b0, acc[mb][n8][1] + b1);
            float2 o1 = make_float2(acc[mb][n8][2] + b0, acc[mb][n8][3] + b1);
            *(float2*)&C[(size_t)r * N + gc] = o0;
            *(float2*)&C[(size_t)(r + 8) * N + gc] = o1;
        }
    }
}

// ---------------------------------------------------------------------------
// attn_mma v6 (unchanged): scores fp32 in regs; P fp16; V fp16.
// ---------------------------------------------------------------------------
#define AT_QH 0u
#define AT_QL 11264u
#define AT_K  22528u
#define AT_KSTG 45056u
#define AT_VSTG 21760u
#define AT_SMEM 112640

__global__ __launch_bounds__(256, 2) void attn_mma(
    const float* __restrict__ qsrc,
    const __nv_bfloat16* __restrict__ Kh, const __nv_bfloat16* __restrict__ Kl,
    const __half* __restrict__ Vh,
    const float* __restrict__ gm, const float* __restrict__ gp,
    const float* __restrict__ ga, const float* __restrict__ qp,
    const float* __restrict__ isr,
    __half* __restrict__ out_h) {
    extern __shared__ __align__(128) char smc[];
    __shared__ float coeff[240];
    __shared__ float pbuf[128];
    __shared__ float rsum[16];
    char* sm = smc;
    const uint32_t base = smem_u32(smc);

    const int tid = threadIdx.x;
    const int wid = tid >> 5, lane = tid & 31;
    const int lr = lane & 15, lc = (lane >> 4) << 4;
    const int rr = lane >> 2, cc = (lane & 3) * 2;
    const int bh = blockIdx.y, b = bh >> 5, h = bh & 31;
    const int q0 = blockIdx.x * 16;

    const __nv_bfloat16* KhB = Kh + (size_t)bh * 90112;
    const __nv_bfloat16* KlB = Kl + (size_t)bh * 90112;
    auto load_k = [&](int kt, int stg) {
        const uint32_t sb = base + AT_K + (uint32_t)stg * AT_KSTG;
#pragma unroll
        for (int j = 0; j < 11; j++) {
            int idx = tid + j * 256;
            int m = idx >= 1408;
            int rem = m ? idx - 1408 : idx;
            int row = rem / 11, ch = rem - row * 11;
            const __nv_bfloat16* g =
                (m ? KlB : KhB) + (size_t)(kt * 128 + row) * 88 + ch * 8;
            CP16(sb + m * 22528u + row * 176 + ch * 16, g);
        }
        asm volatile("cp.async.commit_group;");
    };

    load_k(0, 0);

    if (tid < 240) {
        int g = tid / 80, d = tid - g * 80;
        float r0 = gm[g * 4 + 0] + gm[g * 4 + 1];
        float r1 = gm[g * 4 + 2] + gm[g * 4 + 3];
        float ph = gp[g * 80 + d];
        coeff[tid] = (cosf(ph) * r0 + sinf(ph) * r1) * ga[g * 80 + d];
    }
    __syncthreads();

    const float scale = rsqrtf(80.0f);
    for (int idx = tid; idx < 1280; idx += 256) {
        int r = idx / 80, d = idx - r * 80;
        float v = qsrc[(size_t)(b * 1024 + q0 + r) * 2560 + h * 80 + d] * scale;
        float vv[4] = {v, v * coeff[d], v * coeff[80 + d], v * coeff[160 + d]};
#pragma unroll
        for (int g = 0; g < 4; g++) {
            uint32_t o = (g * 16 + r) * 176 + d * 2;
            __nv_bfloat16 hh = __float2bfloat16(vv[g]);
            *(__nv_bfloat16*)(sm + AT_QH + o) = hh;
            *(__nv_bfloat16*)(sm + AT_QL + o) =
                __float2bfloat16(vv[g] - __bfloat162float(hh));
        }
    }

    const float intf = isr[0] * (1.0f / 3.0f);
    float csf[64];

#pragma unroll
    for (int kt = 0; kt < 8; kt++) {
        const int stg = kt & 1;
        asm volatile("cp.async.wait_group 0;");
        __syncthreads();
        if (kt < 7) load_k(kt + 1, stg ^ 1);

        const uint32_t kbase = base + AT_K + (uint32_t)stg * AT_KSTG;
        float acc[4][2][4];
#pragma unroll
        for (int g = 0; g < 4; g++)
#pragma unroll
            for (int i = 0; i < 2; i++)
#pragma unroll
                for (int j = 0; j < 4; j++) acc[g][i][j] = 0.0f;

#pragma unroll
        for (int ks = 0; ks < 5; ks++) {
            uint32_t bH[4], bL[4];
            uint32_t rb = (wid * 16 + lr) * 176 + ks * 32 + lc;
            LDSM4(bH, kbase + rb);
            LDSM4(bL, kbase + 22528u + rb);
#pragma unroll
            for (int g = 0; g < 4; g++) {
                uint32_t aH[4], aL[4];
                uint32_t ro = (g * 16 + lr) * 176 + ks * 32 + lc;
                LDSM4(aH, base + AT_QH + ro);
                LDSM4(aL, base + AT_QL + ro);
                MMA_BF16(acc[g][0], aH, bH[0], bH[2]);
                MMA_BF16(acc[g][1], aH, bH[1], bH[3]);
                MMA_BF16(acc[g][0], aH, bL[0], bL[2]);
                MMA_BF16(acc[g][1], aH, bL[1], bL[3]);
                MMA_BF16(acc[g][0], aL, bH[0], bH[2]);
                MMA_BF16(acc[g][1], aL, bH[1], bH[3]);
            }
        }

#pragma unroll
        for (int n8 = 0; n8 < 2; n8++) {
#pragma unroll
            for (int j = 0; j < 4; j++) {
                float a0 = acc[1][n8][j], a1 = acc[2][n8][j], a2 = acc[3][n8][j];
                csf[kt * 8 + n8 * 4 + j] =
                    acc[0][n8][j] + (a0 * a1 + a0 * a2 + a1 * a2) * intf;
            }
        }
    }
    __syncthreads();

    const __half* VhB = Vh + (size_t)bh * 81920;
    auto load_v = [&](int kt, int stg) {
#pragma unroll
        for (int j = 0; j < 5; j++) {
            int idx = tid + j * 256;
            int dim = idx >> 4, ch = idx & 15;
            const __half* g = VhB + (size_t)dim * 1024 + kt * 128 + ch * 8;
            CP16(base + stg * AT_VSTG + dim * 272 + ch * 16, g);
        }
        asm volatile("cp.async.commit_group;");
    };
    load_v(0, 0);
    load_v(1, 1);

    float m0 = -1e30f, m1 = -1e30f;
#pragma unroll
    for (int i = 0; i < 16; i++) {
        m0 = fmaxf(m0, fmaxf(csf[i * 4 + 0], csf[i * 4 + 1]));
        m1 = fmaxf(m1, fmaxf(csf[i * 4 + 2], csf[i * 4 + 3]));
    }
#pragma unroll
    for (int off = 1; off <= 2; off <<= 1) {
        m0 = fmaxf(m0, __shfl_xor_sync(0xffffffffu, m0, off));
        m1 = fmaxf(m1, __shfl_xor_sync(0xffffffffu, m1, off));
    }
    if ((lane & 3) == 0) {
        pbuf[wid * 16 + rr] = m0;
        pbuf[wid * 16 + rr + 8] = m1;
    }
    __syncthreads();
    float M0 = -1e30f, M1 = -1e30f;
#pragma unroll
    for (int w = 0; w < 8; w++) {
        M0 = fmaxf(M0, pbuf[w * 16 + rr]);
        M1 = fmaxf(M1, pbuf[w * 16 + rr + 8]);
    }
    __syncthreads();

    uint32_t ps[32];
    float s0 = 0.0f, s1 = 0.0f;
#pragma unroll
    for (int i = 0; i < 16; i++) {
        float e0 = __expf(csf[i * 4 + 0] - M0);
        float e1 = __expf(csf[i * 4 + 1] - M0);
        float e2 = __expf(csf[i * 4 + 2] - M1);
        float e3 = __expf(csf[i * 4 + 3] - M1);
        s0 += e0 + e1;
        s1 += e2 + e3;
        ps[i * 2 + 0] = pack_h2(e0, e1);
        ps[i * 2 + 1] = pack_h2(e2, e3);
    }
#pragma unroll
    for (int off = 1; off <= 2; off <<= 1) {
        s0 += __shfl_xor_sync(0xffffffffu, s0, off);
        s1 += __shfl_xor_sync(0xffffffffu, s1, off);
    }
    if ((lane & 3) == 0) {
        pbuf[wid * 16 + rr] = s0;
        pbuf[wid * 16 + rr + 8] = s1;
    }
    __syncthreads();
    if (wid == 0 && lane < 16) {
        float S = 0.0f;
#pragma unroll
        for (int w = 0; w < 8; w++) S += pbuf[w * 16 + lane];
        rsum[lane] = S;
    }

    float acc3[10][4];
#pragma unroll
    for (int i = 0; i < 10; i++)
#pragma unroll
        for (int j = 0; j < 4; j++) acc3[i][j] = 0.0f;

#pragma unroll
    for (int kt = 0; kt < 8; kt++) {
        if (kt < 7) {
            asm volatile("cp.async.wait_group 1;");
        } else {
            asm volatile("cp.async.wait_group 0;");
        }
        __syncthreads();

        const uint32_t vb = base + (uint32_t)(kt & 1) * AT_VSTG;
        uint32_t pA[4] = {ps[kt * 4 + 0], ps[kt * 4 + 1],
                          ps[kt * 4 + 2], ps[kt * 4 + 3]};
#pragma unroll
        for (int nd = 0; nd < 5; nd++) {
            uint32_t vh[4];
            uint32_t rb = (nd * 16 + lr) * 272 + wid * 32 + lc;
            LDSM4(vh, vb + rb);
            MMA_F16(acc3[nd * 2],     pA, vh[0], vh[2]);
            MMA_F16(acc3[nd * 2 + 1], pA, vh[1], vh[3]);
        }
        __syncthreads();
        if (kt < 6) load_v(kt + 2, kt & 1);
    }

    float* red = (float*)sm;
    float* redw = red + wid * 1344;
#pragma unroll
    for (int j = 0; j < 10; j++) {
        int d = (j >> 1) * 16 + (j & 1) * 8 + cc;
        redw[rr * 84 + d]           = acc3[j][0];
        redw[rr * 84 + d + 1]       = acc3[j][1];
        redw[(rr + 8) * 84 + d]     = acc3[j][2];
        redw[(rr + 8) * 84 + d + 1] = acc3[j][3];
    }
    __syncthreads();

    const float cph = cosf(qp[h]);
    for (int idx = tid; idx < 1280; idx += 256) {
        int r = idx / 80, d = idx - r * 80;
        float s = 0.0f;
#pragma unroll
        for (int w = 0; w < 8; w++) s += red[w * 1344 + r * 84 + d];
        float o = s * cph / rsum[r];
        size_t go = (size_t)(b * 1024 + q0 + r) * 2560 + h * 80 + d;
        out_h[go] = __float2half(o);
    }
}

// ---------------------------------------------------------------------------
extern "C" void kernel_launch(void* const* d_in, const int* in_sizes, int n_in,
                              void* d_out, int out_size) {
    const float* hidden = (const float*)d_in[0];
    const float* Wqkv   = (const float*)d_in[1];
    const float* bqkv   = (const float*)d_in[2];
    const float* Wproj  = (const float*)d_in[3];
    const float* bproj  = (const float*)d_in[4];
    const float* gm     = (const float*)d_in[5];
    const float* gp     = (const float*)d_in[6];
    const float* ga     = (const float*)d_in[7];
    const float* qp     = (const float*)d_in[8];
    const float* isr    = (const float*)d_in[9];
    float* out = (float*)d_out;

    void *p_q, *p_hh, *p_hl, *p_wqh, *p_wql, *p_wph, *p_wpl, *p_at;
    void *p_kh, *p_kl, *p_vh;
    cudaGetSymbolAddress(&p_q, g_q);
    cudaGetSymbolAddress(&p_hh, g_hid_hi);
    cudaGetSymbolAddress(&p_hl, g_hid_lo);
    cudaGetSymbolAddress(&p_wqh, g_wqkvT_hi);
    cudaGetSymbolAddress(&p_wql, g_wqkvT_lo);
    cudaGetSymbolAddress(&p_wph, g_wprojT_hi);
    cudaGetSymbolAddress(&p_wpl, g_wprojT_lo);
    cudaGetSymbolAddress(&p_at, g_attn);
    cudaGetSymbolAddress(&p_kh, g_Khi);
    cudaGetSymbolAddress(&p_kl, g_Klo);
    cudaGetSymbolAddress(&p_vh, g_Vthi);

    const int QKV_SMEM = 2 * 49152;
    const int PROJ_SMEM = 3 * 32768;
    cudaFuncSetAttribute(gemm_qkv,
                         cudaFuncAttributeMaxDynamicSharedMemorySize, QKV_SMEM);
    cudaFuncSetAttribute(gemm_proj_f16,
                         cudaFuncAttributeMaxDynamicSharedMemorySize, PROJ_SMEM);
    cudaFuncSetAttribute(attn_mma,
                         cudaFuncAttributeMaxDynamicSharedMemorySize, AT_SMEM);

    // 1) input conversions (single launch)
    prep_inputs<<<dim3(240, 80, 3), dim3(32, 8)>>>(
        hidden, Wqkv, Wproj,
        (__nv_bfloat16*)p_hh, (__nv_bfloat16*)p_hl,
        (__nv_bfloat16*)p_wqh, (__nv_bfloat16*)p_wql,
        (__half*)p_wph, (__half*)p_wpl);

    // 2) fused qkv GEMM (2 CTAs/SM): q fp32, k bf16 hi/lo, v fp16
    gemm_qkv<<<dim3(120, 16), 256, QKV_SMEM>>>(
        (const __nv_bfloat16*)p_hh, (const __nv_bfloat16*)p_hl,
        (const __nv_bfloat16*)p_wqh, (const __nv_bfloat16*)p_wql,
        bqkv, (float*)p_q,
        (__nv_bfloat16*)p_kh, (__nv_bfloat16*)p_kl,
        (__half*)p_vh);

    // 3) register-resident tensor-core quantum attention -> fp16
    attn_mma<<<dim3(64, 64), 256, AT_SMEM>>>(
        (const float*)p_q,
        (const __nv_bfloat16*)p_kh, (const __nv_bfloat16*)p_kl,
        (const __half*)p_vh,
        gm, gp, ga, qp, isr,
        (__half*)p_at);

    // 4) out = attn @ Wproj + bproj (fp16 2-term, 2 CTAs/SM)
    gemm_proj_f16<<<dim3(40, 16), 256, PROJ_SMEM>>>(
        (const __half*)p_at,
        (const __half*)p_wph, (const __half*)p_wpl,
        bproj, out, 2560);
}

// round 17
// speedup vs baseline: 2.0690x; 1.0128x over previous
#include <cuda_runtime.h>
#include <cuda_bf16.h>
#include <cuda_fp16.h>
#include <stdint.h>
#include <math.h>

// Problem constants: B=2, S=1024, E=2560, H=32, D=80, 3E=7680, BS=2048, K=2560

// ---------------- device scratch ----------------
__device__ float g_q[2048ull * 2560];
__device__ __nv_bfloat16 g_hid_hi[2048ull * 2560];
__device__ __nv_bfloat16 g_hid_lo[2048ull * 2560];
__device__ __nv_bfloat16 g_wqkvT_hi[7680ull * 2560];   // (N,K)
__device__ __nv_bfloat16 g_wqkvT_lo[7680ull * 2560];
__device__ __half g_wprojT_hi[2560ull * 2560];         // fp16 (N,K)
__device__ __half g_wprojT_lo[2560ull * 2560];
__device__ __half g_attn[2048ull * 2560];              // fp16 single
__device__ __nv_bfloat16 g_Khi[64ull * 1024 * 88];     // [bh][key][88]
__device__ __nv_bfloat16 g_Klo[64ull * 1024 * 88];
__device__ __half g_Vthi[64ull * 80 * 1024];           // [bh][dim][1024] fp16

__device__ __forceinline__ uint32_t smem_u32(const void* p) {
    uint32_t a;
    asm("{ .reg .u64 t; cvta.to.shared.u64 t, %1; cvt.u32.u64 %0, t; }"
        : "=r"(a) : "l"(p));
    return a;
}

#define SWZ(o) ((uint32_t)(o) ^ ((((uint32_t)(o)) >> 3) & 0x70u))

#define CP16(s, g) \
    asm volatile("cp.async.cg.shared.global [%0], [%1], 16;" :: "r"(s), "l"(g))

#define LDSM4(r, addr) \
    asm volatile("ldmatrix.sync.aligned.m8n8.x4.shared.b16 {%0,%1,%2,%3}, [%4];" \
                 : "=r"((r)[0]), "=r"((r)[1]), "=r"((r)[2]), "=r"((r)[3]) \
                 : "r"(addr))

#define MMA_BF16(acc, A, b0, b1) \
    asm volatile("mma.sync.aligned.m16n8k16.row.col.f32.bf16.bf16.f32 " \
                 "{%0,%1,%2,%3}, {%4,%5,%6,%7}, {%8,%9}, {%0,%1,%2,%3};" \
                 : "+f"((acc)[0]), "+f"((acc)[1]), "+f"((acc)[2]), "+f"((acc)[3]) \
                 : "r"((A)[0]), "r"((A)[1]), "r"((A)[2]), "r"((A)[3]), \
                   "r"(b0), "r"(b1))

#define MMA_F16(acc, A, b0, b1) \
    asm volatile("mma.sync.aligned.m16n8k16.row.col.f32.f16.f16.f32 " \
                 "{%0,%1,%2,%3}, {%4,%5,%6,%7}, {%8,%9}, {%0,%1,%2,%3};" \
                 : "+f"((acc)[0]), "+f"((acc)[1]), "+f"((acc)[2]), "+f"((acc)[3]) \
                 : "r"((A)[0]), "r"((A)[1]), "r"((A)[2]), "r"((A)[3]), \
                   "r"(b0), "r"(b1))

__device__ __forceinline__ uint32_t pack_h2(float a, float b) {
    __half2 h = __floats2half2_rn(a, b);
    return *(uint32_t*)&h;
}

// ---------------------------------------------------------------------------
// prep_inputs: z=0 transpose Wqkv -> bf16 hi/lo, z=1 transpose Wproj -> fp16
// hi/lo, z=2 hidden -> bf16 hi/lo. grid (240, 80, 3), block (32, 8).
// ---------------------------------------------------------------------------
__global__ void prep_inputs(const float* __restrict__ hid,
                            const float* __restrict__ Wq,
                            const float* __restrict__ Wp,
                            __nv_bfloat16* __restrict__ Hh,
                            __nv_bfloat16* __restrict__ Hl,
                            __nv_bfloat16* __restrict__ Tqh,
                            __nv_bfloat16* __restrict__ Tql,
                            __half* __restrict__ Tph,
                            __half* __restrict__ Tpl) {
    const int z = blockIdx.z;
    const int tx = threadIdx.x, ty = threadIdx.y;
    const int t = ty * 32 + tx;

    if (z == 2) {
        int bid = blockIdx.y * 240 + blockIdx.x;
        if (bid >= 5120) return;
        int i = bid * 256 + t;
        float4 v = ((const float4*)hid)[i];
        __nv_bfloat16 h0 = __float2bfloat16(v.x), h1 = __float2bfloat16(v.y);
        __nv_bfloat16 h2 = __float2bfloat16(v.z), h3 = __float2bfloat16(v.w);
        __nv_bfloat162 a, b;
        a.x = h0; a.y = h1; b.x = h2; b.y = h3;
        ((__nv_bfloat162*)Hh)[i * 2] = a;
        ((__nv_bfloat162*)Hh)[i * 2 + 1] = b;
        __nv_bfloat162 c, d;
        c.x = __float2bfloat16(v.x - __bfloat162float(h0));
        c.y = __float2bfloat16(v.y - __bfloat162float(h1));
        d.x = __float2bfloat16(v.z - __bfloat162float(h2));
        d.y = __float2bfloat16(v.w - __bfloat162float(h3));
        ((__nv_bfloat162*)Hl)[i * 2] = c;
        ((__nv_bfloat162*)Hl)[i * 2 + 1] = d;
        return;
    }

    __shared__ float tb[32][33];
    if (z == 1 && blockIdx.x >= 80) return;
    const float* W = z ? Wp : Wq;
    const int N = z ? 2560 : 7680;
    const int K = 2560;
    int n0 = blockIdx.x * 32, k0 = blockIdx.y * 32;
#pragma unroll
    for (int j = 0; j < 4; j++)
        tb[ty + j * 8][tx] = W[(size_t)(k0 + ty + j * 8) * N + n0 + tx];
    __syncthreads();
#pragma unroll
    for (int j = 0; j < 4; j++) {
        float v = tb[tx][ty + j * 8];
        size_t o = (size_t)(n0 + ty + j * 8) * K + k0 + tx;
        if (z == 0) {
            __nv_bfloat16 h = __float2bfloat16(v);
            Tqh[o] = h;
            Tql[o] = __float2bfloat16(v - __bfloat162float(h));
        } else {
            __half h = __float2half(v);
            Tph[o] = h;
            Tpl[o] = __float2half(v - __half2float(h));
        }
    }
}

// ---------------------------------------------------------------------------
// GEMM1 (fused): CTA 128x64, 256 threads, K-chunk 64, 2-stage cp.async
// (48KB/stage -> 96KB total -> 2 CTAs/SM). Epilogue routes q/k/v.
// ---------------------------------------------------------------------------
__global__ __launch_bounds__(256, 2) void gemm_qkv(
    const __nv_bfloat16* __restrict__ Ah, const __nv_bfloat16* __restrict__ Al,
    const __nv_bfloat16* __restrict__ Bh, const __nv_bfloat16* __restrict__ Bl,
    const float* __restrict__ bias, float* __restrict__ Qout,
    __nv_bfloat16* __restrict__ Kh, __nv_bfloat16* __restrict__ Kl,
    __half* __restrict__ Vh) {
    extern __shared__ __align__(1024) char dsm[];
    const uint32_t base = smem_u32(dsm);

    const int tid = threadIdx.x;
    const int wid = tid >> 5, lane = tid & 31;
    const int mw = wid & 3;
    const int nw = wid >> 2;
    const int mt = blockIdx.y, nt = blockIdx.x;
    const int K = 2560;

    const int trow = tid >> 3;
    const int tkg = tid & 7;

    float acc[2][4][4];
#pragma unroll
    for (int a = 0; a < 2; a++)
#pragma unroll
        for (int b = 0; b < 4; b++)
#pragma unroll
            for (int c = 0; c < 4; c++) acc[a][b][c] = 0.0f;

    auto load_chunk = [&](int c, int st) {
        const int k0 = c * 64;
        const uint32_t s0 = base + st * 49152;
#pragma unroll
        for (int j = 0; j < 4; j++) {
            const int row = j * 32 + trow;
            const uint32_t so = SWZ(row * 128 + tkg * 16);
            CP16(s0 + so, Ah + (size_t)(mt * 128 + row) * K + k0 + tkg * 8);
            CP16(s0 + 16384 + so, Al + (size_t)(mt * 128 + row) * K + k0 + tkg * 8);
        }
#pragma unroll
        for (int j = 0; j < 2; j++) {
            const int row = j * 32 + trow;
            const uint32_t so = SWZ(row * 128 + tkg * 16);
            CP16(s0 + 32768 + so, Bh + (size_t)(nt * 64 + row) * K + k0 + tkg * 8);
            CP16(s0 + 40960 + so, Bl + (size_t)(nt * 64 + row) * K + k0 + tkg * 8);
        }
        asm volatile("cp.async.commit_group;");
    };

    const int lr = lane & 15;
    const int lc = (lane >> 4) * 16;

    load_chunk(0, 0);

    for (int c = 0; c < 40; c++) {
        const int st = c & 1;
        asm volatile("cp.async.wait_group 0;");
        __syncthreads();
        if (c < 39) load_chunk(c + 1, st ^ 1);

        const uint32_t sA = base + st * 49152;
#pragma unroll
        for (int ks = 0; ks < 4; ks++) {
            uint32_t ah[2][4], al[2][4];
#pragma unroll
            for (int mb = 0; mb < 2; mb++) {
                const uint32_t ro = (mw * 32 + mb * 16 + lr) * 128 + ks * 32 + lc;
                LDSM4(ah[mb], sA + SWZ(ro));
                LDSM4(al[mb], sA + 16384 + SWZ(ro));
            }
            uint32_t bh2[2][4], bl2[2][4];
#pragma unroll
            for (int nb = 0; nb < 2; nb++) {
                const uint32_t ro = (nw * 32 + nb * 16 + lr) * 128 + ks * 32 + lc;
                LDSM4(bh2[nb], sA + 32768 + SWZ(ro));
                LDSM4(bl2[nb], sA + 40960 + SWZ(ro));
            }
#pragma unroll
            for (int mb = 0; mb < 2; mb++)
#pragma unroll
                for (int nb = 0; nb < 2; nb++) {
                    MMA_BF16(acc[mb][nb * 2],     ah[mb], bh2[nb][0], bh2[nb][2]);
                    MMA_BF16(acc[mb][nb * 2 + 1], ah[mb], bh2[nb][1], bh2[nb][3]);
                }
#pragma unroll
            for (int mb = 0; mb < 2; mb++)
#pragma unroll
                for (int nb = 0; nb < 2; nb++) {
                    MMA_BF16(acc[mb][nb * 2],     ah[mb], bl2[nb][0], bl2[nb][2]);
                    MMA_BF16(acc[mb][nb * 2 + 1], ah[mb], bl2[nb][1], bl2[nb][3]);
                }
#pragma unroll
            for (int mb = 0; mb < 2; mb++)
#pragma unroll
                for (int nb = 0; nb < 2; nb++) {
                    MMA_BF16(acc[mb][nb * 2],     al[mb], bh2[nb][0], bh2[nb][2]);
                    MMA_BF16(acc[mb][nb * 2 + 1], al[mb], bh2[nb][1], bh2[nb][3]);
                }
        }
    }

    const int row0 = mt * 128 + mw * 32 + (lane >> 2);
    const int col0 = nt * 64 + nw * 32 + 2 * (lane & 3);

    if (nt < 40) {
#pragma unroll
        for (int mb = 0; mb < 2; mb++) {
#pragma unroll
            for (int n8 = 0; n8 < 4; n8++) {
                const int gc = col0 + n8 * 8;
                const float b0 = bias[gc], b1 = bias[gc + 1];
                const int r = row0 + mb * 16;
                float2 o0 = make_float2(acc[mb][n8][0] + b0, acc[mb][n8][1] + b1);
                float2 o1 = make_float2(acc[mb][n8][2] + b0, acc[mb][n8][3] + b1);
                *(float2*)&Qout[(size_t)r * 2560 + gc] = o0;
                *(float2*)&Qout[(size_t)(r + 8) * 2560 + gc] = o1;
            }
        }
    } else if (nt < 80) {
        // K -> bf16 hi/lo [bh][key][88], paired bf162 stores (d even, same head)
#pragma unroll
        for (int mb = 0; mb < 2; mb++) {
#pragma unroll
            for (int n8 = 0; n8 < 4; n8++) {
#pragma unroll
                for (int half = 0; half < 2; half++) {
                    const int gc = col0 + n8 * 8;
                    const int r = row0 + mb * 16 + half * 8;
                    float v0 = acc[mb][n8][half * 2 + 0] + bias[gc];
                    float v1 = acc[mb][n8][half * 2 + 1] + bias[gc + 1];
                    const int c2 = gc - 2560;
                    const int h = c2 / 80;
                    const int d = c2 - h * 80;
                    const int bb = r >> 10, key = r & 1023;
                    const size_t o = (size_t)(bb * 32 + h) * 90112 +
                                     (size_t)key * 88 + d;
                    __nv_bfloat16 h0 = __float2bfloat16(v0);
                    __nv_bfloat16 h1 = __float2bfloat16(v1);
                    __nv_bfloat162 ph, pl;
                    ph.x = h0; ph.y = h1;
                    pl.x = __float2bfloat16(v0 - __bfloat162float(h0));
                    pl.y = __float2bfloat16(v1 - __bfloat162float(h1));
                    *(__nv_bfloat162*)&Kh[o] = ph;
                    *(__nv_bfloat162*)&Kl[o] = pl;
                }
            }
        }
    } else {
#pragma unroll
        for (int mb = 0; mb < 2; mb++) {
#pragma unroll
            for (int n8 = 0; n8 < 4; n8++) {
#pragma unroll
                for (int e = 0; e < 4; e++) {
                    const int gc = col0 + n8 * 8 + (e & 1);
                    const int r = row0 + mb * 16 + (e >> 1) * 8;
                    float val = acc[mb][n8][e] + bias[gc];
                    const int c2 = gc - 5120;
                    const int h = c2 / 80;
                    const int d = c2 - h * 80;
                    const int bb = r >> 10, key = r & 1023;
                    const size_t o = (size_t)(bb * 32 + h) * 81920 +
                                     (size_t)d * 1024 + key;
                    Vh[o] = __float2half(val);
                }
            }
        }
    }
}

// ---------------------------------------------------------------------------
// GEMM2: fp16 2-term, CTA 128x64, K-chunk 64, 3-stage (32KB/stage) -> 96KB
// smem, 2 CTAs/SM. grid (40, 16).
// ---------------------------------------------------------------------------
__global__ __launch_bounds__(256, 2) void gemm_proj_f16(
    const __half* __restrict__ Ah,
    const __half* __restrict__ Bh, const __half* __restrict__ Bl,
    const float* __restrict__ bias, float* __restrict__ C, int N) {
    extern __shared__ __align__(1024) char dsm[];
    const uint32_t base = smem_u32(dsm);

    const int tid = threadIdx.x;
    const int wid = tid >> 5, lane = tid & 31;
    const int mw = wid & 3;
    const int nw = wid >> 2;
    const int mt = blockIdx.y, nt = blockIdx.x;
    const int K = 2560;

    const int trow = tid >> 3;
    const int tkg = tid & 7;

    float acc[2][4][4];
#pragma unroll
    for (int a = 0; a < 2; a++)
#pragma unroll
        for (int b = 0; b < 4; b++)
#pragma unroll
            for (int c = 0; c < 4; c++) acc[a][b][c] = 0.0f;

    auto load_chunk = [&](int c, int st) {
        const int k0 = c * 64;
        const uint32_t s0 = base + st * 32768;
#pragma unroll
        for (int j = 0; j < 4; j++) {
            const int row = j * 32 + trow;
            const uint32_t so = SWZ(row * 128 + tkg * 16);
            CP16(s0 + so, Ah + (size_t)(mt * 128 + row) * K + k0 + tkg * 8);
        }
#pragma unroll
        for (int j = 0; j < 2; j++) {
            const int row = j * 32 + trow;
            const uint32_t so = SWZ(row * 128 + tkg * 16);
            CP16(s0 + 16384 + so, Bh + (size_t)(nt * 64 + row) * K + k0 + tkg * 8);
            CP16(s0 + 24576 + so, Bl + (size_t)(nt * 64 + row) * K + k0 + tkg * 8);
        }
        asm volatile("cp.async.commit_group;");
    };

    const int lr = lane & 15;
    const int lc = (lane >> 4) * 16;

    load_chunk(0, 0);
    load_chunk(1, 1);

    int st = 0;
    for (int c = 0; c < 40; c++) {
        if (c < 39) {
            asm volatile("cp.async.wait_group 1;");
        } else {
            asm volatile("cp.async.wait_group 0;");
        }
        __syncthreads();
        if (c + 2 < 40) {
            int st2 = st + 2;
            if (st2 >= 3) st2 -= 3;
            load_chunk(c + 2, st2);
        }

        const uint32_t sA = base + st * 32768;
#pragma unroll
        for (int ks = 0; ks < 4; ks++) {
            uint32_t ah[2][4];
#pragma unroll
            for (int mb = 0; mb < 2; mb++) {
                const uint32_t ro = (mw * 32 + mb * 16 + lr) * 128 + ks * 32 + lc;
                LDSM4(ah[mb], sA + SWZ(ro));
            }
            uint32_t bh2[2][4], bl2[2][4];
#pragma unroll
            for (int nb = 0; nb < 2; nb++) {
                const uint32_t ro = (nw * 32 + nb * 16 + lr) * 128 + ks * 32 + lc;
                LDSM4(bh2[nb], sA + 16384 + SWZ(ro));
                LDSM4(bl2[nb], sA + 24576 + SWZ(ro));
            }
#pragma unroll
            for (int mb = 0; mb < 2; mb++)
#pragma unroll
                for (int nb = 0; nb < 2; nb++) {
                    MMA_F16(acc[mb][nb * 2],     ah[mb], bh2[nb][0], bh2[nb][2]);
                    MMA_F16(acc[mb][nb * 2 + 1], ah[mb], bh2[nb][1], bh2[nb][3]);
                }
#pragma unroll
            for (int mb = 0; mb < 2; mb++)
#pragma unroll
                for (int nb = 0; nb < 2; nb++) {
                    MMA_F16(acc[mb][nb * 2],     ah[mb], bl2[nb][0], bl2[nb][2]);
                    MMA_F16(acc[mb][nb * 2 + 1], ah[mb], bl2[nb][1], bl2[nb][3]);
                }
        }
        st++;
        if (st >= 3) st -= 3;
    }

    const int row0 = mt * 128 + mw * 32 + (lane >> 2);
    const int col0 = nt * 64 + nw * 32 + 2 * (lane & 3);
#pragma unroll
    for (int mb = 0; mb < 2; mb++) {
#pragma unroll
        for (int n8 = 0; n8 < 4; n8++) {
            const int gc = col0 + n8 * 8;
            const float b0 = bias[gc], b1 = bias[gc + 1];
            const int r = row0 + mb * 16;
            float2 o0 = make_float2(acc[mb][n8][0] + b0, acc[mb][n8][1] + b1);
            float2 o1 = make_float2(acc[mb][n8][2] + b0, acc[mb][n8][3] + b1);
            *(float2*)&C[(size_t)r * N + gc] = o0;
            *(float2*)&C[(size_t)(r + 8) * N + gc] = o1;
        }
    }
}

// ---------------------------------------------------------------------------
// attn_mma v7: scores fp32 in regs; P fp16; V fp16 with 3-stage ring (1 sync/kt).
// smem: QH [0,11264) | QL [11264,22528) | K 2 stages [22528,112640) -> 2 CTAs/SM.
// Phase3: V 3 buffers at [0, 65280); RED overlay [0,43008) after.
// ---------------------------------------------------------------------------
#define AT_QH 0u
#define AT_QL 11264u
#define AT_K  22528u
#define AT_KSTG 45056u
#define AT_VSTG 21760u
#define AT_SMEM 112640

__global__ __launch_bounds__(256, 2) void attn_mma(
    const float* __restrict__ qsrc,
    const __nv_bfloat16* __restrict__ Kh, const __nv_bfloat16* __restrict__ Kl,
    const __half* __restrict__ Vh,
    const float* __restrict__ gm, const float* __restrict__ gp,
    const float* __restrict__ ga, const float* __restrict__ qp,
    const float* __restrict__ isr,
    __half* __restrict__ out_h) {
    extern __shared__ __align__(128) char smc[];
    __shared__ float coeff[240];
    __shared__ float pbuf[128];
    __shared__ float rsum[16];
    char* sm = smc;
    const uint32_t base = smem_u32(smc);

    const int tid = threadIdx.x;
    const int wid = tid >> 5, lane = tid & 31;
    const int lr = lane & 15, lc = (lane >> 4) << 4;
    const int rr = lane >> 2, cc = (lane & 3) * 2;
    const int bh = blockIdx.y, b = bh >> 5, h = bh & 31;
    const int q0 = blockIdx.x * 16;

    const __nv_bfloat16* KhB = Kh + (size_t)bh * 90112;
    const __nv_bfloat16* KlB = Kl + (size_t)bh * 90112;
    auto load_k = [&](int kt, int stg) {
        const uint32_t sb = base + AT_K + (uint32_t)stg * AT_KSTG;
#pragma unroll
        for (int j = 0; j < 11; j++) {
            int idx = tid + j * 256;
            int m = idx >= 1408;
            int rem = m ? idx - 1408 : idx;
            int row = rem / 11, ch = rem - row * 11;
            const __nv_bfloat16* g =
                (m ? KlB : KhB) + (size_t)(kt * 128 + row) * 88 + ch * 8;
            CP16(sb + m * 22528u + row * 176 + ch * 16, g);
        }
        asm volatile("cp.async.commit_group;");
    };

    load_k(0, 0);

    if (tid < 240) {
        int g = tid / 80, d = tid - g * 80;
        float r0 = gm[g * 4 + 0] + gm[g * 4 + 1];
        float r1 = gm[g * 4 + 2] + gm[g * 4 + 3];
        float ph = gp[g * 80 + d];
        coeff[tid] = (cosf(ph) * r0 + sinf(ph) * r1) * ga[g * 80 + d];
    }
    __syncthreads();

    const float scale = rsqrtf(80.0f);
    for (int idx = tid; idx < 1280; idx += 256) {
        int r = idx / 80, d = idx - r * 80;
        float v = qsrc[(size_t)(b * 1024 + q0 + r) * 2560 + h * 80 + d] * scale;
        float vv[4] = {v, v * coeff[d], v * coeff[80 + d], v * coeff[160 + d]};
#pragma unroll
        for (int g = 0; g < 4; g++) {
            uint32_t o = (g * 16 + r) * 176 + d * 2;
            __nv_bfloat16 hh = __float2bfloat16(vv[g]);
            *(__nv_bfloat16*)(sm + AT_QH + o) = hh;
            *(__nv_bfloat16*)(sm + AT_QL + o) =
                __float2bfloat16(vv[g] - __bfloat162float(hh));
        }
    }

    const float intf = isr[0] * (1.0f / 3.0f);
    float csf[64];

#pragma unroll
    for (int kt = 0; kt < 8; kt++) {
        const int stg = kt & 1;
        asm volatile("cp.async.wait_group 0;");
        __syncthreads();
        if (kt < 7) load_k(kt + 1, stg ^ 1);

        const uint32_t kbase = base + AT_K + (uint32_t)stg * AT_KSTG;
        float acc[4][2][4];
#pragma unroll
        for (int g = 0; g < 4; g++)
#pragma unroll
            for (int i = 0; i < 2; i++)
#pragma unroll
                for (int j = 0; j < 4; j++) acc[g][i][j] = 0.0f;

#pragma unroll
        for (int ks = 0; ks < 5; ks++) {
            uint32_t bH[4], bL[4];
            uint32_t rb = (wid * 16 + lr) * 176 + ks * 32 + lc;
            LDSM4(bH, kbase + rb);
            LDSM4(bL, kbase + 22528u + rb);
#pragma unroll
            for (int g = 0; g < 4; g++) {
                uint32_t aH[4], aL[4];
                uint32_t ro = (g * 16 + lr) * 176 + ks * 32 + lc;
                LDSM4(aH, base + AT_QH + ro);
                LDSM4(aL, base + AT_QL + ro);
                MMA_BF16(acc[g][0], aH, bH[0], bH[2]);
                MMA_BF16(acc[g][1], aH, bH[1], bH[3]);
                MMA_BF16(acc[g][0], aH, bL[0], bL[2]);
                MMA_BF16(acc[g][1], aH, bL[1], bL[3]);
                MMA_BF16(acc[g][0], aL, bH[0], bH[2]);
                MMA_BF16(acc[g][1], aL, bH[1], bH[3]);
            }
        }

#pragma unroll
        for (int n8 = 0; n8 < 2; n8++) {
#pragma unroll
            for (int j = 0; j < 4; j++) {
                float a0 = acc[1][n8][j], a1 = acc[2][n8][j], a2 = acc[3][n8][j];
                csf[kt * 8 + n8 * 4 + j] =
                    acc[0][n8][j] + (a0 * a1 + a0 * a2 + a1 * a2) * intf;
            }
        }
    }
    __syncthreads();   // K/Q reads done before V overwrites region

    const __half* VhB = Vh + (size_t)bh * 81920;
    auto load_v = [&](int kt, int stg) {
#pragma unroll
        for (int j = 0; j < 5; j++) {
            int idx = tid + j * 256;
            int dim = idx >> 4, ch = idx & 15;
            const __half* g = VhB + (size_t)dim * 1024 + kt * 128 + ch * 8;
            CP16(base + stg * AT_VSTG + dim * 272 + ch * 16, g);
        }
        asm volatile("cp.async.commit_group;");
    };
    load_v(0, 0);
    load_v(1, 1);

    // ---- Phase 2: softmax (fp32), pack exp to fp16 fragments ----
    float m0 = -1e30f, m1 = -1e30f;
#pragma unroll
    for (int i = 0; i < 16; i++) {
        m0 = fmaxf(m0, fmaxf(csf[i * 4 + 0], csf[i * 4 + 1]));
        m1 = fmaxf(m1, fmaxf(csf[i * 4 + 2], csf[i * 4 + 3]));
    }
#pragma unroll
    for (int off = 1; off <= 2; off <<= 1) {
        m0 = fmaxf(m0, __shfl_xor_sync(0xffffffffu, m0, off));
        m1 = fmaxf(m1, __shfl_xor_sync(0xffffffffu, m1, off));
    }
    if ((lane & 3) == 0) {
        pbuf[wid * 16 + rr] = m0;
        pbuf[wid * 16 + rr + 8] = m1;
    }
    __syncthreads();
    float M0 = -1e30f, M1 = -1e30f;
#pragma unroll
    for (int w = 0; w < 8; w++) {
        M0 = fmaxf(M0, pbuf[w * 16 + rr]);
        M1 = fmaxf(M1, pbuf[w * 16 + rr + 8]);
    }
    __syncthreads();

    uint32_t ps[32];
    float s0 = 0.0f, s1 = 0.0f;
#pragma unroll
    for (int i = 0; i < 16; i++) {
        float e0 = __expf(csf[i * 4 + 0] - M0);
        float e1 = __expf(csf[i * 4 + 1] - M0);
        float e2 = __expf(csf[i * 4 + 2] - M1);
        float e3 = __expf(csf[i * 4 + 3] - M1);
        s0 += e0 + e1;
        s1 += e2 + e3;
        ps[i * 2 + 0] = pack_h2(e0, e1);
        ps[i * 2 + 1] = pack_h2(e2, e3);
    }
#pragma unroll
    for (int off = 1; off <= 2; off <<= 1) {
        s0 += __shfl_xor_sync(0xffffffffu, s0, off);
        s1 += __shfl_xor_sync(0xffffffffu, s1, off);
    }
    if ((lane & 3) == 0) {
        pbuf[wid * 16 + rr] = s0;
        pbuf[wid * 16 + rr + 8] = s1;
    }
    __syncthreads();
    if (wid == 0 && lane < 16) {
        float S = 0.0f;
#pragma unroll
        for (int w = 0; w < 8; w++) S += pbuf[w * 16 + lane];
        rsum[lane] = S;
    }

    // ---- Phase 3: P @ Vh, 3-stage V ring, one sync per kt ----
    float acc3[10][4];
#pragma unroll
    for (int i = 0; i < 10; i++)
#pragma unroll
        for (int j = 0; j < 4; j++) acc3[i][j] = 0.0f;

#pragma unroll
    for (int kt = 0; kt < 8; kt++) {
        if (kt < 7) {
            asm volatile("cp.async.wait_group 1;");
        } else {
            asm volatile("cp.async.wait_group 0;");
        }
        __syncthreads();   // all warps done reading buffer (kt+2)%3 (from kt-1)
        if (kt + 2 < 8) {
            int vs = kt + 2;
            int vb3 = vs - (vs / 3) * 3;
            load_v(vs, vb3);
        }

        const int kb3 = kt - (kt / 3) * 3;
        const uint32_t vb = base + (uint32_t)kb3 * AT_VSTG;
        uint32_t pA[4] = {ps[kt * 4 + 0], ps[kt * 4 + 1],
                          ps[kt * 4 + 2], ps[kt * 4 + 3]};
#pragma unroll
        for (int nd = 0; nd < 5; nd++) {
            uint32_t vh[4];
            uint32_t rb = (nd * 16 + lr) * 272 + wid * 32 + lc;
            LDSM4(vh, vb + rb);
            MMA_F16(acc3[nd * 2],     pA, vh[0], vh[2]);
            MMA_F16(acc3[nd * 2 + 1], pA, vh[1], vh[3]);
        }
    }
    __syncthreads();   // all V reads done before RED overlay

    float* red = (float*)sm;
    float* redw = red + wid * 1344;
#pragma unroll
    for (int j = 0; j < 10; j++) {
        int d = (j >> 1) * 16 + (j & 1) * 8 + cc;
        redw[rr * 84 + d]           = acc3[j][0];
        redw[rr * 84 + d + 1]       = acc3[j][1];
        redw[(rr + 8) * 84 + d]     = acc3[j][2];
        redw[(rr + 8) * 84 + d + 1] = acc3[j][3];
    }
    __syncthreads();

    const float cph = cosf(qp[h]);
    for (int idx = tid; idx < 1280; idx += 256) {
        int r = idx / 80, d = idx - r * 80;
        float s = 0.0f;
#pragma unroll
        for (int w = 0; w < 8; w++) s += red[w * 1344 + r * 84 + d];
        float o = s * cph / rsum[r];
        size_t go = (size_t)(b * 1024 + q0 + r) * 2560 + h * 80 + d;
        out_h[go] = __float2half(o);
    }
}

// ---------------------------------------------------------------------------
extern "C" void kernel_launch(void* const* d_in, const int* in_sizes, int n_in,
                              void* d_out, int out_size) {
    const float* hidden = (const float*)d_in[0];
    const float* Wqkv   = (const float*)d_in[1];
    const float* bqkv   = (const float*)d_in[2];
    const float* Wproj  = (const float*)d_in[3];
    const float* bproj  = (const float*)d_in[4];
    const float* gm     = (const float*)d_in[5];
    const float* gp     = (const float*)d_in[6];
    const float* ga     = (const float*)d_in[7];
    const float* qp     = (const float*)d_in[8];
    const float* isr    = (const float*)d_in[9];
    float* out = (float*)d_out;

    void *p_q, *p_hh, *p_hl, *p_wqh, *p_wql, *p_wph, *p_wpl, *p_at;
    void *p_kh, *p_kl, *p_vh;
    cudaGetSymbolAddress(&p_q, g_q);
    cudaGetSymbolAddress(&p_hh, g_hid_hi);
    cudaGetSymbolAddress(&p_hl, g_hid_lo);
    cudaGetSymbolAddress(&p_wqh, g_wqkvT_hi);
    cudaGetSymbolAddress(&p_wql, g_wqkvT_lo);
    cudaGetSymbolAddress(&p_wph, g_wprojT_hi);
    cudaGetSymbolAddress(&p_wpl, g_wprojT_lo);
    cudaGetSymbolAddress(&p_at, g_attn);
    cudaGetSymbolAddress(&p_kh, g_Khi);
    cudaGetSymbolAddress(&p_kl, g_Klo);
    cudaGetSymbolAddress(&p_vh, g_Vthi);

    const int QKV_SMEM = 2 * 49152;
    const int PROJ_SMEM = 3 * 32768;
    cudaFuncSetAttribute(gemm_qkv,
                         cudaFuncAttributeMaxDynamicSharedMemorySize, QKV_SMEM);
    cudaFuncSetAttribute(gemm_proj_f16,
                         cudaFuncAttributeMaxDynamicSharedMemorySize, PROJ_SMEM);
    cudaFuncSetAttribute(attn_mma,
                         cudaFuncAttributeMaxDynamicSharedMemorySize, AT_SMEM);

    // 1) input conversions (single launch)
    prep_inputs<<<dim3(240, 80, 3), dim3(32, 8)>>>(
        hidden, Wqkv, Wproj,
        (__nv_bfloat16*)p_hh, (__nv_bfloat16*)p_hl,
        (__nv_bfloat16*)p_wqh, (__nv_bfloat16*)p_wql,
        (__half*)p_wph, (__half*)p_wpl);

    // 2) fused qkv GEMM (2 CTAs/SM): q fp32, k bf16 hi/lo, v fp16
    gemm_qkv<<<dim3(120, 16), 256, QKV_SMEM>>>(
        (const __nv_bfloat16*)p_hh, (const __nv_bfloat16*)p_hl,
        (const __nv_bfloat16*)p_wqh, (const __nv_bfloat16*)p_wql,
        bqkv, (float*)p_q,
        (__nv_bfloat16*)p_kh, (__nv_bfloat16*)p_kl,
        (__half*)p_vh);

    // 3) register-resident tensor-core quantum attention -> fp16
    attn_mma<<<dim3(64, 64), 256, AT_SMEM>>>(
        (const float*)p_q,
        (const __nv_bfloat16*)p_kh, (const __nv_bfloat16*)p_kl,
        (const __half*)p_vh,
        gm, gp, ga, qp, isr,
        (__half*)p_at);

    // 4) out = attn @ Wproj + bproj (fp16 2-term, 2 CTAs/SM)
    gemm_proj_f16<<<dim3(40, 16), 256, PROJ_SMEM>>>(
        (const __half*)p_at,
        (const __half*)p_wph, (const __half*)p_wpl,
        bproj, out, 2560);
}